// round 6
// baseline (speedup 1.0000x reference)
#include <cuda_runtime.h>
#include <cuda_bf16.h>
#include <cstdint>

typedef __nv_bfloat16 bf16;

#define BS 8
#define NW 512
#define NV 1024

// ---------------- bf16 hi/lo planes (allocation-free scratch) ----------------
__device__ bf16 g_tah[BS*NW*1024], g_tal[BS*NW*1024];      // LN(text)
__device__ bf16 g_aah[BS*NV*1024], g_aal[BS*NV*1024];      // LN(av)
__device__ bf16 g_wth[3][1024*1024], g_wtl[3][1024*1024];  // W^T [k][n]
__device__ bf16 g_qh[BS*NW*1024],  g_ql[BS*NW*1024];
__device__ bf16 g_kh[BS*NV*1024],  g_kl[BS*NV*1024];
__device__ bf16 g_vh[BS*NV*1024],  g_vl[BS*NV*1024];
__device__ float g_opart[4][(size_t)BS*NW*1024];           // O k-split partials, 64 MB

// ---------------- helpers ----------------
__device__ __forceinline__ uint32_t smem_to_u32(const void* p) {
    uint32_t a;
    asm("{ .reg .u64 t; cvta.to.shared.u64 t, %1; cvt.u32.u64 %0, t; }" : "=r"(a) : "l"(p));
    return a;
}
__device__ __forceinline__ void split_pack(float x0, float x1, uint32_t& hi, uint32_t& lo) {
    __nv_bfloat16 h0 = __float2bfloat16(x0), h1 = __float2bfloat16(x1);
    float r0 = x0 - __bfloat162float(h0), r1 = x1 - __bfloat162float(h1);
    __nv_bfloat16 l0 = __float2bfloat16(r0), l1 = __float2bfloat16(r1);
    hi = ((uint32_t)__bfloat16_as_ushort(h1) << 16) | __bfloat16_as_ushort(h0);
    lo = ((uint32_t)__bfloat16_as_ushort(l1) << 16) | __bfloat16_as_ushort(l0);
}

#define LDSM_X4(r0, r1, r2, r3, addr) \
    asm volatile("ldmatrix.sync.aligned.m8n8.x4.shared.b16 {%0,%1,%2,%3}, [%4];" \
        : "=r"(r0), "=r"(r1), "=r"(r2), "=r"(r3) : "r"(addr))
#define LDSM_X4_T(r0, r1, r2, r3, addr) \
    asm volatile("ldmatrix.sync.aligned.m8n8.x4.trans.shared.b16 {%0,%1,%2,%3}, [%4];" \
        : "=r"(r0), "=r"(r1), "=r"(r2), "=r"(r3) : "r"(addr))

__device__ __forceinline__ void mma16816(float* c, const uint32_t* a, const uint32_t* b) {
    asm volatile(
        "mma.sync.aligned.m16n8k16.row.col.f32.bf16.bf16.f32 "
        "{%0,%1,%2,%3}, {%4,%5,%6,%7}, {%8,%9}, {%0,%1,%2,%3};"
        : "+f"(c[0]), "+f"(c[1]), "+f"(c[2]), "+f"(c[3])
        : "r"(a[0]), "r"(a[1]), "r"(a[2]), "r"(a[3]), "r"(b[0]), "r"(b[1]));
}

#define CP16(dst, src) \
    asm volatile("cp.async.cg.shared.global [%0], [%1], 16;" :: "r"((uint32_t)(dst)), "l"(src) : "memory")
#define CP_COMMIT() asm volatile("cp.async.commit_group;" ::: "memory")
#define CP_WAIT(n)  asm volatile("cp.async.wait_group %0;" :: "n"(n) : "memory")

// ---------------- LayerNorm -> bf16 hi/lo planes ----------------
__global__ __launch_bounds__(256) void ln_split(const float* __restrict__ x,
                                                const float* __restrict__ w,
                                                const float* __restrict__ b,
                                                int dst)
{
    bf16* yh = dst ? g_aah : g_tah;
    bf16* yl = dst ? g_aal : g_tal;
    int row = blockIdx.x, t = threadIdx.x;
    float4 xv = reinterpret_cast<const float4*>(x)[(size_t)row * 256 + t];
    float s  = xv.x + xv.y + xv.z + xv.w;
    float ss = xv.x*xv.x + xv.y*xv.y + xv.z*xv.z + xv.w*xv.w;
#pragma unroll
    for (int o = 16; o > 0; o >>= 1) {
        s  += __shfl_xor_sync(0xffffffffu, s,  o);
        ss += __shfl_xor_sync(0xffffffffu, ss, o);
    }
    __shared__ float rs[8], rss[8];
    if ((t & 31) == 0) { rs[t >> 5] = s; rss[t >> 5] = ss; }
    __syncthreads();
    float tot = 0.f, tot2 = 0.f;
#pragma unroll
    for (int i = 0; i < 8; i++) { tot += rs[i]; tot2 += rss[i]; }
    float mean = tot * (1.f / 1024.f);
    float var  = tot2 * (1.f / 1024.f) - mean * mean;
    float rstd = rsqrtf(var + 1e-5f);
    float4 wv = reinterpret_cast<const float4*>(w)[t];
    float4 bv = reinterpret_cast<const float4*>(b)[t];
    float o0 = (xv.x - mean) * rstd * wv.x + bv.x;
    float o1 = (xv.y - mean) * rstd * wv.y + bv.y;
    float o2 = (xv.z - mean) * rstd * wv.z + bv.z;
    float o3 = (xv.w - mean) * rstd * wv.w + bv.w;
    uint32_t h0, l0, h1, l1;
    split_pack(o0, o1, h0, l0);
    split_pack(o2, o3, h1, l1);
    *reinterpret_cast<uint2*>(reinterpret_cast<char*>(yh) + (size_t)row * 2048 + t * 8) = make_uint2(h0, h1);
    *reinterpret_cast<uint2*>(reinterpret_cast<char*>(yl) + (size_t)row * 2048 + t * 8) = make_uint2(l0, l1);
}

// ---------------- W[n][k] -> W^T[k][n] hi/lo ----------------
__global__ void wsplit(const float* __restrict__ Wq,
                       const float* __restrict__ Wk,
                       const float* __restrict__ Wv)
{
    int wsel = blockIdx.z;
    const float* W = (wsel == 0) ? Wq : (wsel == 1) ? Wk : Wv;
    bf16* th = g_wth[wsel];
    bf16* tl = g_wtl[wsel];
    __shared__ float tile[32][33];
    int k = blockIdx.x * 32 + threadIdx.x;
    int n0 = blockIdx.y * 32;
#pragma unroll
    for (int i = threadIdx.y; i < 32; i += 8)
        tile[i][threadIdx.x] = W[(size_t)(n0 + i) * 1024 + k];
    __syncthreads();
#pragma unroll
    for (int i = threadIdx.y; i < 32; i += 8) {
        float v = tile[threadIdx.x][i];
        __nv_bfloat16 h = __float2bfloat16(v);
        __nv_bfloat16 l = __float2bfloat16(v - __bfloat162float(h));
        size_t idx = (size_t)(blockIdx.x * 32 + i) * 1024 + n0 + threadIdx.x;
        th[idx] = h;
        tl[idx] = l;
    }
}

// ---------------- projection GEMM (unchanged from R4/R5) ----------------
#define G_AHOFF 0
#define G_ALOFF 6144
#define G_BHOFF 12288
#define G_BLOFF 16640
#define G_STAGE 20992

__global__ __launch_bounds__(512, 1) void gemm_tc(int src, int dst,
                                                  const float* __restrict__ bias)
{
    extern __shared__ __align__(16) uint8_t smg[];
    const bf16* Ah = src ? g_aah : g_tah;
    const bf16* Al = src ? g_aal : g_tal;
    const bf16* Bh = g_wth[dst];
    const bf16* Bl = g_wtl[dst];
    bf16* Ch = (dst == 0) ? g_qh : (dst == 1) ? g_kh : g_vh;
    bf16* Cl = (dst == 0) ? g_ql : (dst == 1) ? g_kl : g_vl;

    int t = threadIdx.x, lane = t & 31, warp = t >> 5;
    int wm = warp >> 2, wn = warp & 3;
    int bm = blockIdx.x * 128, bn = blockIdx.y * 128;
    uint32_t smb = smem_to_u32(smg);

    bool isA = t < 256;
    int u = t & 255;
    int arow = u >> 1, aseg = u & 1;
    int brow = u >> 4, bseg = u & 15;
    const bf16* agh = Ah + (size_t)(bm + arow) * 1024 + aseg * 8;
    const bf16* agl = Al + (size_t)(bm + arow) * 1024 + aseg * 8;
    const bf16* bgh = Bh + (size_t)brow * 1024 + bn + bseg * 8;
    const bf16* bgl = Bl + (size_t)brow * 1024 + bn + bseg * 8;
    uint32_t a_dst = arow * 48 + aseg * 16;
    uint32_t b_dst = brow * 272 + bseg * 16;

    auto issue = [&](int ch) {
        uint32_t base = smb + (uint32_t)((ch & 3) * G_STAGE);
        if (isA) {
            CP16(base + G_AHOFF + a_dst, agh + ch * 16);
            CP16(base + G_ALOFF + a_dst, agl + ch * 16);
        } else {
            CP16(base + G_BHOFF + b_dst, bgh + (size_t)ch * 16 * 1024);
            CP16(base + G_BLOFF + b_dst, bgl + (size_t)ch * 16 * 1024);
        }
    };

    float acc[2][4][4];
#pragma unroll
    for (int i = 0; i < 2; i++)
#pragma unroll
        for (int j = 0; j < 4; j++)
#pragma unroll
            for (int e = 0; e < 4; e++) acc[i][j][e] = 0.f;

    issue(0); CP_COMMIT();
    issue(1); CP_COMMIT();
    issue(2); CP_COMMIT();

    uint32_t a_off = (lane & 15) * 48 + (lane >> 4) * 16;
    uint32_t b_off = ((lane & 7) + ((lane >> 3) & 1) * 8) * 272 + (lane >> 4) * 16;

    for (int ch = 0; ch < 64; ch++) {
        CP_WAIT(2);
        __syncthreads();
        if (ch + 3 < 64) issue(ch + 3);
        CP_COMMIT();

        uint32_t base = smb + (uint32_t)((ch & 3) * G_STAGE);
        uint32_t ah[2][4], al[2][4], bh2[4][2], bl2[4][2];
#pragma unroll
        for (int mt = 0; mt < 2; mt++) {
            uint32_t r = base + G_AHOFF + (uint32_t)((wm * 32 + mt * 16) * 48) + a_off;
            LDSM_X4(ah[mt][0], ah[mt][1], ah[mt][2], ah[mt][3], r);
            uint32_t rl = base + G_ALOFF + (uint32_t)((wm * 32 + mt * 16) * 48) + a_off;
            LDSM_X4(al[mt][0], al[mt][1], al[mt][2], al[mt][3], rl);
        }
#pragma unroll
        for (int pp = 0; pp < 2; pp++) {
            uint32_t r = base + G_BHOFF + (uint32_t)((wn * 32 + pp * 16) * 2) + b_off;
            LDSM_X4_T(bh2[pp*2][0], bh2[pp*2][1], bh2[pp*2+1][0], bh2[pp*2+1][1], r);
            uint32_t rl = base + G_BLOFF + (uint32_t)((wn * 32 + pp * 16) * 2) + b_off;
            LDSM_X4_T(bl2[pp*2][0], bl2[pp*2][1], bl2[pp*2+1][0], bl2[pp*2+1][1], rl);
        }
#pragma unroll
        for (int mt = 0; mt < 2; mt++)
#pragma unroll
            for (int nt = 0; nt < 4; nt++) {
                mma16816(acc[mt][nt], ah[mt], bh2[nt]);
                mma16816(acc[mt][nt], ah[mt], bl2[nt]);
                mma16816(acc[mt][nt], al[mt], bh2[nt]);
            }
    }

    int lr = lane >> 2, lc = (lane & 3) * 2;
#pragma unroll
    for (int nt = 0; nt < 4; nt++) {
        int col = bn + wn * 32 + nt * 8 + lc;
        float b0 = __ldg(bias + col), b1 = __ldg(bias + col + 1);
#pragma unroll
        for (int mt = 0; mt < 2; mt++) {
            int row = bm + wm * 32 + mt * 16 + lr;
            uint32_t h01, l01;
            split_pack(acc[mt][nt][0] + b0, acc[mt][nt][1] + b1, h01, l01);
            *reinterpret_cast<uint32_t*>(reinterpret_cast<char*>(Ch) + ((size_t)row * 1024 + col) * 2) = h01;
            *reinterpret_cast<uint32_t*>(reinterpret_cast<char*>(Cl) + ((size_t)row * 1024 + col) * 2) = l01;
            split_pack(acc[mt][nt][2] + b0, acc[mt][nt][3] + b1, h01, l01);
            *reinterpret_cast<uint32_t*>(reinterpret_cast<char*>(Ch) + ((size_t)(row + 8) * 1024 + col) * 2) = h01;
            *reinterpret_cast<uint32_t*>(reinterpret_cast<char*>(Cl) + ((size_t)(row + 8) * 1024 + col) * 2) = l01;
        }
    }
}

// ---------------- fused attention: S = sigmoid(QK^T/8); amean += S/16; O += S@V ----
// grid (q0:4, ks:4, b:8); 256 thr / 8 warps; warp = 16 q-rows x 128 keys.
// smem: Q bufs 2 x [hi 128x144 | lo 128x144] then KV bufs 2 x [Kh|Kl|Vh|Vl each 128x144]
#define F_PLANE 18432
#define FQ(buf)  ((buf) * 2 * F_PLANE)
#define FKV(buf) (4 * F_PLANE + (buf) * 4 * F_PLANE)
#define F_SMEM   (12 * F_PLANE)   // 221184

__global__ __launch_bounds__(256, 1) void attn_fused(float* __restrict__ amean)
{
    extern __shared__ __align__(16) uint8_t smg[];
    int q0 = blockIdx.x, ks = blockIdx.y, b = blockIdx.z;
    int t = threadIdx.x, lane = t & 31, w = t >> 5;
    uint32_t smb = smem_to_u32(smg);
    int gr = lane >> 2, lc2 = (lane & 3) * 2;

    // ---- staging ----
    auto issueQ = [&](int h2) {
        uint32_t base = smb + FQ(h2 & 1);
        int pl = t >> 7, row = t & 127;
        const bf16* arr = pl ? g_ql : g_qh;
        const bf16* s = arr + (size_t)(b * 512 + q0 * 128 + row) * 1024 + h2 * 64;
        uint32_t d = base + pl * F_PLANE + row * 144;
#pragma unroll
        for (int seg = 0; seg < 8; seg++) CP16(d + seg * 16, s + seg * 8);
    };
    auto issueKV = [&](int it2) {
        int h2 = it2 >> 1, kt2 = it2 & 1;
        uint32_t base = smb + FKV(it2 & 1);
        int key0 = ks * 256 + kt2 * 128;
#pragma unroll
        for (int i = 0; i < 2; i++) {
            int j = t + i * 256;
            int pl = j >> 7, row = j & 127;
            const bf16* arr = (pl == 0) ? g_kh : (pl == 1) ? g_kl : (pl == 2) ? g_vh : g_vl;
            const bf16* s = arr + (size_t)(b * 1024 + key0 + row) * 1024 + h2 * 64;
            uint32_t d = base + pl * F_PLANE + row * 144;
#pragma unroll
            for (int seg = 0; seg < 8; seg++) CP16(d + seg * 16, s + seg * 8);
        }
    };

    uint32_t a_off = (lane & 15) * 144 + (lane >> 4) * 16;                              // Q frag
    uint32_t k_off = ((lane & 7) + ((lane >> 4) & 1) * 8) * 144 + ((lane >> 3) & 1) * 16; // K frag
    uint32_t v_off = ((lane & 7) + ((lane >> 3) & 1) * 8) * 144 + (lane >> 4) * 16;       // V frag (trans)

    // prologue: G0 = {Q0, KV0}, G1 = {Q1, KV1}
    issueQ(0); issueKV(0); CP_COMMIT();
    issueQ(1); issueKV(1); CP_COMMIT();

    float oacc[8][4];

    for (int it = 0; it < 32; it++) {
        int h = it >> 1, kt = it & 1;
        CP_WAIT(1);
        __syncthreads();

        uint32_t qb  = smb + FQ(h & 1);
        uint32_t kvb = smb + FKV(it & 1);

        if (kt == 0) {
#pragma unroll
            for (int i = 0; i < 8; i++)
#pragma unroll
                for (int e = 0; e < 4; e++) oacc[i][e] = 0.f;
        }

        // ---- S = Q_h K_h^T ----
        float sacc[16][4];
#pragma unroll
        for (int i = 0; i < 16; i++)
#pragma unroll
            for (int e = 0; e < 4; e++) sacc[i][e] = 0.f;

#pragma unroll
        for (int kc = 0; kc < 4; kc++) {
            uint32_t qh_f[4], ql_f[4];
            uint32_t ra = qb + (uint32_t)(w * 16 * 144) + a_off + kc * 32;
            LDSM_X4(qh_f[0], qh_f[1], qh_f[2], qh_f[3], ra);
            LDSM_X4(ql_f[0], ql_f[1], ql_f[2], ql_f[3], ra + F_PLANE);
#pragma unroll
            for (int kb = 0; kb < 8; kb++) {
                uint32_t rh = kvb + (uint32_t)(kb * 16 * 144) + k_off + kc * 32;
                uint32_t kh0, kh1, kh2, kh3, kl0, kl1, kl2, kl3;
                LDSM_X4(kh0, kh1, kh2, kh3, rh);
                LDSM_X4(kl0, kl1, kl2, kl3, rh + F_PLANE);
                uint32_t bh[2] = {kh0, kh1}, bh2[2] = {kh2, kh3};
                uint32_t bl[2] = {kl0, kl1}, bl2[2] = {kl2, kl3};
                mma16816(sacc[kb*2],   qh_f, bh);
                mma16816(sacc[kb*2],   qh_f, bl);
                mma16816(sacc[kb*2],   ql_f, bh);
                mma16816(sacc[kb*2+1], qh_f, bh2);
                mma16816(sacc[kb*2+1], qh_f, bl2);
                mma16816(sacc[kb*2+1], ql_f, bh2);
            }
        }

        // ---- sigmoid, A-fragments (hi/lo), amean RMW ----
        uint32_t shf[8][4], slf[8][4];
#pragma unroll
        for (int nt = 0; nt < 16; nt++) {
            float s0 = 1.f / (1.f + __expf(-0.125f * sacc[nt][0]));
            float s1 = 1.f / (1.f + __expf(-0.125f * sacc[nt][1]));
            float s2 = 1.f / (1.f + __expf(-0.125f * sacc[nt][2]));
            float s3 = 1.f / (1.f + __expf(-0.125f * sacc[nt][3]));
            sacc[nt][0] = s0; sacc[nt][1] = s1; sacc[nt][2] = s2; sacc[nt][3] = s3;
            int g = nt >> 1, half = (nt & 1) * 2;
            split_pack(s0, s1, shf[g][half],     slf[g][half]);
            split_pack(s2, s3, shf[g][half + 1], slf[g][half + 1]);
        }
        {
            size_t rowbase = (size_t)(b * 512 + q0 * 128 + w * 16 + gr) * 1024;
            int colbase = ks * 256 + kt * 128 + lc2;
            float* p0 = amean + rowbase + colbase;
            float* p1 = amean + rowbase + 8 * 1024 + colbase;
            if (h == 0) {
#pragma unroll
                for (int nt = 0; nt < 16; nt++) {
                    *reinterpret_cast<float2*>(p0 + nt * 8) =
                        make_float2(sacc[nt][0] * 0.0625f, sacc[nt][1] * 0.0625f);
                    *reinterpret_cast<float2*>(p1 + nt * 8) =
                        make_float2(sacc[nt][2] * 0.0625f, sacc[nt][3] * 0.0625f);
                }
            } else {
#pragma unroll
                for (int nt = 0; nt < 16; nt++) {
                    float2 a0 = *reinterpret_cast<float2*>(p0 + nt * 8);
                    float2 a1 = *reinterpret_cast<float2*>(p1 + nt * 8);
                    a0.x += sacc[nt][0] * 0.0625f; a0.y += sacc[nt][1] * 0.0625f;
                    a1.x += sacc[nt][2] * 0.0625f; a1.y += sacc[nt][3] * 0.0625f;
                    *reinterpret_cast<float2*>(p0 + nt * 8) = a0;
                    *reinterpret_cast<float2*>(p1 + nt * 8) = a1;
                }
            }
        }

        // ---- O += S @ V ----
        uint32_t vbase = kvb + 2 * F_PLANE;
#pragma unroll
        for (int g = 0; g < 8; g++) {
#pragma unroll
            for (int p = 0; p < 4; p++) {
                uint32_t rv = vbase + (uint32_t)(g * 16 * 144) + v_off + p * 32;
                uint32_t vh0, vh1, vh2, vh3, vl0, vl1, vl2, vl3;
                LDSM_X4_T(vh0, vh1, vh2, vh3, rv);
                LDSM_X4_T(vl0, vl1, vl2, vl3, rv + F_PLANE);
                uint32_t bh[2] = {vh0, vh1}, bhB[2] = {vh2, vh3};
                uint32_t bl[2] = {vl0, vl1}, blB[2] = {vl2, vl3};
                mma16816(oacc[p*2],   shf[g], bh);
                mma16816(oacc[p*2],   shf[g], bl);
                mma16816(oacc[p*2],   slf[g], bh);
                mma16816(oacc[p*2+1], shf[g], bhB);
                mma16816(oacc[p*2+1], shf[g], blB);
                mma16816(oacc[p*2+1], slf[g], bhB);
            }
        }

        if (kt == 1) {
            float* op = g_opart[ks] + (size_t)(b * 512 + q0 * 128 + w * 16 + gr) * 1024 + h * 64 + lc2;
#pragma unroll
            for (int nd = 0; nd < 8; nd++) {
                *reinterpret_cast<float2*>(op + nd * 8) = make_float2(oacc[nd][0], oacc[nd][1]);
                *reinterpret_cast<float2*>(op + 8 * 1024 + nd * 8) = make_float2(oacc[nd][2], oacc[nd][3]);
            }
        }

        __syncthreads();
        int nx = it + 2;
        if (nx < 32) {
            issueKV(nx);
            if (nx >= 4 && !(nx & 1)) issueQ(nx >> 1);
        }
        CP_COMMIT();
    }
}

// ---------------- reduce O partials ----------------
__global__ __launch_bounds__(256) void reduce_o(float* __restrict__ out)
{
    size_t i = ((size_t)blockIdx.x * 256 + threadIdx.x) * 4;
    float4 a = *reinterpret_cast<const float4*>(&g_opart[0][i]);
    float4 c = *reinterpret_cast<const float4*>(&g_opart[1][i]);
    float4 d = *reinterpret_cast<const float4*>(&g_opart[2][i]);
    float4 e = *reinterpret_cast<const float4*>(&g_opart[3][i]);
    a.x += c.x + d.x + e.x;
    a.y += c.y + d.y + e.y;
    a.z += c.z + d.z + e.z;
    a.w += c.w + d.w + e.w;
    *reinterpret_cast<float4*>(out + i) = a;
}

// ---------------- launch ----------------
extern "C" void kernel_launch(void* const* d_in, const int* in_sizes, int n_in,
                              void* d_out, int out_size)
{
    (void)in_sizes; (void)n_in; (void)out_size;
    const float* text = (const float*)d_in[0];
    const float* av   = (const float*)d_in[1];
    const float* tn_w = (const float*)d_in[2];
    const float* tn_b = (const float*)d_in[3];
    const float* an_w = (const float*)d_in[4];
    const float* an_b = (const float*)d_in[5];
    const float* Wq   = (const float*)d_in[6];
    const float* bq   = (const float*)d_in[7];
    const float* Wk   = (const float*)d_in[8];
    const float* bk   = (const float*)d_in[9];
    const float* Wv   = (const float*)d_in[10];
    const float* bv   = (const float*)d_in[11];

    float* out   = (float*)d_out;
    float* amean = out + (size_t)BS * NW * 1024;

    static int attr_done = 0;
    if (!attr_done) {
        cudaFuncSetAttribute(gemm_tc,    cudaFuncAttributeMaxDynamicSharedMemorySize, 4 * G_STAGE);
        cudaFuncSetAttribute(attn_fused, cudaFuncAttributeMaxDynamicSharedMemorySize, F_SMEM);
        attr_done = 1;
    }

    ln_split<<<BS * NW, 256>>>(text, tn_w, tn_b, 0);
    ln_split<<<BS * NV, 256>>>(av, an_w, an_b, 1);
    wsplit<<<dim3(32, 32, 3), dim3(32, 8)>>>(Wq, Wk, Wv);

    gemm_tc<<<dim3(32, 8), 512, 4 * G_STAGE>>>(0, 0, bq);
    gemm_tc<<<dim3(64, 8), 512, 4 * G_STAGE>>>(1, 1, bk);
    gemm_tc<<<dim3(64, 8), 512, 4 * G_STAGE>>>(1, 2, bv);

    attn_fused<<<dim3(4, 4, 8), 256, F_SMEM>>>(amean);
    reduce_o<<<(BS * NW * 1024) / (4 * 256), 256>>>(out);
}

// round 7
// speedup vs baseline: 1.4030x; 1.4030x over previous
#include <cuda_runtime.h>
#include <cuda_bf16.h>
#include <cuda_fp16.h>
#include <cstdint>

typedef __nv_bfloat16 bf16;

#define BS 8
#define NW 512
#define NV 1024

// ---------------- scratch (allocation-free) ----------------
__device__ bf16 g_tah[BS*NW*1024], g_tal[BS*NW*1024];      // LN(text) hi/lo
__device__ bf16 g_aah[BS*NV*1024], g_aal[BS*NV*1024];      // LN(av) hi/lo
__device__ bf16 g_wth[3][1024*1024], g_wtl[3][1024*1024];  // W^T [k][n] hi/lo
__device__ __half g_qf[BS*NW*1024];                        // Q fp16
__device__ __half g_kf[BS*NV*1024];                        // K fp16
__device__ __half g_vf[BS*NV*1024];                        // V fp16
__device__ __half g_sf[(size_t)BS*16*NW*NV];               // sigmoid scores fp16, 128 MB

// ---------------- helpers ----------------
__device__ __forceinline__ uint32_t smem_to_u32(const void* p) {
    uint32_t a;
    asm("{ .reg .u64 t; cvta.to.shared.u64 t, %1; cvt.u32.u64 %0, t; }" : "=r"(a) : "l"(p));
    return a;
}
__device__ __forceinline__ void split_pack(float x0, float x1, uint32_t& hi, uint32_t& lo) {
    __nv_bfloat16 h0 = __float2bfloat16(x0), h1 = __float2bfloat16(x1);
    float r0 = x0 - __bfloat162float(h0), r1 = x1 - __bfloat162float(h1);
    __nv_bfloat16 l0 = __float2bfloat16(r0), l1 = __float2bfloat16(r1);
    hi = ((uint32_t)__bfloat16_as_ushort(h1) << 16) | __bfloat16_as_ushort(h0);
    lo = ((uint32_t)__bfloat16_as_ushort(l1) << 16) | __bfloat16_as_ushort(l0);
}
__device__ __forceinline__ uint32_t pack_h2(float x0, float x1) {
    __half2 p = __floats2half2_rn(x0, x1);   // low = x0
    return *reinterpret_cast<uint32_t*>(&p);
}

#define LDSM_X4(r0, r1, r2, r3, addr) \
    asm volatile("ldmatrix.sync.aligned.m8n8.x4.shared.b16 {%0,%1,%2,%3}, [%4];" \
        : "=r"(r0), "=r"(r1), "=r"(r2), "=r"(r3) : "r"(addr))
#define LDSM_X4_T(r0, r1, r2, r3, addr) \
    asm volatile("ldmatrix.sync.aligned.m8n8.x4.trans.shared.b16 {%0,%1,%2,%3}, [%4];" \
        : "=r"(r0), "=r"(r1), "=r"(r2), "=r"(r3) : "r"(addr))

__device__ __forceinline__ void mma_bf16(float* c, const uint32_t* a, const uint32_t* b) {
    asm volatile(
        "mma.sync.aligned.m16n8k16.row.col.f32.bf16.bf16.f32 "
        "{%0,%1,%2,%3}, {%4,%5,%6,%7}, {%8,%9}, {%0,%1,%2,%3};"
        : "+f"(c[0]), "+f"(c[1]), "+f"(c[2]), "+f"(c[3])
        : "r"(a[0]), "r"(a[1]), "r"(a[2]), "r"(a[3]), "r"(b[0]), "r"(b[1]));
}
__device__ __forceinline__ void mma_f16(float* c, const uint32_t* a, const uint32_t* b) {
    asm volatile(
        "mma.sync.aligned.m16n8k16.row.col.f32.f16.f16.f32 "
        "{%0,%1,%2,%3}, {%4,%5,%6,%7}, {%8,%9}, {%0,%1,%2,%3};"
        : "+f"(c[0]), "+f"(c[1]), "+f"(c[2]), "+f"(c[3])
        : "r"(a[0]), "r"(a[1]), "r"(a[2]), "r"(a[3]), "r"(b[0]), "r"(b[1]));
}

#define CP16(dst, src) \
    asm volatile("cp.async.cg.shared.global [%0], [%1], 16;" :: "r"((uint32_t)(dst)), "l"(src) : "memory")
#define CP_COMMIT() asm volatile("cp.async.commit_group;" ::: "memory")
#define CP_WAIT(n)  asm volatile("cp.async.wait_group %0;" :: "n"(n) : "memory")

// ---------------- LayerNorm -> bf16 hi/lo planes ----------------
__global__ __launch_bounds__(256) void ln_split(const float* __restrict__ x,
                                                const float* __restrict__ w,
                                                const float* __restrict__ b,
                                                int dst)
{
    bf16* yh = dst ? g_aah : g_tah;
    bf16* yl = dst ? g_aal : g_tal;
    int row = blockIdx.x, t = threadIdx.x;
    float4 xv = reinterpret_cast<const float4*>(x)[(size_t)row * 256 + t];
    float s  = xv.x + xv.y + xv.z + xv.w;
    float ss = xv.x*xv.x + xv.y*xv.y + xv.z*xv.z + xv.w*xv.w;
#pragma unroll
    for (int o = 16; o > 0; o >>= 1) {
        s  += __shfl_xor_sync(0xffffffffu, s,  o);
        ss += __shfl_xor_sync(0xffffffffu, ss, o);
    }
    __shared__ float rs[8], rss[8];
    if ((t & 31) == 0) { rs[t >> 5] = s; rss[t >> 5] = ss; }
    __syncthreads();
    float tot = 0.f, tot2 = 0.f;
#pragma unroll
    for (int i = 0; i < 8; i++) { tot += rs[i]; tot2 += rss[i]; }
    float mean = tot * (1.f / 1024.f);
    float var  = tot2 * (1.f / 1024.f) - mean * mean;
    float rstd = rsqrtf(var + 1e-5f);
    float4 wv = reinterpret_cast<const float4*>(w)[t];
    float4 bv = reinterpret_cast<const float4*>(b)[t];
    float o0 = (xv.x - mean) * rstd * wv.x + bv.x;
    float o1 = (xv.y - mean) * rstd * wv.y + bv.y;
    float o2 = (xv.z - mean) * rstd * wv.z + bv.z;
    float o3 = (xv.w - mean) * rstd * wv.w + bv.w;
    uint32_t h0, l0, h1, l1;
    split_pack(o0, o1, h0, l0);
    split_pack(o2, o3, h1, l1);
    *reinterpret_cast<uint2*>(reinterpret_cast<char*>(yh) + (size_t)row * 2048 + t * 8) = make_uint2(h0, h1);
    *reinterpret_cast<uint2*>(reinterpret_cast<char*>(yl) + (size_t)row * 2048 + t * 8) = make_uint2(l0, l1);
}

// ---------------- W[n][k] -> W^T[k][n] hi/lo ----------------
__global__ void wsplit(const float* __restrict__ Wq,
                       const float* __restrict__ Wk,
                       const float* __restrict__ Wv)
{
    int wsel = blockIdx.z;
    const float* W = (wsel == 0) ? Wq : (wsel == 1) ? Wk : Wv;
    bf16* th = g_wth[wsel];
    bf16* tl = g_wtl[wsel];
    __shared__ float tile[32][33];
    int k = blockIdx.x * 32 + threadIdx.x;
    int n0 = blockIdx.y * 32;
#pragma unroll
    for (int i = threadIdx.y; i < 32; i += 8)
        tile[i][threadIdx.x] = W[(size_t)(n0 + i) * 1024 + k];
    __syncthreads();
#pragma unroll
    for (int i = threadIdx.y; i < 32; i += 8) {
        float v = tile[threadIdx.x][i];
        __nv_bfloat16 h = __float2bfloat16(v);
        __nv_bfloat16 l = __float2bfloat16(v - __bfloat162float(h));
        size_t idx = (size_t)(blockIdx.x * 32 + i) * 1024 + n0 + threadIdx.x;
        th[idx] = h;
        tl[idx] = l;
    }
}

// ---------------- projection GEMM: bf16x3 compute, fp16 output ----------------
#define G_AHOFF 0
#define G_ALOFF 6144
#define G_BHOFF 12288
#define G_BLOFF 16640
#define G_STAGE 20992

__global__ __launch_bounds__(512, 1) void gemm_tc(int src, int dst,
                                                  const float* __restrict__ bias)
{
    extern __shared__ __align__(16) uint8_t smg[];
    const bf16* Ah = src ? g_aah : g_tah;
    const bf16* Al = src ? g_aal : g_tal;
    const bf16* Bh = g_wth[dst];
    const bf16* Bl = g_wtl[dst];
    __half* Cf = (dst == 0) ? g_qf : (dst == 1) ? g_kf : g_vf;

    int t = threadIdx.x, lane = t & 31, warp = t >> 5;
    int wm = warp >> 2, wn = warp & 3;
    int bm = blockIdx.x * 128, bn = blockIdx.y * 128;
    uint32_t smb = smem_to_u32(smg);

    bool isA = t < 256;
    int u = t & 255;
    int arow = u >> 1, aseg = u & 1;
    int brow = u >> 4, bseg = u & 15;
    const bf16* agh = Ah + (size_t)(bm + arow) * 1024 + aseg * 8;
    const bf16* agl = Al + (size_t)(bm + arow) * 1024 + aseg * 8;
    const bf16* bgh = Bh + (size_t)brow * 1024 + bn + bseg * 8;
    const bf16* bgl = Bl + (size_t)brow * 1024 + bn + bseg * 8;
    uint32_t a_dst = arow * 48 + aseg * 16;
    uint32_t b_dst = brow * 272 + bseg * 16;

    auto issue = [&](int ch) {
        uint32_t base = smb + (uint32_t)((ch & 3) * G_STAGE);
        if (isA) {
            CP16(base + G_AHOFF + a_dst, agh + ch * 16);
            CP16(base + G_ALOFF + a_dst, agl + ch * 16);
        } else {
            CP16(base + G_BHOFF + b_dst, bgh + (size_t)ch * 16 * 1024);
            CP16(base + G_BLOFF + b_dst, bgl + (size_t)ch * 16 * 1024);
        }
    };

    float acc[2][4][4];
#pragma unroll
    for (int i = 0; i < 2; i++)
#pragma unroll
        for (int j = 0; j < 4; j++)
#pragma unroll
            for (int e = 0; e < 4; e++) acc[i][j][e] = 0.f;

    issue(0); CP_COMMIT();
    issue(1); CP_COMMIT();
    issue(2); CP_COMMIT();

    uint32_t a_off = (lane & 15) * 48 + (lane >> 4) * 16;
    uint32_t b_off = ((lane & 7) + ((lane >> 3) & 1) * 8) * 272 + (lane >> 4) * 16;

    for (int ch = 0; ch < 64; ch++) {
        CP_WAIT(2);
        __syncthreads();
        if (ch + 3 < 64) issue(ch + 3);
        CP_COMMIT();

        uint32_t base = smb + (uint32_t)((ch & 3) * G_STAGE);
        uint32_t ah[2][4], al[2][4], bh2[4][2], bl2[4][2];
#pragma unroll
        for (int mt = 0; mt < 2; mt++) {
            uint32_t r = base + G_AHOFF + (uint32_t)((wm * 32 + mt * 16) * 48) + a_off;
            LDSM_X4(ah[mt][0], ah[mt][1], ah[mt][2], ah[mt][3], r);
            uint32_t rl = base + G_ALOFF + (uint32_t)((wm * 32 + mt * 16) * 48) + a_off;
            LDSM_X4(al[mt][0], al[mt][1], al[mt][2], al[mt][3], rl);
        }
#pragma unroll
        for (int pp = 0; pp < 2; pp++) {
            uint32_t r = base + G_BHOFF + (uint32_t)((wn * 32 + pp * 16) * 2) + b_off;
            LDSM_X4_T(bh2[pp*2][0], bh2[pp*2][1], bh2[pp*2+1][0], bh2[pp*2+1][1], r);
            uint32_t rl = base + G_BLOFF + (uint32_t)((wn * 32 + pp * 16) * 2) + b_off;
            LDSM_X4_T(bl2[pp*2][0], bl2[pp*2][1], bl2[pp*2+1][0], bl2[pp*2+1][1], rl);
        }
#pragma unroll
        for (int mt = 0; mt < 2; mt++)
#pragma unroll
            for (int nt = 0; nt < 4; nt++) {
                mma_bf16(acc[mt][nt], ah[mt], bh2[nt]);
                mma_bf16(acc[mt][nt], ah[mt], bl2[nt]);
                mma_bf16(acc[mt][nt], al[mt], bh2[nt]);
            }
    }

    int lr = lane >> 2, lc = (lane & 3) * 2;
#pragma unroll
    for (int nt = 0; nt < 4; nt++) {
        int col = bn + wn * 32 + nt * 8 + lc;
        float b0 = __ldg(bias + col), b1 = __ldg(bias + col + 1);
#pragma unroll
        for (int mt = 0; mt < 2; mt++) {
            int row = bm + wm * 32 + mt * 16 + lr;
            *reinterpret_cast<uint32_t*>(reinterpret_cast<char*>(Cf) + ((size_t)row * 1024 + col) * 2) =
                pack_h2(acc[mt][nt][0] + b0, acc[mt][nt][1] + b1);
            *reinterpret_cast<uint32_t*>(reinterpret_cast<char*>(Cf) + ((size_t)(row + 8) * 1024 + col) * 2) =
                pack_h2(acc[mt][nt][2] + b0, acc[mt][nt][3] + b1);
        }
    }
}

// ---------------- score+mean: fp16, per (b, q-tile, k-tile), loop 16 heads ----------------
// smem per buffer: Q [128][144B] + K [128][144B] = 36864; double buffered
#define S_Q 0
#define S_K 18432
#define S_BUF 36864

__global__ __launch_bounds__(512, 1) void score_mean_tc(float* __restrict__ amean)
{
    extern __shared__ __align__(16) uint8_t smg[];
    int b = blockIdx.z;
    int q0 = blockIdx.y * 128, k0 = blockIdx.x * 128;
    int t = threadIdx.x, lane = t & 31, warp = t >> 5;       // 16 warps
    int wm = warp >> 2, wn = warp & 3;                        // 32x32 warp tile
    uint32_t smb = smem_to_u32(smg);

    // staging: 2 planes x 128 rows x 128B; 512 threads -> half-row each (4x CP16)
    int plane = t >> 8, v = (t & 255) >> 1, hseg = t & 1;
    const __half* srcp = plane ? (g_kf + (size_t)(b * 1024 + k0 + v) * 1024)
                               : (g_qf + (size_t)(b * 512  + q0 + v) * 1024);
    uint32_t doff = (plane ? S_K : S_Q) + v * 144 + hseg * 64;

    auto issue = [&](int h) {
        uint32_t base = smb + (uint32_t)((h & 1) * S_BUF);
        const __half* s = srcp + h * 64 + hseg * 32;
#pragma unroll
        for (int seg = 0; seg < 4; seg++)
            CP16(base + doff + seg * 16, s + seg * 8);
    };

    uint32_t a_off = (lane & 15) * 144 + (lane >> 4) * 16;
    uint32_t b_off = ((lane & 7) + ((lane >> 4) & 1) * 8) * 144 + ((lane >> 3) & 1) * 16;

    float am[2][4][4];
#pragma unroll
    for (int i = 0; i < 2; i++)
#pragma unroll
        for (int j = 0; j < 4; j++)
#pragma unroll
            for (int e = 0; e < 4; e++) am[i][j][e] = 0.f;

    int lr = lane >> 2, lc = (lane & 3) * 2;

    issue(0); CP_COMMIT();

    for (int h = 0; h < 16; h++) {
        if (h < 15) { issue(h + 1); CP_COMMIT(); CP_WAIT(1); }
        else        { CP_WAIT(0); }
        __syncthreads();

        uint32_t base = smb + (uint32_t)((h & 1) * S_BUF);
        float acc[2][4][4];
#pragma unroll
        for (int i = 0; i < 2; i++)
#pragma unroll
            for (int j = 0; j < 4; j++)
#pragma unroll
                for (int e = 0; e < 4; e++) acc[i][j][e] = 0.f;

#pragma unroll
        for (int kc = 0; kc < 4; kc++) {
            uint32_t af[2][4], bf[4][2];
#pragma unroll
            for (int mt = 0; mt < 2; mt++) {
                uint32_t r = base + S_Q + (uint32_t)((wm * 32 + mt * 16) * 144) + kc * 32 + a_off;
                LDSM_X4(af[mt][0], af[mt][1], af[mt][2], af[mt][3], r);
            }
#pragma unroll
            for (int pp = 0; pp < 2; pp++) {
                uint32_t r = base + S_K + (uint32_t)((wn * 32 + pp * 16) * 144) + kc * 32 + b_off;
                LDSM_X4(bf[pp*2][0], bf[pp*2][1], bf[pp*2+1][0], bf[pp*2+1][1], r);
            }
#pragma unroll
            for (int mt = 0; mt < 2; mt++)
#pragma unroll
                for (int nt = 0; nt < 4; nt++)
                    mma_f16(acc[mt][nt], af[mt], bf[nt]);
        }

        // sigmoid, accumulate mean, store S fp16
        size_t splane = ((size_t)b * 16 + h) * 524288;
#pragma unroll
        for (int mt = 0; mt < 2; mt++)
#pragma unroll
            for (int nt = 0; nt < 4; nt++) {
                float s0 = 1.f / (1.f + __expf(-0.125f * acc[mt][nt][0]));
                float s1 = 1.f / (1.f + __expf(-0.125f * acc[mt][nt][1]));
                float s2 = 1.f / (1.f + __expf(-0.125f * acc[mt][nt][2]));
                float s3 = 1.f / (1.f + __expf(-0.125f * acc[mt][nt][3]));
                am[mt][nt][0] += s0; am[mt][nt][1] += s1;
                am[mt][nt][2] += s2; am[mt][nt][3] += s3;
                int row = q0 + wm * 32 + mt * 16 + lr;
                int col = k0 + wn * 32 + nt * 8 + lc;
                *reinterpret_cast<uint32_t*>(reinterpret_cast<char*>(g_sf) + (splane + (size_t)row * 1024 + col) * 2) =
                    pack_h2(s0, s1);
                *reinterpret_cast<uint32_t*>(reinterpret_cast<char*>(g_sf) + (splane + (size_t)(row + 8) * 1024 + col) * 2) =
                    pack_h2(s2, s3);
            }
        __syncthreads();
    }

#pragma unroll
    for (int mt = 0; mt < 2; mt++)
#pragma unroll
        for (int nt = 0; nt < 4; nt++) {
            int row = q0 + wm * 32 + mt * 16 + lr;
            int col = k0 + wn * 32 + nt * 8 + lc;
            *reinterpret_cast<float2*>(amean + ((size_t)(b * 512) + row) * 1024 + col) =
                make_float2(am[mt][nt][0] * 0.0625f, am[mt][nt][1] * 0.0625f);
            *reinterpret_cast<float2*>(amean + ((size_t)(b * 512) + row + 8) * 1024 + col) =
                make_float2(am[mt][nt][2] * 0.0625f, am[mt][nt][3] * 0.0625f);
        }
}

// ---------------- AV: out = S @ V, fp16 ----------------
// smem per stage: S [128][48B] = 6144, V [16][144B] = 2304 -> 8448; 4 stages
#define A_S 0
#define A_V 6144
#define A_STAGE 8448

__global__ __launch_bounds__(256, 2) void av_tc(float* __restrict__ out)
{
    extern __shared__ __align__(16) uint8_t smg[];
    int bh = blockIdx.y, b = bh >> 4, h = bh & 15;
    int q0 = blockIdx.x * 128;
    int t = threadIdx.x, lane = t & 31, warp = t >> 5;
    int wm = warp >> 1, wn = warp & 1;                        // 4x2 warps, 32x32 tiles
    uint32_t smb = smem_to_u32(smg);

    int srow = t >> 1, sseg = t & 1;
    uint32_t s_dst = srow * 48 + sseg * 16;
    const __half* sg = g_sf + ((size_t)bh * 512 + q0 + srow) * 1024 + sseg * 8;
    int vrow = (t & 127) >> 3, vseg = t & 7;
    uint32_t v_dst = A_V + vrow * 144 + vseg * 16;
    const __half* vg = g_vf + (size_t)(b * 1024 + vrow) * 1024 + h * 64 + vseg * 8;
    bool doV = t < 128;

    auto issue = [&](int ch) {
        uint32_t base = smb + (uint32_t)((ch & 3) * A_STAGE);
        CP16(base + A_S + s_dst, sg + ch * 16);
        if (doV) CP16(base + v_dst, vg + (size_t)ch * 16 * 1024);
    };

    float acc[2][4][4];
#pragma unroll
    for (int i = 0; i < 2; i++)
#pragma unroll
        for (int j = 0; j < 4; j++)
#pragma unroll
            for (int e = 0; e < 4; e++) acc[i][j][e] = 0.f;

    issue(0); CP_COMMIT();
    issue(1); CP_COMMIT();
    issue(2); CP_COMMIT();

    uint32_t a_off = (lane & 15) * 48 + (lane >> 4) * 16;
    uint32_t b_off = ((lane & 7) + ((lane >> 3) & 1) * 8) * 144 + (lane >> 4) * 16;

    for (int ch = 0; ch < 64; ch++) {
        CP_WAIT(2);
        __syncthreads();
        if (ch + 3 < 64) issue(ch + 3);
        CP_COMMIT();

        uint32_t base = smb + (uint32_t)((ch & 3) * A_STAGE);
        uint32_t af[2][4], bf[4][2];
#pragma unroll
        for (int mt = 0; mt < 2; mt++) {
            uint32_t r = base + A_S + (uint32_t)((wm * 32 + mt * 16) * 48) + a_off;
            LDSM_X4(af[mt][0], af[mt][1], af[mt][2], af[mt][3], r);
        }
#pragma unroll
        for (int pp = 0; pp < 2; pp++) {
            uint32_t r = base + A_V + (uint32_t)((wn * 32 + pp * 16) * 2) + b_off;
            LDSM_X4_T(bf[pp*2][0], bf[pp*2][1], bf[pp*2+1][0], bf[pp*2+1][1], r);
        }
#pragma unroll
        for (int mt = 0; mt < 2; mt++)
#pragma unroll
            for (int nt = 0; nt < 4; nt++)
                mma_f16(acc[mt][nt], af[mt], bf[nt]);
    }

    int lr = lane >> 2, lc = (lane & 3) * 2;
#pragma unroll
    for (int nt = 0; nt < 4; nt++) {
        int col = h * 64 + wn * 32 + nt * 8 + lc;
#pragma unroll
        for (int mt = 0; mt < 2; mt++) {
            int row = b * 512 + q0 + wm * 32 + mt * 16 + lr;
            *reinterpret_cast<float2*>(out + (size_t)row * 1024 + col) =
                make_float2(acc[mt][nt][0], acc[mt][nt][1]);
            *reinterpret_cast<float2*>(out + (size_t)(row + 8) * 1024 + col) =
                make_float2(acc[mt][nt][2], acc[mt][nt][3]);
        }
    }
}

// ---------------- launch ----------------
extern "C" void kernel_launch(void* const* d_in, const int* in_sizes, int n_in,
                              void* d_out, int out_size)
{
    (void)in_sizes; (void)n_in; (void)out_size;
    const float* text = (const float*)d_in[0];
    const float* av   = (const float*)d_in[1];
    const float* tn_w = (const float*)d_in[2];
    const float* tn_b = (const float*)d_in[3];
    const float* an_w = (const float*)d_in[4];
    const float* an_b = (const float*)d_in[5];
    const float* Wq   = (const float*)d_in[6];
    const float* bq   = (const float*)d_in[7];
    const float* Wk   = (const float*)d_in[8];
    const float* bk   = (const float*)d_in[9];
    const float* Wv   = (const float*)d_in[10];
    const float* bv   = (const float*)d_in[11];

    float* out   = (float*)d_out;
    float* amean = out + (size_t)BS * NW * 1024;

    static int attr_done = 0;
    if (!attr_done) {
        cudaFuncSetAttribute(gemm_tc,       cudaFuncAttributeMaxDynamicSharedMemorySize, 4 * G_STAGE);
        cudaFuncSetAttribute(score_mean_tc, cudaFuncAttributeMaxDynamicSharedMemorySize, 2 * S_BUF);
        cudaFuncSetAttribute(av_tc,         cudaFuncAttributeMaxDynamicSharedMemorySize, 4 * A_STAGE);
        attr_done = 1;
    }

    ln_split<<<BS * NW, 256>>>(text, tn_w, tn_b, 0);
    ln_split<<<BS * NV, 256>>>(av, an_w, an_b, 1);
    wsplit<<<dim3(32, 32, 3), dim3(32, 8)>>>(Wq, Wk, Wv);

    gemm_tc<<<dim3(32, 8), 512, 4 * G_STAGE>>>(0, 0, bq);
    gemm_tc<<<dim3(64, 8), 512, 4 * G_STAGE>>>(1, 1, bk);
    gemm_tc<<<dim3(64, 8), 512, 4 * G_STAGE>>>(1, 2, bv);

    score_mean_tc<<<dim3(8, 4, 8), 512, 2 * S_BUF>>>(amean);
    av_tc<<<dim3(4, 128), 256, 4 * A_STAGE>>>(out);
}

// round 8
// speedup vs baseline: 2.2703x; 1.6181x over previous
#include <cuda_runtime.h>
#include <cuda_fp16.h>
#include <cstdint>

#define BS 8
#define NW 512
#define NV 1024

// ---------------- fp16 scratch (allocation-free) ----------------
__device__ __half g_taf[BS*NW*1024];                       // LN(text)
__device__ __half g_aaf[BS*NV*1024];                       // LN(av)
__device__ __half g_wtf[3][1024*1024];                     // W^T [k][n]
__device__ __half g_qf[BS*NW*1024];
__device__ __half g_kf[BS*NV*1024];
__device__ __half g_vf[BS*NV*1024];
__device__ __half g_sf[(size_t)BS*16*NW*NV];               // sigmoid scores, 128 MB

// ---------------- helpers ----------------
__device__ __forceinline__ uint32_t smem_to_u32(const void* p) {
    uint32_t a;
    asm("{ .reg .u64 t; cvta.to.shared.u64 t, %1; cvt.u32.u64 %0, t; }" : "=r"(a) : "l"(p));
    return a;
}
__device__ __forceinline__ uint32_t pack_h2(float x0, float x1) {
    __half2 p = __floats2half2_rn(x0, x1);   // low = x0
    return *reinterpret_cast<uint32_t*>(&p);
}

#define LDSM_X4(r0, r1, r2, r3, addr) \
    asm volatile("ldmatrix.sync.aligned.m8n8.x4.shared.b16 {%0,%1,%2,%3}, [%4];" \
        : "=r"(r0), "=r"(r1), "=r"(r2), "=r"(r3) : "r"(addr))
#define LDSM_X4_T(r0, r1, r2, r3, addr) \
    asm volatile("ldmatrix.sync.aligned.m8n8.x4.trans.shared.b16 {%0,%1,%2,%3}, [%4];" \
        : "=r"(r0), "=r"(r1), "=r"(r2), "=r"(r3) : "r"(addr))

__device__ __forceinline__ void mma_f16(float* c, const uint32_t* a, const uint32_t* b) {
    asm volatile(
        "mma.sync.aligned.m16n8k16.row.col.f32.f16.f16.f32 "
        "{%0,%1,%2,%3}, {%4,%5,%6,%7}, {%8,%9}, {%0,%1,%2,%3};"
        : "+f"(c[0]), "+f"(c[1]), "+f"(c[2]), "+f"(c[3])
        : "r"(a[0]), "r"(a[1]), "r"(a[2]), "r"(a[3]), "r"(b[0]), "r"(b[1]));
}

#define CP16(dst, src) \
    asm volatile("cp.async.cg.shared.global [%0], [%1], 16;" :: "r"((uint32_t)(dst)), "l"(src) : "memory")
#define CP_COMMIT() asm volatile("cp.async.commit_group;" ::: "memory")
#define CP_WAIT(n)  asm volatile("cp.async.wait_group %0;" :: "n"(n) : "memory")

// ---------------- LayerNorm -> fp16 ----------------
__global__ __launch_bounds__(256) void ln_f16(const float* __restrict__ x,
                                              const float* __restrict__ w,
                                              const float* __restrict__ b,
                                              int dst)
{
    __half* y = dst ? g_aaf : g_taf;
    int row = blockIdx.x, t = threadIdx.x;
    float4 xv = reinterpret_cast<const float4*>(x)[(size_t)row * 256 + t];
    float s  = xv.x + xv.y + xv.z + xv.w;
    float ss = xv.x*xv.x + xv.y*xv.y + xv.z*xv.z + xv.w*xv.w;
#pragma unroll
    for (int o = 16; o > 0; o >>= 1) {
        s  += __shfl_xor_sync(0xffffffffu, s,  o);
        ss += __shfl_xor_sync(0xffffffffu, ss, o);
    }
    __shared__ float rs[8], rss[8];
    if ((t & 31) == 0) { rs[t >> 5] = s; rss[t >> 5] = ss; }
    __syncthreads();
    float tot = 0.f, tot2 = 0.f;
#pragma unroll
    for (int i = 0; i < 8; i++) { tot += rs[i]; tot2 += rss[i]; }
    float mean = tot * (1.f / 1024.f);
    float var  = tot2 * (1.f / 1024.f) - mean * mean;
    float rstd = rsqrtf(var + 1e-5f);
    float4 wv = reinterpret_cast<const float4*>(w)[t];
    float4 bv = reinterpret_cast<const float4*>(b)[t];
    float o0 = (xv.x - mean) * rstd * wv.x + bv.x;
    float o1 = (xv.y - mean) * rstd * wv.y + bv.y;
    float o2 = (xv.z - mean) * rstd * wv.z + bv.z;
    float o3 = (xv.w - mean) * rstd * wv.w + bv.w;
    *reinterpret_cast<uint2*>(reinterpret_cast<char*>(y) + (size_t)row * 2048 + t * 8) =
        make_uint2(pack_h2(o0, o1), pack_h2(o2, o3));
}

// ---------------- W[n][k] -> W^T[k][n] fp16 ----------------
__global__ void wsplit(const float* __restrict__ Wq,
                       const float* __restrict__ Wk,
                       const float* __restrict__ Wv)
{
    int wsel = blockIdx.z;
    const float* W = (wsel == 0) ? Wq : (wsel == 1) ? Wk : Wv;
    __half* tf = g_wtf[wsel];
    __shared__ float tile[32][33];
    int k = blockIdx.x * 32 + threadIdx.x;
    int n0 = blockIdx.y * 32;
#pragma unroll
    for (int i = threadIdx.y; i < 32; i += 8)
        tile[i][threadIdx.x] = W[(size_t)(n0 + i) * 1024 + k];
    __syncthreads();
#pragma unroll
    for (int i = threadIdx.y; i < 32; i += 8) {
        float v = tile[threadIdx.x][i];
        size_t idx = (size_t)(blockIdx.x * 32 + i) * 1024 + n0 + threadIdx.x;
        tf[idx] = __float2half_rn(v);
    }
}

// ---------------- projection GEMM: fp16 single-plane ----------------
// smem stage: A [128 rows][16 fp16 pad 48B] = 6144, B [16 k][128 n pad 272B] = 4352
#define G_A 0
#define G_B 6144
#define G_STAGE 10496

__global__ __launch_bounds__(512, 1) void gemm_tc(int src, int dst,
                                                  const float* __restrict__ bias)
{
    extern __shared__ __align__(16) uint8_t smg[];
    const __half* Af = src ? g_aaf : g_taf;
    const __half* Bf = g_wtf[dst];
    __half* Cf = (dst == 0) ? g_qf : (dst == 1) ? g_kf : g_vf;

    int t = threadIdx.x, lane = t & 31, warp = t >> 5;   // 16 warps, 4x4
    int wm = warp >> 2, wn = warp & 3;
    int bm = blockIdx.x * 128, bn = blockIdx.y * 128;
    uint32_t smb = smem_to_u32(smg);

    bool isA = t < 256;
    int u = t & 255;
    int arow = u >> 1, aseg = u & 1;
    int brow = u >> 4, bseg = u & 15;
    const __half* agf = Af + (size_t)(bm + arow) * 1024 + aseg * 8;
    const __half* bgf = Bf + (size_t)brow * 1024 + bn + bseg * 8;
    uint32_t a_dst = arow * 48 + aseg * 16;
    uint32_t b_dst = brow * 272 + bseg * 16;

    auto issue = [&](int ch) {
        uint32_t base = smb + (uint32_t)((ch & 3) * G_STAGE);
        if (isA) CP16(base + G_A + a_dst, agf + ch * 16);
        else     CP16(base + G_B + b_dst, bgf + (size_t)ch * 16 * 1024);
    };

    float acc[2][4][4];
#pragma unroll
    for (int i = 0; i < 2; i++)
#pragma unroll
        for (int j = 0; j < 4; j++)
#pragma unroll
            for (int e = 0; e < 4; e++) acc[i][j][e] = 0.f;

    issue(0); CP_COMMIT();
    issue(1); CP_COMMIT();
    issue(2); CP_COMMIT();

    uint32_t a_off = (lane & 15) * 48 + (lane >> 4) * 16;
    uint32_t b_off = ((lane & 7) + ((lane >> 3) & 1) * 8) * 272 + (lane >> 4) * 16;

    for (int ch = 0; ch < 64; ch++) {
        CP_WAIT(2);
        __syncthreads();
        if (ch + 3 < 64) issue(ch + 3);
        CP_COMMIT();

        uint32_t base = smb + (uint32_t)((ch & 3) * G_STAGE);
        uint32_t af[2][4], bf[4][2];
#pragma unroll
        for (int mt = 0; mt < 2; mt++) {
            uint32_t r = base + G_A + (uint32_t)((wm * 32 + mt * 16) * 48) + a_off;
            LDSM_X4(af[mt][0], af[mt][1], af[mt][2], af[mt][3], r);
        }
#pragma unroll
        for (int pp = 0; pp < 2; pp++) {
            uint32_t r = base + G_B + (uint32_t)((wn * 32 + pp * 16) * 2) + b_off;
            LDSM_X4_T(bf[pp*2][0], bf[pp*2][1], bf[pp*2+1][0], bf[pp*2+1][1], r);
        }
#pragma unroll
        for (int mt = 0; mt < 2; mt++)
#pragma unroll
            for (int nt = 0; nt < 4; nt++)
                mma_f16(acc[mt][nt], af[mt], bf[nt]);
    }

    int lr = lane >> 2, lc = (lane & 3) * 2;
#pragma unroll
    for (int nt = 0; nt < 4; nt++) {
        int col = bn + wn * 32 + nt * 8 + lc;
        float b0 = __ldg(bias + col), b1 = __ldg(bias + col + 1);
#pragma unroll
        for (int mt = 0; mt < 2; mt++) {
            int row = bm + wm * 32 + mt * 16 + lr;
            *reinterpret_cast<uint32_t*>(reinterpret_cast<char*>(Cf) + ((size_t)row * 1024 + col) * 2) =
                pack_h2(acc[mt][nt][0] + b0, acc[mt][nt][1] + b1);
            *reinterpret_cast<uint32_t*>(reinterpret_cast<char*>(Cf) + ((size_t)(row + 8) * 1024 + col) * 2) =
                pack_h2(acc[mt][nt][2] + b0, acc[mt][nt][3] + b1);
        }
    }
}

// ---------------- score+mean: fp16, per (b, q-tile, k-tile), loop 16 heads ----------------
#define S_Q 0
#define S_K 18432
#define S_BUF 36864

__global__ __launch_bounds__(512, 1) void score_mean_tc(float* __restrict__ amean)
{
    extern __shared__ __align__(16) uint8_t smg[];
    int b = blockIdx.z;
    int q0 = blockIdx.y * 128, k0 = blockIdx.x * 128;
    int t = threadIdx.x, lane = t & 31, warp = t >> 5;
    int wm = warp >> 2, wn = warp & 3;
    uint32_t smb = smem_to_u32(smg);

    int plane = t >> 8, v = (t & 255) >> 1, hseg = t & 1;
    const __half* srcp = plane ? (g_kf + (size_t)(b * 1024 + k0 + v) * 1024)
                               : (g_qf + (size_t)(b * 512  + q0 + v) * 1024);
    uint32_t doff = (plane ? S_K : S_Q) + v * 144 + hseg * 64;

    auto issue = [&](int h) {
        uint32_t base = smb + (uint32_t)((h & 1) * S_BUF);
        const __half* s = srcp + h * 64 + hseg * 32;
#pragma unroll
        for (int seg = 0; seg < 4; seg++)
            CP16(base + doff + seg * 16, s + seg * 8);
    };

    uint32_t a_off = (lane & 15) * 144 + (lane >> 4) * 16;
    uint32_t b_off = ((lane & 7) + ((lane >> 4) & 1) * 8) * 144 + ((lane >> 3) & 1) * 16;

    float am[2][4][4];
#pragma unroll
    for (int i = 0; i < 2; i++)
#pragma unroll
        for (int j = 0; j < 4; j++)
#pragma unroll
            for (int e = 0; e < 4; e++) am[i][j][e] = 0.f;

    int lr = lane >> 2, lc = (lane & 3) * 2;

    issue(0); CP_COMMIT();

    for (int h = 0; h < 16; h++) {
        if (h < 15) { issue(h + 1); CP_COMMIT(); CP_WAIT(1); }
        else        { CP_WAIT(0); }
        __syncthreads();

        uint32_t base = smb + (uint32_t)((h & 1) * S_BUF);
        float acc[2][4][4];
#pragma unroll
        for (int i = 0; i < 2; i++)
#pragma unroll
            for (int j = 0; j < 4; j++)
#pragma unroll
                for (int e = 0; e < 4; e++) acc[i][j][e] = 0.f;

#pragma unroll
        for (int kc = 0; kc < 4; kc++) {
            uint32_t af[2][4], bf[4][2];
#pragma unroll
            for (int mt = 0; mt < 2; mt++) {
                uint32_t r = base + S_Q + (uint32_t)((wm * 32 + mt * 16) * 144) + kc * 32 + a_off;
                LDSM_X4(af[mt][0], af[mt][1], af[mt][2], af[mt][3], r);
            }
#pragma unroll
            for (int pp = 0; pp < 2; pp++) {
                uint32_t r = base + S_K + (uint32_t)((wn * 32 + pp * 16) * 144) + kc * 32 + b_off;
                LDSM_X4(bf[pp*2][0], bf[pp*2][1], bf[pp*2+1][0], bf[pp*2+1][1], r);
            }
#pragma unroll
            for (int mt = 0; mt < 2; mt++)
#pragma unroll
                for (int nt = 0; nt < 4; nt++)
                    mma_f16(acc[mt][nt], af[mt], bf[nt]);
        }

        size_t splane = ((size_t)b * 16 + h) * 524288;
#pragma unroll
        for (int mt = 0; mt < 2; mt++)
#pragma unroll
            for (int nt = 0; nt < 4; nt++) {
                float s0 = 1.f / (1.f + __expf(-0.125f * acc[mt][nt][0]));
                float s1 = 1.f / (1.f + __expf(-0.125f * acc[mt][nt][1]));
                float s2 = 1.f / (1.f + __expf(-0.125f * acc[mt][nt][2]));
                float s3 = 1.f / (1.f + __expf(-0.125f * acc[mt][nt][3]));
                am[mt][nt][0] += s0; am[mt][nt][1] += s1;
                am[mt][nt][2] += s2; am[mt][nt][3] += s3;
                int row = q0 + wm * 32 + mt * 16 + lr;
                int col = k0 + wn * 32 + nt * 8 + lc;
                *reinterpret_cast<uint32_t*>(reinterpret_cast<char*>(g_sf) + (splane + (size_t)row * 1024 + col) * 2) =
                    pack_h2(s0, s1);
                *reinterpret_cast<uint32_t*>(reinterpret_cast<char*>(g_sf) + (splane + (size_t)(row + 8) * 1024 + col) * 2) =
                    pack_h2(s2, s3);
            }
        __syncthreads();
    }

#pragma unroll
    for (int mt = 0; mt < 2; mt++)
#pragma unroll
        for (int nt = 0; nt < 4; nt++) {
            int row = q0 + wm * 32 + mt * 16 + lr;
            int col = k0 + wn * 32 + nt * 8 + lc;
            *reinterpret_cast<float2*>(amean + ((size_t)(b * 512) + row) * 1024 + col) =
                make_float2(am[mt][nt][0] * 0.0625f, am[mt][nt][1] * 0.0625f);
            *reinterpret_cast<float2*>(amean + ((size_t)(b * 512) + row + 8) * 1024 + col) =
                make_float2(am[mt][nt][2] * 0.0625f, am[mt][nt][3] * 0.0625f);
        }
}

// ---------------- AV: out = S @ V, fp16 ----------------
#define A_S 0
#define A_V 6144
#define A_STAGE 8448

__global__ __launch_bounds__(256, 2) void av_tc(float* __restrict__ out)
{
    extern __shared__ __align__(16) uint8_t smg[];
    int bh = blockIdx.y, b = bh >> 4, h = bh & 15;
    int q0 = blockIdx.x * 128;
    int t = threadIdx.x, lane = t & 31, warp = t >> 5;
    int wm = warp >> 1, wn = warp & 1;
    uint32_t smb = smem_to_u32(smg);

    int srow = t >> 1, sseg = t & 1;
    uint32_t s_dst = srow * 48 + sseg * 16;
    const __half* sg = g_sf + ((size_t)bh * 512 + q0 + srow) * 1024 + sseg * 8;
    int vrow = (t & 127) >> 3, vseg = t & 7;
    uint32_t v_dst = A_V + vrow * 144 + vseg * 16;
    const __half* vg = g_vf + (size_t)(b * 1024 + vrow) * 1024 + h * 64 + vseg * 8;
    bool doV = t < 128;

    auto issue = [&](int ch) {
        uint32_t base = smb + (uint32_t)((ch & 3) * A_STAGE);
        CP16(base + A_S + s_dst, sg + ch * 16);
        if (doV) CP16(base + v_dst, vg + (size_t)ch * 16 * 1024);
    };

    float acc[2][4][4];
#pragma unroll
    for (int i = 0; i < 2; i++)
#pragma unroll
        for (int j = 0; j < 4; j++)
#pragma unroll
            for (int e = 0; e < 4; e++) acc[i][j][e] = 0.f;

    issue(0); CP_COMMIT();
    issue(1); CP_COMMIT();
    issue(2); CP_COMMIT();

    uint32_t a_off = (lane & 15) * 48 + (lane >> 4) * 16;
    uint32_t b_off = ((lane & 7) + ((lane >> 3) & 1) * 8) * 144 + (lane >> 4) * 16;

    for (int ch = 0; ch < 64; ch++) {
        CP_WAIT(2);
        __syncthreads();
        if (ch + 3 < 64) issue(ch + 3);
        CP_COMMIT();

        uint32_t base = smb + (uint32_t)((ch & 3) * A_STAGE);
        uint32_t af[2][4], bf[4][2];
#pragma unroll
        for (int mt = 0; mt < 2; mt++) {
            uint32_t r = base + A_S + (uint32_t)((wm * 32 + mt * 16) * 48) + a_off;
            LDSM_X4(af[mt][0], af[mt][1], af[mt][2], af[mt][3], r);
        }
#pragma unroll
        for (int pp = 0; pp < 2; pp++) {
            uint32_t r = base + A_V + (uint32_t)((wn * 32 + pp * 16) * 2) + b_off;
            LDSM_X4_T(bf[pp*2][0], bf[pp*2][1], bf[pp*2+1][0], bf[pp*2+1][1], r);
        }
#pragma unroll
        for (int mt = 0; mt < 2; mt++)
#pragma unroll
            for (int nt = 0; nt < 4; nt++)
                mma_f16(acc[mt][nt], af[mt], bf[nt]);
    }

    int lr = lane >> 2, lc = (lane & 3) * 2;
#pragma unroll
    for (int nt = 0; nt < 4; nt++) {
        int col = h * 64 + wn * 32 + nt * 8 + lc;
#pragma unroll
        for (int mt = 0; mt < 2; mt++) {
            int row = b * 512 + q0 + wm * 32 + mt * 16 + lr;
            *reinterpret_cast<float2*>(out + (size_t)row * 1024 + col) =
                make_float2(acc[mt][nt][0], acc[mt][nt][1]);
            *reinterpret_cast<float2*>(out + (size_t)(row + 8) * 1024 + col) =
                make_float2(acc[mt][nt][2], acc[mt][nt][3]);
        }
    }
}

// ---------------- launch ----------------
extern "C" void kernel_launch(void* const* d_in, const int* in_sizes, int n_in,
                              void* d_out, int out_size)
{
    (void)in_sizes; (void)n_in; (void)out_size;
    const float* text = (const float*)d_in[0];
    const float* av   = (const float*)d_in[1];
    const float* tn_w = (const float*)d_in[2];
    const float* tn_b = (const float*)d_in[3];
    const float* an_w = (const float*)d_in[4];
    const float* an_b = (const float*)d_in[5];
    const float* Wq   = (const float*)d_in[6];
    const float* bq   = (const float*)d_in[7];
    const float* Wk   = (const float*)d_in[8];
    const float* bk   = (const float*)d_in[9];
    const float* Wv   = (const float*)d_in[10];
    const float* bv   = (const float*)d_in[11];

    float* out   = (float*)d_out;
    float* amean = out + (size_t)BS * NW * 1024;

    static int attr_done = 0;
    if (!attr_done) {
        cudaFuncSetAttribute(gemm_tc,       cudaFuncAttributeMaxDynamicSharedMemorySize, 4 * G_STAGE);
        cudaFuncSetAttribute(score_mean_tc, cudaFuncAttributeMaxDynamicSharedMemorySize, 2 * S_BUF);
        cudaFuncSetAttribute(av_tc,         cudaFuncAttributeMaxDynamicSharedMemorySize, 4 * A_STAGE);
        attr_done = 1;
    }

    ln_f16<<<BS * NW, 256>>>(text, tn_w, tn_b, 0);
    ln_f16<<<BS * NV, 256>>>(av, an_w, an_b, 1);
    wsplit<<<dim3(32, 32, 3), dim3(32, 8)>>>(Wq, Wk, Wv);

    gemm_tc<<<dim3(32, 8), 512, 4 * G_STAGE>>>(0, 0, bq);
    gemm_tc<<<dim3(64, 8), 512, 4 * G_STAGE>>>(1, 1, bk);
    gemm_tc<<<dim3(64, 8), 512, 4 * G_STAGE>>>(1, 2, bv);

    score_mean_tc<<<dim3(8, 4, 8), 512, 2 * S_BUF>>>(amean);
    av_tc<<<dim3(4, 128), 256, 4 * A_STAGE>>>(out);
}

// round 9
// speedup vs baseline: 2.6829x; 1.1818x over previous
#include <cuda_runtime.h>
#include <cuda_fp16.h>
#include <cstdint>

#define BS 8
#define NW 512
#define NV 1024

// ---------------- fp16 scratch (allocation-free) ----------------
__device__ __half g_taf[BS*NW*1024];                       // LN(text)
__device__ __half g_aaf[BS*NV*1024];                       // LN(av)
__device__ __half g_wtf[3][1024*1024];                     // W^T [k][n]
__device__ __half g_qf[BS*NW*1024];
__device__ __half g_kf[BS*NV*1024];
__device__ __half g_vf[BS*NV*1024];
__device__ __half g_sf[(size_t)BS*16*NW*NV];               // sigmoid scores, 128 MB

// ---------------- helpers ----------------
__device__ __forceinline__ uint32_t smem_to_u32(const void* p) {
    uint32_t a;
    asm("{ .reg .u64 t; cvta.to.shared.u64 t, %1; cvt.u32.u64 %0, t; }" : "=r"(a) : "l"(p));
    return a;
}
__device__ __forceinline__ uint32_t pack_h2(float x0, float x1) {
    __half2 p = __floats2half2_rn(x0, x1);
    return *reinterpret_cast<uint32_t*>(&p);
}

#define LDSM_X4(r0, r1, r2, r3, addr) \
    asm volatile("ldmatrix.sync.aligned.m8n8.x4.shared.b16 {%0,%1,%2,%3}, [%4];" \
        : "=r"(r0), "=r"(r1), "=r"(r2), "=r"(r3) : "r"(addr))
#define LDSM_X4_T(r0, r1, r2, r3, addr) \
    asm volatile("ldmatrix.sync.aligned.m8n8.x4.trans.shared.b16 {%0,%1,%2,%3}, [%4];" \
        : "=r"(r0), "=r"(r1), "=r"(r2), "=r"(r3) : "r"(addr))

__device__ __forceinline__ void mma_f16(float* c, const uint32_t* a, const uint32_t* b) {
    asm volatile(
        "mma.sync.aligned.m16n8k16.row.col.f32.f16.f16.f32 "
        "{%0,%1,%2,%3}, {%4,%5,%6,%7}, {%8,%9}, {%0,%1,%2,%3};"
        : "+f"(c[0]), "+f"(c[1]), "+f"(c[2]), "+f"(c[3])
        : "r"(a[0]), "r"(a[1]), "r"(a[2]), "r"(a[3]), "r"(b[0]), "r"(b[1]));
}

#define CP16(dst, src) \
    asm volatile("cp.async.cg.shared.global [%0], [%1], 16;" :: "r"((uint32_t)(dst)), "l"(src) : "memory")
#define CP_COMMIT() asm volatile("cp.async.commit_group;" ::: "memory")
#define CP_WAIT(n)  asm volatile("cp.async.wait_group %0;" :: "n"(n) : "memory")

// ---------------- LayerNorm -> fp16 ----------------
__global__ __launch_bounds__(256) void ln_f16(const float* __restrict__ x,
                                              const float* __restrict__ w,
                                              const float* __restrict__ b,
                                              int dst)
{
    __half* y = dst ? g_aaf : g_taf;
    int row = blockIdx.x, t = threadIdx.x;
    float4 xv = reinterpret_cast<const float4*>(x)[(size_t)row * 256 + t];
    float s  = xv.x + xv.y + xv.z + xv.w;
    float ss = xv.x*xv.x + xv.y*xv.y + xv.z*xv.z + xv.w*xv.w;
#pragma unroll
    for (int o = 16; o > 0; o >>= 1) {
        s  += __shfl_xor_sync(0xffffffffu, s,  o);
        ss += __shfl_xor_sync(0xffffffffu, ss, o);
    }
    __shared__ float rs[8], rss[8];
    if ((t & 31) == 0) { rs[t >> 5] = s; rss[t >> 5] = ss; }
    __syncthreads();
    float tot = 0.f, tot2 = 0.f;
#pragma unroll
    for (int i = 0; i < 8; i++) { tot += rs[i]; tot2 += rss[i]; }
    float mean = tot * (1.f / 1024.f);
    float var  = tot2 * (1.f / 1024.f) - mean * mean;
    float rstd = rsqrtf(var + 1e-5f);
    float4 wv = reinterpret_cast<const float4*>(w)[t];
    float4 bv = reinterpret_cast<const float4*>(b)[t];
    float o0 = (xv.x - mean) * rstd * wv.x + bv.x;
    float o1 = (xv.y - mean) * rstd * wv.y + bv.y;
    float o2 = (xv.z - mean) * rstd * wv.z + bv.z;
    float o3 = (xv.w - mean) * rstd * wv.w + bv.w;
    *reinterpret_cast<uint2*>(reinterpret_cast<char*>(y) + (size_t)row * 2048 + t * 8) =
        make_uint2(pack_h2(o0, o1), pack_h2(o2, o3));
}

// ---------------- W[n][k] -> W^T[k][n] fp16 ----------------
__global__ void wsplit(const float* __restrict__ Wq,
                       const float* __restrict__ Wk,
                       const float* __restrict__ Wv)
{
    int wsel = blockIdx.z;
    const float* W = (wsel == 0) ? Wq : (wsel == 1) ? Wk : Wv;
    __half* tf = g_wtf[wsel];
    __shared__ float tile[32][33];
    int k = blockIdx.x * 32 + threadIdx.x;
    int n0 = blockIdx.y * 32;
#pragma unroll
    for (int i = threadIdx.y; i < 32; i += 8)
        tile[i][threadIdx.x] = W[(size_t)(n0 + i) * 1024 + k];
    __syncthreads();
#pragma unroll
    for (int i = threadIdx.y; i < 32; i += 8) {
        float v = tile[threadIdx.x][i];
        size_t idx = (size_t)(blockIdx.x * 32 + i) * 1024 + n0 + threadIdx.x;
        tf[idx] = __float2half_rn(v);
    }
}

// ---------------- projection GEMM: 128x256 tile, K-chunk 32, fp16 ----------------
// smem stage: A [128 rows][32 fp16 = 64B + 16 pad = 80B] = 10240
//             B [32 k][256 fp16 = 512B + 16 pad = 528B] = 16896
#define G_A 0
#define G_B 10240
#define G_STAGE 27136

__global__ __launch_bounds__(512, 1) void gemm_tc(int src, int dst,
                                                  const float* __restrict__ bias)
{
    extern __shared__ __align__(16) uint8_t smg[];
    const __half* Af = src ? g_aaf : g_taf;
    const __half* Bf = g_wtf[dst];
    __half* Cf = (dst == 0) ? g_qf : (dst == 1) ? g_kf : g_vf;

    int t = threadIdx.x, lane = t & 31, warp = t >> 5;   // 16 warps, 4x4
    int wm = warp >> 2, wn = warp & 3;                    // warp tile 32 x 64
    int bm = blockIdx.x * 128, bn = blockIdx.y * 256;
    uint32_t smb = smem_to_u32(smg);

    // staging: A 512 segs (1/thread), B 1024 segs (2/thread)
    int arow = t >> 2, aseg = t & 3;
    int brow = t >> 4, bseg = t & 15;
    const __half* agf = Af + (size_t)(bm + arow) * 1024 + aseg * 8;
    const __half* bgf = Bf + (size_t)brow * 1024 + bn + bseg * 8;
    uint32_t a_dst = arow * 80 + aseg * 16;
    uint32_t b_dst = brow * 528 + bseg * 16;

    auto issue = [&](int ch) {
        uint32_t base = smb + (uint32_t)((ch & 3) * G_STAGE);
        CP16(base + G_A + a_dst, agf + ch * 32);
        CP16(base + G_B + b_dst, bgf + (size_t)ch * 32 * 1024);
        CP16(base + G_B + b_dst + 256, bgf + (size_t)ch * 32 * 1024 + 128);
    };

    float acc[2][8][4];
#pragma unroll
    for (int i = 0; i < 2; i++)
#pragma unroll
        for (int j = 0; j < 8; j++)
#pragma unroll
            for (int e = 0; e < 4; e++) acc[i][j][e] = 0.f;

    issue(0); CP_COMMIT();
    issue(1); CP_COMMIT();
    issue(2); CP_COMMIT();

    uint32_t a_off = (lane & 15) * 80 + (lane >> 4) * 16;
    uint32_t b_off = ((lane & 7) + ((lane >> 3) & 1) * 8) * 528 + (lane >> 4) * 16;

    for (int ch = 0; ch < 32; ch++) {
        CP_WAIT(2);
        __syncthreads();
        if (ch + 3 < 32) issue(ch + 3);
        CP_COMMIT();

        uint32_t base = smb + (uint32_t)((ch & 3) * G_STAGE);
#pragma unroll
        for (int kc = 0; kc < 2; kc++) {
            uint32_t af[2][4], bf[8][2];
#pragma unroll
            for (int mt = 0; mt < 2; mt++) {
                uint32_t r = base + G_A + (uint32_t)((wm * 32 + mt * 16) * 80) + kc * 32 + a_off;
                LDSM_X4(af[mt][0], af[mt][1], af[mt][2], af[mt][3], r);
            }
#pragma unroll
            for (int pp = 0; pp < 4; pp++) {
                uint32_t r = base + G_B + (uint32_t)(kc * 16 * 528) +
                             (uint32_t)((wn * 64 + pp * 16) * 2) + b_off;
                LDSM_X4_T(bf[pp*2][0], bf[pp*2][1], bf[pp*2+1][0], bf[pp*2+1][1], r);
            }
#pragma unroll
            for (int mt = 0; mt < 2; mt++)
#pragma unroll
                for (int nt = 0; nt < 8; nt++)
                    mma_f16(acc[mt][nt], af[mt], bf[nt]);
        }
    }

    int lr = lane >> 2, lc = (lane & 3) * 2;
#pragma unroll
    for (int nt = 0; nt < 8; nt++) {
        int col = bn + wn * 64 + nt * 8 + lc;
        float b0 = __ldg(bias + col), b1 = __ldg(bias + col + 1);
#pragma unroll
        for (int mt = 0; mt < 2; mt++) {
            int row = bm + wm * 32 + mt * 16 + lr;
            *reinterpret_cast<uint32_t*>(reinterpret_cast<char*>(Cf) + ((size_t)row * 1024 + col) * 2) =
                pack_h2(acc[mt][nt][0] + b0, acc[mt][nt][1] + b1);
            *reinterpret_cast<uint32_t*>(reinterpret_cast<char*>(Cf) + ((size_t)(row + 8) * 1024 + col) * 2) =
                pack_h2(acc[mt][nt][2] + b0, acc[mt][nt][3] + b1);
        }
    }
}

// ---------------- score+mean: fp16, per (b, q-tile, k-tile), loop 16 heads ----------------
#define S_Q 0
#define S_K 18432
#define S_BUF 36864

__global__ __launch_bounds__(512, 1) void score_mean_tc(float* __restrict__ amean)
{
    extern __shared__ __align__(16) uint8_t smg[];
    int b = blockIdx.z;
    int q0 = blockIdx.y * 128, k0 = blockIdx.x * 128;
    int t = threadIdx.x, lane = t & 31, warp = t >> 5;
    int wm = warp >> 2, wn = warp & 3;
    uint32_t smb = smem_to_u32(smg);

    int plane = t >> 8, v = (t & 255) >> 1, hseg = t & 1;
    const __half* srcp = plane ? (g_kf + (size_t)(b * 1024 + k0 + v) * 1024)
                               : (g_qf + (size_t)(b * 512  + q0 + v) * 1024);
    uint32_t doff = (plane ? S_K : S_Q) + v * 144 + hseg * 64;

    auto issue = [&](int h) {
        uint32_t base = smb + (uint32_t)((h & 1) * S_BUF);
        const __half* s = srcp + h * 64 + hseg * 32;
#pragma unroll
        for (int seg = 0; seg < 4; seg++)
            CP16(base + doff + seg * 16, s + seg * 8);
    };

    uint32_t a_off = (lane & 15) * 144 + (lane >> 4) * 16;
    uint32_t b_off = ((lane & 7) + ((lane >> 4) & 1) * 8) * 144 + ((lane >> 3) & 1) * 16;

    float am[2][4][4];
#pragma unroll
    for (int i = 0; i < 2; i++)
#pragma unroll
        for (int j = 0; j < 4; j++)
#pragma unroll
            for (int e = 0; e < 4; e++) am[i][j][e] = 0.f;

    int lr = lane >> 2, lc = (lane & 3) * 2;

    issue(0); CP_COMMIT();

    for (int h = 0; h < 16; h++) {
        if (h < 15) { issue(h + 1); CP_COMMIT(); CP_WAIT(1); }
        else        { CP_WAIT(0); }
        __syncthreads();

        uint32_t base = smb + (uint32_t)((h & 1) * S_BUF);
        float acc[2][4][4];
#pragma unroll
        for (int i = 0; i < 2; i++)
#pragma unroll
            for (int j = 0; j < 4; j++)
#pragma unroll
                for (int e = 0; e < 4; e++) acc[i][j][e] = 0.f;

#pragma unroll
        for (int kc = 0; kc < 4; kc++) {
            uint32_t af[2][4], bf[4][2];
#pragma unroll
            for (int mt = 0; mt < 2; mt++) {
                uint32_t r = base + S_Q + (uint32_t)((wm * 32 + mt * 16) * 144) + kc * 32 + a_off;
                LDSM_X4(af[mt][0], af[mt][1], af[mt][2], af[mt][3], r);
            }
#pragma unroll
            for (int pp = 0; pp < 2; pp++) {
                uint32_t r = base + S_K + (uint32_t)((wn * 32 + pp * 16) * 144) + kc * 32 + b_off;
                LDSM_X4(bf[pp*2][0], bf[pp*2][1], bf[pp*2+1][0], bf[pp*2+1][1], r);
            }
#pragma unroll
            for (int mt = 0; mt < 2; mt++)
#pragma unroll
                for (int nt = 0; nt < 4; nt++)
                    mma_f16(acc[mt][nt], af[mt], bf[nt]);
        }

        size_t splane = ((size_t)b * 16 + h) * 524288;
#pragma unroll
        for (int mt = 0; mt < 2; mt++)
#pragma unroll
            for (int nt = 0; nt < 4; nt++) {
                float s0 = 1.f / (1.f + __expf(-0.125f * acc[mt][nt][0]));
                float s1 = 1.f / (1.f + __expf(-0.125f * acc[mt][nt][1]));
                float s2 = 1.f / (1.f + __expf(-0.125f * acc[mt][nt][2]));
                float s3 = 1.f / (1.f + __expf(-0.125f * acc[mt][nt][3]));
                am[mt][nt][0] += s0; am[mt][nt][1] += s1;
                am[mt][nt][2] += s2; am[mt][nt][3] += s3;
                int row = q0 + wm * 32 + mt * 16 + lr;
                int col = k0 + wn * 32 + nt * 8 + lc;
                *reinterpret_cast<uint32_t*>(reinterpret_cast<char*>(g_sf) + (splane + (size_t)row * 1024 + col) * 2) =
                    pack_h2(s0, s1);
                *reinterpret_cast<uint32_t*>(reinterpret_cast<char*>(g_sf) + (splane + (size_t)(row + 8) * 1024 + col) * 2) =
                    pack_h2(s2, s3);
            }
        __syncthreads();
    }

#pragma unroll
    for (int mt = 0; mt < 2; mt++)
#pragma unroll
        for (int nt = 0; nt < 4; nt++) {
            int row = q0 + wm * 32 + mt * 16 + lr;
            int col = k0 + wn * 32 + nt * 8 + lc;
            *reinterpret_cast<float2*>(amean + ((size_t)(b * 512) + row) * 1024 + col) =
                make_float2(am[mt][nt][0] * 0.0625f, am[mt][nt][1] * 0.0625f);
            *reinterpret_cast<float2*>(amean + ((size_t)(b * 512) + row + 8) * 1024 + col) =
                make_float2(am[mt][nt][2] * 0.0625f, am[mt][nt][3] * 0.0625f);
        }
}

// ---------------- AV: out = S @ V, fp16, K-chunk 32 ----------------
// smem stage: S [128 q][32 k = 64B + 16 pad = 80B] = 10240, V [32 k][144B] = 4608
#define A_S 0
#define A_V 10240
#define A_STAGE 14848

__global__ __launch_bounds__(256, 2) void av_tc(float* __restrict__ out)
{
    extern __shared__ __align__(16) uint8_t smg[];
    int bh = blockIdx.y, b = bh >> 4, h = bh & 15;
    int q0 = blockIdx.x * 128;
    int t = threadIdx.x, lane = t & 31, warp = t >> 5;
    int wm = warp >> 1, wn = warp & 1;                   // 4x2, warp tile 32x32
    uint32_t smb = smem_to_u32(smg);

    // S: 128 rows x 64B = 512 segs -> 2 CP16/thread; V: 32 rows x 8 segs = 256 -> 1/thread
    int srow = t >> 1, sh = t & 1;
    uint32_t s_dst = srow * 80 + sh * 32;
    const __half* sg = g_sf + ((size_t)bh * 512 + q0 + srow) * 1024 + sh * 16;
    int vrow = t >> 3, vseg = t & 7;
    uint32_t v_dst = A_V + vrow * 144 + vseg * 16;
    const __half* vg = g_vf + (size_t)(b * 1024 + vrow) * 1024 + h * 64 + vseg * 8;

    auto issue = [&](int ch) {
        uint32_t base = smb + (uint32_t)((ch & 3) * A_STAGE);
        CP16(base + A_S + s_dst, sg + ch * 32);
        CP16(base + A_S + s_dst + 16, sg + ch * 32 + 8);
        CP16(base + v_dst, vg + (size_t)ch * 32 * 1024);
    };

    float acc[2][4][4];
#pragma unroll
    for (int i = 0; i < 2; i++)
#pragma unroll
        for (int j = 0; j < 4; j++)
#pragma unroll
            for (int e = 0; e < 4; e++) acc[i][j][e] = 0.f;

    issue(0); CP_COMMIT();
    issue(1); CP_COMMIT();
    issue(2); CP_COMMIT();

    uint32_t a_off = (lane & 15) * 80 + (lane >> 4) * 16;
    uint32_t b_off = ((lane & 7) + ((lane >> 3) & 1) * 8) * 144 + (lane >> 4) * 16;

    for (int ch = 0; ch < 32; ch++) {
        CP_WAIT(2);
        __syncthreads();
        if (ch + 3 < 32) issue(ch + 3);
        CP_COMMIT();

        uint32_t base = smb + (uint32_t)((ch & 3) * A_STAGE);
#pragma unroll
        for (int kc = 0; kc < 2; kc++) {
            uint32_t af[2][4], bf[4][2];
#pragma unroll
            for (int mt = 0; mt < 2; mt++) {
                uint32_t r = base + A_S + (uint32_t)((wm * 32 + mt * 16) * 80) + kc * 32 + a_off;
                LDSM_X4(af[mt][0], af[mt][1], af[mt][2], af[mt][3], r);
            }
#pragma unroll
            for (int pp = 0; pp < 2; pp++) {
                uint32_t r = base + A_V + (uint32_t)(kc * 16 * 144) +
                             (uint32_t)((wn * 32 + pp * 16) * 2) + b_off;
                LDSM_X4_T(bf[pp*2][0], bf[pp*2][1], bf[pp*2+1][0], bf[pp*2+1][1], r);
            }
#pragma unroll
            for (int mt = 0; mt < 2; mt++)
#pragma unroll
                for (int nt = 0; nt < 4; nt++)
                    mma_f16(acc[mt][nt], af[mt], bf[nt]);
        }
    }

    int lr = lane >> 2, lc = (lane & 3) * 2;
#pragma unroll
    for (int nt = 0; nt < 4; nt++) {
        int col = h * 64 + wn * 32 + nt * 8 + lc;
#pragma unroll
        for (int mt = 0; mt < 2; mt++) {
            int row = b * 512 + q0 + wm * 32 + mt * 16 + lr;
            *reinterpret_cast<float2*>(out + (size_t)row * 1024 + col) =
                make_float2(acc[mt][nt][0], acc[mt][nt][1]);
            *reinterpret_cast<float2*>(out + (size_t)(row + 8) * 1024 + col) =
                make_float2(acc[mt][nt][2], acc[mt][nt][3]);
        }
    }
}

// ---------------- launch ----------------
extern "C" void kernel_launch(void* const* d_in, const int* in_sizes, int n_in,
                              void* d_out, int out_size)
{
    (void)in_sizes; (void)n_in; (void)out_size;
    const float* text = (const float*)d_in[0];
    const float* av   = (const float*)d_in[1];
    const float* tn_w = (const float*)d_in[2];
    const float* tn_b = (const float*)d_in[3];
    const float* an_w = (const float*)d_in[4];
    const float* an_b = (const float*)d_in[5];
    const float* Wq   = (const float*)d_in[6];
    const float* bq   = (const float*)d_in[7];
    const float* Wk   = (const float*)d_in[8];
    const float* bk   = (const float*)d_in[9];
    const float* Wv   = (const float*)d_in[10];
    const float* bv   = (const float*)d_in[11];

    float* out   = (float*)d_out;
    float* amean = out + (size_t)BS * NW * 1024;

    static int attr_done = 0;
    if (!attr_done) {
        cudaFuncSetAttribute(gemm_tc,       cudaFuncAttributeMaxDynamicSharedMemorySize, 4 * G_STAGE);
        cudaFuncSetAttribute(score_mean_tc, cudaFuncAttributeMaxDynamicSharedMemorySize, 2 * S_BUF);
        cudaFuncSetAttribute(av_tc,         cudaFuncAttributeMaxDynamicSharedMemorySize, 4 * A_STAGE);
        attr_done = 1;
    }

    ln_f16<<<BS * NW, 256>>>(text, tn_w, tn_b, 0);
    ln_f16<<<BS * NV, 256>>>(av, an_w, an_b, 1);
    wsplit<<<dim3(32, 32, 3), dim3(32, 8)>>>(Wq, Wk, Wv);

    gemm_tc<<<dim3(32, 4), 512, 4 * G_STAGE>>>(0, 0, bq);
    gemm_tc<<<dim3(64, 4), 512, 4 * G_STAGE>>>(1, 1, bk);
    gemm_tc<<<dim3(64, 4), 512, 4 * G_STAGE>>>(1, 2, bv);

    score_mean_tc<<<dim3(8, 4, 8), 512, 2 * S_BUF>>>(amean);
    av_tc<<<dim3(4, 128), 256, 4 * A_STAGE>>>(out);
}

// round 10
// speedup vs baseline: 2.9361x; 1.0944x over previous
#include <cuda_runtime.h>
#include <cuda_fp16.h>
#include <cstdint>

#define BS 8
#define NW 512
#define NV 1024

// ---------------- fp16 scratch (allocation-free) ----------------
__device__ __half g_taf[BS*NW*1024];                       // LN(text)
__device__ __half g_aaf[BS*NV*1024];                       // LN(av)
__device__ __half g_wtf[3][1024*1024];                     // W^T [k][n]
__device__ __half g_qf[BS*NW*1024];
__device__ __half g_kf[BS*NV*1024];
__device__ __half g_vf[BS*NV*1024];
__device__ __half g_sf[(size_t)BS*16*NW*NV];               // sigmoid scores, 128 MB

// ---------------- helpers ----------------
__device__ __forceinline__ uint32_t smem_to_u32(const void* p) {
    uint32_t a;
    asm("{ .reg .u64 t; cvta.to.shared.u64 t, %1; cvt.u32.u64 %0, t; }" : "=r"(a) : "l"(p));
    return a;
}
__device__ __forceinline__ uint32_t pack_h2(float x0, float x1) {
    __half2 p = __floats2half2_rn(x0, x1);
    return *reinterpret_cast<uint32_t*>(&p);
}

#define LDSM_X4(r0, r1, r2, r3, addr) \
    asm volatile("ldmatrix.sync.aligned.m8n8.x4.shared.b16 {%0,%1,%2,%3}, [%4];" \
        : "=r"(r0), "=r"(r1), "=r"(r2), "=r"(r3) : "r"(addr))
#define LDSM_X4_T(r0, r1, r2, r3, addr) \
    asm volatile("ldmatrix.sync.aligned.m8n8.x4.trans.shared.b16 {%0,%1,%2,%3}, [%4];" \
        : "=r"(r0), "=r"(r1), "=r"(r2), "=r"(r3) : "r"(addr))

__device__ __forceinline__ void mma_f16(float* c, const uint32_t* a, const uint32_t* b) {
    asm volatile(
        "mma.sync.aligned.m16n8k16.row.col.f32.f16.f16.f32 "
        "{%0,%1,%2,%3}, {%4,%5,%6,%7}, {%8,%9}, {%0,%1,%2,%3};"
        : "+f"(c[0]), "+f"(c[1]), "+f"(c[2]), "+f"(c[3])
        : "r"(a[0]), "r"(a[1]), "r"(a[2]), "r"(a[3]), "r"(b[0]), "r"(b[1]));
}

#define CP16(dst, src) \
    asm volatile("cp.async.cg.shared.global [%0], [%1], 16;" :: "r"((uint32_t)(dst)), "l"(src) : "memory")
#define CP_COMMIT() asm volatile("cp.async.commit_group;" ::: "memory")
#define CP_WAIT(n)  asm volatile("cp.async.wait_group %0;" :: "n"(n) : "memory")

// ---------------- LayerNorm -> fp16 ----------------
__global__ __launch_bounds__(256) void ln_f16(const float* __restrict__ x,
                                              const float* __restrict__ w,
                                              const float* __restrict__ b,
                                              int dst)
{
    __half* y = dst ? g_aaf : g_taf;
    int row = blockIdx.x, t = threadIdx.x;
    float4 xv = reinterpret_cast<const float4*>(x)[(size_t)row * 256 + t];
    float s  = xv.x + xv.y + xv.z + xv.w;
    float ss = xv.x*xv.x + xv.y*xv.y + xv.z*xv.z + xv.w*xv.w;
#pragma unroll
    for (int o = 16; o > 0; o >>= 1) {
        s  += __shfl_xor_sync(0xffffffffu, s,  o);
        ss += __shfl_xor_sync(0xffffffffu, ss, o);
    }
    __shared__ float rs[8], rss[8];
    if ((t & 31) == 0) { rs[t >> 5] = s; rss[t >> 5] = ss; }
    __syncthreads();
    float tot = 0.f, tot2 = 0.f;
#pragma unroll
    for (int i = 0; i < 8; i++) { tot += rs[i]; tot2 += rss[i]; }
    float mean = tot * (1.f / 1024.f);
    float var  = tot2 * (1.f / 1024.f) - mean * mean;
    float rstd = rsqrtf(var + 1e-5f);
    float4 wv = reinterpret_cast<const float4*>(w)[t];
    float4 bv = reinterpret_cast<const float4*>(b)[t];
    float o0 = (xv.x - mean) * rstd * wv.x + bv.x;
    float o1 = (xv.y - mean) * rstd * wv.y + bv.y;
    float o2 = (xv.z - mean) * rstd * wv.z + bv.z;
    float o3 = (xv.w - mean) * rstd * wv.w + bv.w;
    *reinterpret_cast<uint2*>(reinterpret_cast<char*>(y) + (size_t)row * 2048 + t * 8) =
        make_uint2(pack_h2(o0, o1), pack_h2(o2, o3));
}

// ---------------- W[n][k] -> W^T[k][n] fp16 ----------------
__global__ void wsplit(const float* __restrict__ Wq,
                       const float* __restrict__ Wk,
                       const float* __restrict__ Wv)
{
    int wsel = blockIdx.z;
    const float* W = (wsel == 0) ? Wq : (wsel == 1) ? Wk : Wv;
    __half* tf = g_wtf[wsel];
    __shared__ float tile[32][33];
    int k = blockIdx.x * 32 + threadIdx.x;
    int n0 = blockIdx.y * 32;
#pragma unroll
    for (int i = threadIdx.y; i < 32; i += 8)
        tile[i][threadIdx.x] = W[(size_t)(n0 + i) * 1024 + k];
    __syncthreads();
#pragma unroll
    for (int i = threadIdx.y; i < 32; i += 8) {
        float v = tile[threadIdx.x][i];
        size_t idx = (size_t)(blockIdx.x * 32 + i) * 1024 + n0 + threadIdx.x;
        tf[idx] = __float2half_rn(v);
    }
}

// ---------------- projection GEMM: 128x256 tile, K-chunk 64, 3-stage ----------------
// stage: A [128 rows][64 fp16 + 8 pad = 144B] = 18432
//        B [64 k][256 fp16 + 8 pad = 528B]    = 33792
#define G_A 0
#define G_B 18432
#define G_STAGE 52224

__global__ __launch_bounds__(512, 1) void gemm_tc(int src, int dst,
                                                  const float* __restrict__ bias)
{
    extern __shared__ __align__(16) uint8_t smg[];
    const __half* Af = src ? g_aaf : g_taf;
    const __half* Bf = g_wtf[dst];
    __half* Cf = (dst == 0) ? g_qf : (dst == 1) ? g_kf : g_vf;

    int t = threadIdx.x, lane = t & 31, warp = t >> 5;   // 16 warps, 4x4
    int wm = warp >> 2, wn = warp & 3;                    // warp tile 32 x 64
    int bm = blockIdx.x * 128, bn = blockIdx.y * 256;
    uint32_t smb = smem_to_u32(smg);

    // staging: A 1024 segs (2/thread), B 2048 segs (4/thread)
    int ar0 = t >> 3, as0 = t & 7;                        // A seg t
    int ar1 = (t + 512) >> 3;                             // A seg t+512 (same as0)
    int br = t >> 5, bsg = t & 31;                        // B: 4 rows apart
    const __half* ag0 = Af + (size_t)(bm + ar0) * 1024 + as0 * 8;
    const __half* ag1 = Af + (size_t)(bm + ar1) * 1024 + as0 * 8;
    const __half* bg  = Bf + (size_t)br * 1024 + bn + bsg * 8;
    uint32_t a_dst0 = ar0 * 144 + as0 * 16;
    uint32_t a_dst1 = ar1 * 144 + as0 * 16;
    uint32_t b_dst  = br * 528 + bsg * 16;

    auto issue = [&](int ch) {
        uint32_t base = smb + (uint32_t)((ch % 3) * G_STAGE);
        CP16(base + G_A + a_dst0, ag0 + ch * 64);
        CP16(base + G_A + a_dst1, ag1 + ch * 64);
#pragma unroll
        for (int i = 0; i < 4; i++)
            CP16(base + G_B + b_dst + i * 16 * 528,
                 bg + ((size_t)ch * 64 + i * 16) * 1024);
    };

    float acc[2][8][4];
#pragma unroll
    for (int i = 0; i < 2; i++)
#pragma unroll
        for (int j = 0; j < 8; j++)
#pragma unroll
            for (int e = 0; e < 4; e++) acc[i][j][e] = 0.f;

    issue(0); CP_COMMIT();
    issue(1); CP_COMMIT();

    uint32_t a_off = (lane & 15) * 144 + (lane >> 4) * 16;
    uint32_t b_off = ((lane & 7) + ((lane >> 3) & 1) * 8) * 528 + (lane >> 4) * 16;

    for (int ch = 0; ch < 16; ch++) {
        CP_WAIT(1);
        __syncthreads();
        if (ch + 2 < 16) issue(ch + 2);
        CP_COMMIT();

        uint32_t base = smb + (uint32_t)((ch % 3) * G_STAGE);
#pragma unroll
        for (int kc = 0; kc < 4; kc++) {
            uint32_t af[2][4], bf[8][2];
#pragma unroll
            for (int mt = 0; mt < 2; mt++) {
                uint32_t r = base + G_A + (uint32_t)((wm * 32 + mt * 16) * 144) + kc * 32 + a_off;
                LDSM_X4(af[mt][0], af[mt][1], af[mt][2], af[mt][3], r);
            }
#pragma unroll
            for (int pp = 0; pp < 4; pp++) {
                uint32_t r = base + G_B + (uint32_t)(kc * 16 * 528) +
                             (uint32_t)((wn * 64 + pp * 16) * 2) + b_off;
                LDSM_X4_T(bf[pp*2][0], bf[pp*2][1], bf[pp*2+1][0], bf[pp*2+1][1], r);
            }
#pragma unroll
            for (int mt = 0; mt < 2; mt++)
#pragma unroll
                for (int nt = 0; nt < 8; nt++)
                    mma_f16(acc[mt][nt], af[mt], bf[nt]);
        }
    }

    int lr = lane >> 2, lc = (lane & 3) * 2;
#pragma unroll
    for (int nt = 0; nt < 8; nt++) {
        int col = bn + wn * 64 + nt * 8 + lc;
        float b0 = __ldg(bias + col), b1 = __ldg(bias + col + 1);
#pragma unroll
        for (int mt = 0; mt < 2; mt++) {
            int row = bm + wm * 32 + mt * 16 + lr;
            *reinterpret_cast<uint32_t*>(reinterpret_cast<char*>(Cf) + ((size_t)row * 1024 + col) * 2) =
                pack_h2(acc[mt][nt][0] + b0, acc[mt][nt][1] + b1);
            *reinterpret_cast<uint32_t*>(reinterpret_cast<char*>(Cf) + ((size_t)(row + 8) * 1024 + col) * 2) =
                pack_h2(acc[mt][nt][2] + b0, acc[mt][nt][3] + b1);
        }
    }
}

// ---------------- score+mean: fp16, per (b, q-tile, k-tile), loop 16 heads ----------------
#define S_Q 0
#define S_K 18432
#define S_BUF 36864

__global__ __launch_bounds__(512, 1) void score_mean_tc(float* __restrict__ amean)
{
    extern __shared__ __align__(16) uint8_t smg[];
    int b = blockIdx.z;
    int q0 = blockIdx.y * 128, k0 = blockIdx.x * 128;
    int t = threadIdx.x, lane = t & 31, warp = t >> 5;
    int wm = warp >> 2, wn = warp & 3;
    uint32_t smb = smem_to_u32(smg);

    int plane = t >> 8, v = (t & 255) >> 1, hseg = t & 1;
    const __half* srcp = plane ? (g_kf + (size_t)(b * 1024 + k0 + v) * 1024)
                               : (g_qf + (size_t)(b * 512  + q0 + v) * 1024);
    uint32_t doff = (plane ? S_K : S_Q) + v * 144 + hseg * 64;

    auto issue = [&](int h) {
        uint32_t base = smb + (uint32_t)((h & 1) * S_BUF);
        const __half* s = srcp + h * 64 + hseg * 32;
#pragma unroll
        for (int seg = 0; seg < 4; seg++)
            CP16(base + doff + seg * 16, s + seg * 8);
    };

    uint32_t a_off = (lane & 15) * 144 + (lane >> 4) * 16;
    uint32_t b_off = ((lane & 7) + ((lane >> 4) & 1) * 8) * 144 + ((lane >> 3) & 1) * 16;

    float am[2][4][4];
#pragma unroll
    for (int i = 0; i < 2; i++)
#pragma unroll
        for (int j = 0; j < 4; j++)
#pragma unroll
            for (int e = 0; e < 4; e++) am[i][j][e] = 0.f;

    int lr = lane >> 2, lc = (lane & 3) * 2;

    issue(0); CP_COMMIT();

    for (int h = 0; h < 16; h++) {
        if (h < 15) { issue(h + 1); CP_COMMIT(); CP_WAIT(1); }
        else        { CP_WAIT(0); }
        __syncthreads();

        uint32_t base = smb + (uint32_t)((h & 1) * S_BUF);
        float acc[2][4][4];
#pragma unroll
        for (int i = 0; i < 2; i++)
#pragma unroll
            for (int j = 0; j < 4; j++)
#pragma unroll
                for (int e = 0; e < 4; e++) acc[i][j][e] = 0.f;

#pragma unroll
        for (int kc = 0; kc < 4; kc++) {
            uint32_t af[2][4], bf[4][2];
#pragma unroll
            for (int mt = 0; mt < 2; mt++) {
                uint32_t r = base + S_Q + (uint32_t)((wm * 32 + mt * 16) * 144) + kc * 32 + a_off;
                LDSM_X4(af[mt][0], af[mt][1], af[mt][2], af[mt][3], r);
            }
#pragma unroll
            for (int pp = 0; pp < 2; pp++) {
                uint32_t r = base + S_K + (uint32_t)((wn * 32 + pp * 16) * 144) + kc * 32 + b_off;
                LDSM_X4(bf[pp*2][0], bf[pp*2][1], bf[pp*2+1][0], bf[pp*2+1][1], r);
            }
#pragma unroll
            for (int mt = 0; mt < 2; mt++)
#pragma unroll
                for (int nt = 0; nt < 4; nt++)
                    mma_f16(acc[mt][nt], af[mt], bf[nt]);
        }

        size_t splane = ((size_t)b * 16 + h) * 524288;
#pragma unroll
        for (int mt = 0; mt < 2; mt++)
#pragma unroll
            for (int nt = 0; nt < 4; nt++) {
                float s0 = __fdividef(1.f, 1.f + __expf(-0.125f * acc[mt][nt][0]));
                float s1 = __fdividef(1.f, 1.f + __expf(-0.125f * acc[mt][nt][1]));
                float s2 = __fdividef(1.f, 1.f + __expf(-0.125f * acc[mt][nt][2]));
                float s3 = __fdividef(1.f, 1.f + __expf(-0.125f * acc[mt][nt][3]));
                am[mt][nt][0] += s0; am[mt][nt][1] += s1;
                am[mt][nt][2] += s2; am[mt][nt][3] += s3;
                int row = q0 + wm * 32 + mt * 16 + lr;
                int col = k0 + wn * 32 + nt * 8 + lc;
                *reinterpret_cast<uint32_t*>(reinterpret_cast<char*>(g_sf) + (splane + (size_t)row * 1024 + col) * 2) =
                    pack_h2(s0, s1);
                *reinterpret_cast<uint32_t*>(reinterpret_cast<char*>(g_sf) + (splane + (size_t)(row + 8) * 1024 + col) * 2) =
                    pack_h2(s2, s3);
            }
        __syncthreads();
    }

#pragma unroll
    for (int mt = 0; mt < 2; mt++)
#pragma unroll
        for (int nt = 0; nt < 4; nt++) {
            int row = q0 + wm * 32 + mt * 16 + lr;
            int col = k0 + wn * 32 + nt * 8 + lc;
            *reinterpret_cast<float2*>(amean + ((size_t)(b * 512) + row) * 1024 + col) =
                make_float2(am[mt][nt][0] * 0.0625f, am[mt][nt][1] * 0.0625f);
            *reinterpret_cast<float2*>(amean + ((size_t)(b * 512) + row + 8) * 1024 + col) =
                make_float2(am[mt][nt][2] * 0.0625f, am[mt][nt][3] * 0.0625f);
        }
}

// ---------------- AV: out = S @ V, fp16, K-chunk 64, 3-stage ----------------
// stage: S [128 q][64 fp16 + 8 pad = 144B] = 18432, V [64 k][144B] = 9216
#define A_S 0
#define A_V 18432
#define A_STAGE 27648

__global__ __launch_bounds__(256, 2) void av_tc(float* __restrict__ out)
{
    extern __shared__ __align__(16) uint8_t smg[];
    int bh = blockIdx.y, b = bh >> 4, h = bh & 15;
    int q0 = blockIdx.x * 128;
    int t = threadIdx.x, lane = t & 31, warp = t >> 5;
    int wm = warp >> 1, wn = warp & 1;                   // 4x2, warp tile 32x32
    uint32_t smb = smem_to_u32(smg);

    // S: 1024 segs -> 4/thread (rows t>>3, +32, +64, +96); V: 512 segs -> 2/thread
    int sr = t >> 3, ss8 = t & 7;
    const __half* sg = g_sf + ((size_t)bh * 512 + q0 + sr) * 1024 + ss8 * 8;
    uint32_t s_dst = sr * 144 + ss8 * 16;
    int vr = t >> 3;                                      // rows 0..31, +32
    const __half* vg = g_vf + (size_t)(b * 1024 + vr) * 1024 + h * 64 + ss8 * 8;
    uint32_t v_dst = A_V + vr * 144 + ss8 * 16;

    auto issue = [&](int ch) {
        uint32_t base = smb + (uint32_t)((ch % 3) * A_STAGE);
#pragma unroll
        for (int i = 0; i < 4; i++)
            CP16(base + A_S + s_dst + i * 32 * 144, sg + (size_t)i * 32 * 1024 + ch * 64);
#pragma unroll
        for (int i = 0; i < 2; i++)
            CP16(base + v_dst + i * 32 * 144, vg + ((size_t)ch * 64 + i * 32) * 1024);
    };

    float acc[2][4][4];
#pragma unroll
    for (int i = 0; i < 2; i++)
#pragma unroll
        for (int j = 0; j < 4; j++)
#pragma unroll
            for (int e = 0; e < 4; e++) acc[i][j][e] = 0.f;

    issue(0); CP_COMMIT();
    issue(1); CP_COMMIT();

    uint32_t a_off = (lane & 15) * 144 + (lane >> 4) * 16;
    uint32_t b_off = ((lane & 7) + ((lane >> 3) & 1) * 8) * 144 + (lane >> 4) * 16;

    for (int ch = 0; ch < 16; ch++) {
        CP_WAIT(1);
        __syncthreads();
        if (ch + 2 < 16) issue(ch + 2);
        CP_COMMIT();

        uint32_t base = smb + (uint32_t)((ch % 3) * A_STAGE);
#pragma unroll
        for (int kc = 0; kc < 4; kc++) {
            uint32_t af[2][4], bf[4][2];
#pragma unroll
            for (int mt = 0; mt < 2; mt++) {
                uint32_t r = base + A_S + (uint32_t)((wm * 32 + mt * 16) * 144) + kc * 32 + a_off;
                LDSM_X4(af[mt][0], af[mt][1], af[mt][2], af[mt][3], r);
            }
#pragma unroll
            for (int pp = 0; pp < 2; pp++) {
                uint32_t r = base + A_V + (uint32_t)(kc * 16 * 144) +
                             (uint32_t)((wn * 32 + pp * 16) * 2) + b_off;
                LDSM_X4_T(bf[pp*2][0], bf[pp*2][1], bf[pp*2+1][0], bf[pp*2+1][1], r);
            }
#pragma unroll
            for (int mt = 0; mt < 2; mt++)
#pragma unroll
                for (int nt = 0; nt < 4; nt++)
                    mma_f16(acc[mt][nt], af[mt], bf[nt]);
        }
    }

    int lr = lane >> 2, lc = (lane & 3) * 2;
#pragma unroll
    for (int nt = 0; nt < 4; nt++) {
        int col = h * 64 + wn * 32 + nt * 8 + lc;
#pragma unroll
        for (int mt = 0; mt < 2; mt++) {
            int row = b * 512 + q0 + wm * 32 + mt * 16 + lr;
            *reinterpret_cast<float2*>(out + (size_t)row * 1024 + col) =
                make_float2(acc[mt][nt][0], acc[mt][nt][1]);
            *reinterpret_cast<float2*>(out + (size_t)(row + 8) * 1024 + col) =
                make_float2(acc[mt][nt][2], acc[mt][nt][3]);
        }
    }
}

// ---------------- launch ----------------
extern "C" void kernel_launch(void* const* d_in, const int* in_sizes, int n_in,
                              void* d_out, int out_size)
{
    (void)in_sizes; (void)n_in; (void)out_size;
    const float* text = (const float*)d_in[0];
    const float* av   = (const float*)d_in[1];
    const float* tn_w = (const float*)d_in[2];
    const float* tn_b = (const float*)d_in[3];
    const float* an_w = (const float*)d_in[4];
    const float* an_b = (const float*)d_in[5];
    const float* Wq   = (const float*)d_in[6];
    const float* bq   = (const float*)d_in[7];
    const float* Wk   = (const float*)d_in[8];
    const float* bk   = (const float*)d_in[9];
    const float* Wv   = (const float*)d_in[10];
    const float* bv   = (const float*)d_in[11];

    float* out   = (float*)d_out;
    float* amean = out + (size_t)BS * NW * 1024;

    static int attr_done = 0;
    if (!attr_done) {
        cudaFuncSetAttribute(gemm_tc,       cudaFuncAttributeMaxDynamicSharedMemorySize, 3 * G_STAGE);
        cudaFuncSetAttribute(score_mean_tc, cudaFuncAttributeMaxDynamicSharedMemorySize, 2 * S_BUF);
        cudaFuncSetAttribute(av_tc,         cudaFuncAttributeMaxDynamicSharedMemorySize, 3 * A_STAGE);
        attr_done = 1;
    }

    ln_f16<<<BS * NW, 256>>>(text, tn_w, tn_b, 0);
    ln_f16<<<BS * NV, 256>>>(av, an_w, an_b, 1);
    wsplit<<<dim3(32, 32, 3), dim3(32, 8)>>>(Wq, Wk, Wv);

    gemm_tc<<<dim3(32, 4), 512, 3 * G_STAGE>>>(0, 0, bq);
    gemm_tc<<<dim3(64, 4), 512, 3 * G_STAGE>>>(1, 1, bk);
    gemm_tc<<<dim3(64, 4), 512, 3 * G_STAGE>>>(1, 2, bv);

    score_mean_tc<<<dim3(8, 4, 8), 512, 2 * S_BUF>>>(amean);
    av_tc<<<dim3(4, 128), 256, 3 * A_STAGE>>>(out);
}

// round 11
// speedup vs baseline: 2.9907x; 1.0186x over previous
#include <cuda_runtime.h>
#include <cuda_fp16.h>
#include <cstdint>

#define BS 8
#define NW 512
#define NV 1024

// ---------------- fp16 scratch (allocation-free) ----------------
__device__ __half g_taf[BS*NW*1024];                       // LN(text)
__device__ __half g_aaf[BS*NV*1024];                       // LN(av)
__device__ __half g_wtf[3][1024*1024];                     // W^T [k][n]
__device__ __half g_qf[BS*NW*1024];
__device__ __half g_kf[BS*NV*1024];
__device__ __half g_vf[BS*NV*1024];
__device__ __half g_sf[(size_t)BS*16*NW*NV];               // sigmoid scores, 128 MB

// ---------------- helpers ----------------
__device__ __forceinline__ uint32_t smem_to_u32(const void* p) {
    uint32_t a;
    asm("{ .reg .u64 t; cvta.to.shared.u64 t, %1; cvt.u32.u64 %0, t; }" : "=r"(a) : "l"(p));
    return a;
}
__device__ __forceinline__ uint32_t pack_h2(float x0, float x1) {
    __half2 p = __floats2half2_rn(x0, x1);
    return *reinterpret_cast<uint32_t*>(&p);
}

#define LDSM_X4(r0, r1, r2, r3, addr) \
    asm volatile("ldmatrix.sync.aligned.m8n8.x4.shared.b16 {%0,%1,%2,%3}, [%4];" \
        : "=r"(r0), "=r"(r1), "=r"(r2), "=r"(r3) : "r"(addr))
#define LDSM_X4_T(r0, r1, r2, r3, addr) \
    asm volatile("ldmatrix.sync.aligned.m8n8.x4.trans.shared.b16 {%0,%1,%2,%3}, [%4];" \
        : "=r"(r0), "=r"(r1), "=r"(r2), "=r"(r3) : "r"(addr))

__device__ __forceinline__ void mma_f16(float* c, const uint32_t* a, const uint32_t* b) {
    asm volatile(
        "mma.sync.aligned.m16n8k16.row.col.f32.f16.f16.f32 "
        "{%0,%1,%2,%3}, {%4,%5,%6,%7}, {%8,%9}, {%0,%1,%2,%3};"
        : "+f"(c[0]), "+f"(c[1]), "+f"(c[2]), "+f"(c[3])
        : "r"(a[0]), "r"(a[1]), "r"(a[2]), "r"(a[3]), "r"(b[0]), "r"(b[1]));
}

#define CP16(dst, src) \
    asm volatile("cp.async.cg.shared.global [%0], [%1], 16;" :: "r"((uint32_t)(dst)), "l"(src) : "memory")
#define CP_COMMIT() asm volatile("cp.async.commit_group;" ::: "memory")
#define CP_WAIT(n)  asm volatile("cp.async.wait_group %0;" :: "n"(n) : "memory")

// ---------------- LayerNorm -> fp16 ----------------
__global__ __launch_bounds__(256) void ln_f16(const float* __restrict__ x,
                                              const float* __restrict__ w,
                                              const float* __restrict__ b,
                                              int dst)
{
    __half* y = dst ? g_aaf : g_taf;
    int row = blockIdx.x, t = threadIdx.x;
    float4 xv = reinterpret_cast<const float4*>(x)[(size_t)row * 256 + t];
    float s  = xv.x + xv.y + xv.z + xv.w;
    float ss = xv.x*xv.x + xv.y*xv.y + xv.z*xv.z + xv.w*xv.w;
#pragma unroll
    for (int o = 16; o > 0; o >>= 1) {
        s  += __shfl_xor_sync(0xffffffffu, s,  o);
        ss += __shfl_xor_sync(0xffffffffu, ss, o);
    }
    __shared__ float rs[8], rss[8];
    if ((t & 31) == 0) { rs[t >> 5] = s; rss[t >> 5] = ss; }
    __syncthreads();
    float tot = 0.f, tot2 = 0.f;
#pragma unroll
    for (int i = 0; i < 8; i++) { tot += rs[i]; tot2 += rss[i]; }
    float mean = tot * (1.f / 1024.f);
    float var  = tot2 * (1.f / 1024.f) - mean * mean;
    float rstd = rsqrtf(var + 1e-5f);
    float4 wv = reinterpret_cast<const float4*>(w)[t];
    float4 bv = reinterpret_cast<const float4*>(b)[t];
    float o0 = (xv.x - mean) * rstd * wv.x + bv.x;
    float o1 = (xv.y - mean) * rstd * wv.y + bv.y;
    float o2 = (xv.z - mean) * rstd * wv.z + bv.z;
    float o3 = (xv.w - mean) * rstd * wv.w + bv.w;
    *reinterpret_cast<uint2*>(reinterpret_cast<char*>(y) + (size_t)row * 2048 + t * 8) =
        make_uint2(pack_h2(o0, o1), pack_h2(o2, o3));
}

// ---------------- W[n][k] -> W^T[k][n] fp16 ----------------
__global__ void wsplit(const float* __restrict__ Wq,
                       const float* __restrict__ Wk,
                       const float* __restrict__ Wv)
{
    int wsel = blockIdx.z;
    const float* W = (wsel == 0) ? Wq : (wsel == 1) ? Wk : Wv;
    __half* tf = g_wtf[wsel];
    __shared__ float tile[32][33];
    int k = blockIdx.x * 32 + threadIdx.x;
    int n0 = blockIdx.y * 32;
#pragma unroll
    for (int i = threadIdx.y; i < 32; i += 8)
        tile[i][threadIdx.x] = W[(size_t)(n0 + i) * 1024 + k];
    __syncthreads();
#pragma unroll
    for (int i = threadIdx.y; i < 32; i += 8) {
        float v = tile[threadIdx.x][i];
        size_t idx = (size_t)(blockIdx.x * 32 + i) * 1024 + n0 + threadIdx.x;
        tf[idx] = __float2half_rn(v);
    }
}

// ---------------- projection GEMM: 128x128 tile, K=32, 4-stage, 2 CTAs/SM ----------------
// stage: A [128 rows][32 fp16 + 8 pad = 80B] = 10240
//        B [32 k][128 fp16 + 8 pad = 272B]   = 8704
#define G_A 0
#define G_B 10240
#define G_STAGE 18944

__global__ __launch_bounds__(256, 2) void gemm_tc(int src, int dst,
                                                  const float* __restrict__ bias)
{
    extern __shared__ __align__(16) uint8_t smg[];
    const __half* Af = src ? g_aaf : g_taf;
    const __half* Bf = g_wtf[dst];
    __half* Cf = (dst == 0) ? g_qf : (dst == 1) ? g_kf : g_vf;

    int t = threadIdx.x, lane = t & 31, warp = t >> 5;   // 8 warps, 2x4
    int wm = warp >> 2, wn = warp & 3;                    // warp tile 64 x 32
    int bm = blockIdx.x * 128, bn = blockIdx.y * 128;
    uint32_t smb = smem_to_u32(smg);

    // staging: A 512 segs -> 2/thread (rows r, r+64); B 512 segs -> 2/thread (rows r, r+16)
    int arow = t >> 2, aseg = t & 3;
    int brow = t >> 4, bseg = t & 15;
    const __half* ag0 = Af + (size_t)(bm + arow) * 1024 + aseg * 8;
    const __half* ag1 = Af + (size_t)(bm + arow + 64) * 1024 + aseg * 8;
    const __half* bg0 = Bf + (size_t)brow * 1024 + bn + bseg * 8;
    uint32_t a_dst0 = arow * 80 + aseg * 16;
    uint32_t a_dst1 = (arow + 64) * 80 + aseg * 16;
    uint32_t b_dst0 = brow * 272 + bseg * 16;

    auto issue = [&](int ch) {
        uint32_t base = smb + (uint32_t)((ch & 3) * G_STAGE);
        CP16(base + G_A + a_dst0, ag0 + ch * 32);
        CP16(base + G_A + a_dst1, ag1 + ch * 32);
        CP16(base + G_B + b_dst0, bg0 + (size_t)ch * 32 * 1024);
        CP16(base + G_B + b_dst0 + 16 * 272, bg0 + ((size_t)ch * 32 + 16) * 1024);
    };

    float acc[4][4][4];
#pragma unroll
    for (int i = 0; i < 4; i++)
#pragma unroll
        for (int j = 0; j < 4; j++)
#pragma unroll
            for (int e = 0; e < 4; e++) acc[i][j][e] = 0.f;

    issue(0); CP_COMMIT();
    issue(1); CP_COMMIT();
    issue(2); CP_COMMIT();

    uint32_t a_off = (lane & 15) * 80 + (lane >> 4) * 16;
    uint32_t b_off = ((lane & 7) + ((lane >> 3) & 1) * 8) * 272 + (lane >> 4) * 16;

    for (int ch = 0; ch < 32; ch++) {
        CP_WAIT(2);
        __syncthreads();
        if (ch + 3 < 32) issue(ch + 3);
        CP_COMMIT();

        uint32_t base = smb + (uint32_t)((ch & 3) * G_STAGE);
#pragma unroll
        for (int kc = 0; kc < 2; kc++) {
            uint32_t af[4][4], bf[4][2];
#pragma unroll
            for (int mt = 0; mt < 4; mt++) {
                uint32_t r = base + G_A + (uint32_t)((wm * 64 + mt * 16) * 80) + kc * 32 + a_off;
                LDSM_X4(af[mt][0], af[mt][1], af[mt][2], af[mt][3], r);
            }
#pragma unroll
            for (int pp = 0; pp < 2; pp++) {
                uint32_t r = base + G_B + (uint32_t)(kc * 16 * 272) +
                             (uint32_t)((wn * 32 + pp * 16) * 2) + b_off;
                LDSM_X4_T(bf[pp*2][0], bf[pp*2][1], bf[pp*2+1][0], bf[pp*2+1][1], r);
            }
#pragma unroll
            for (int mt = 0; mt < 4; mt++)
#pragma unroll
                for (int nt = 0; nt < 4; nt++)
                    mma_f16(acc[mt][nt], af[mt], bf[nt]);
        }
    }

    int lr = lane >> 2, lc = (lane & 3) * 2;
#pragma unroll
    for (int nt = 0; nt < 4; nt++) {
        int col = bn + wn * 32 + nt * 8 + lc;
        float b0 = __ldg(bias + col), b1 = __ldg(bias + col + 1);
#pragma unroll
        for (int mt = 0; mt < 4; mt++) {
            int row = bm + wm * 64 + mt * 16 + lr;
            *reinterpret_cast<uint32_t*>(reinterpret_cast<char*>(Cf) + ((size_t)row * 1024 + col) * 2) =
                pack_h2(acc[mt][nt][0] + b0, acc[mt][nt][1] + b1);
            *reinterpret_cast<uint32_t*>(reinterpret_cast<char*>(Cf) + ((size_t)(row + 8) * 1024 + col) * 2) =
                pack_h2(acc[mt][nt][2] + b0, acc[mt][nt][3] + b1);
        }
    }
}

// ---------------- score+mean: fp16, per (b, q-tile, k-tile), loop 16 heads ----------------
#define S_Q 0
#define S_K 18432
#define S_BUF 36864

__global__ __launch_bounds__(512, 1) void score_mean_tc(float* __restrict__ amean)
{
    extern __shared__ __align__(16) uint8_t smg[];
    int b = blockIdx.z;
    int q0 = blockIdx.y * 128, k0 = blockIdx.x * 128;
    int t = threadIdx.x, lane = t & 31, warp = t >> 5;
    int wm = warp >> 2, wn = warp & 3;
    uint32_t smb = smem_to_u32(smg);

    int plane = t >> 8, v = (t & 255) >> 1, hseg = t & 1;
    const __half* srcp = plane ? (g_kf + (size_t)(b * 1024 + k0 + v) * 1024)
                               : (g_qf + (size_t)(b * 512  + q0 + v) * 1024);
    uint32_t doff = (plane ? S_K : S_Q) + v * 144 + hseg * 64;

    auto issue = [&](int h) {
        uint32_t base = smb + (uint32_t)((h & 1) * S_BUF);
        const __half* s = srcp + h * 64 + hseg * 32;
#pragma unroll
        for (int seg = 0; seg < 4; seg++)
            CP16(base + doff + seg * 16, s + seg * 8);
    };

    uint32_t a_off = (lane & 15) * 144 + (lane >> 4) * 16;
    uint32_t b_off = ((lane & 7) + ((lane >> 4) & 1) * 8) * 144 + ((lane >> 3) & 1) * 16;

    float am[2][4][4];
#pragma unroll
    for (int i = 0; i < 2; i++)
#pragma unroll
        for (int j = 0; j < 4; j++)
#pragma unroll
            for (int e = 0; e < 4; e++) am[i][j][e] = 0.f;

    int lr = lane >> 2, lc = (lane & 3) * 2;

    issue(0); CP_COMMIT();

    for (int h = 0; h < 16; h++) {
        if (h < 15) { issue(h + 1); CP_COMMIT(); CP_WAIT(1); }
        else        { CP_WAIT(0); }
        __syncthreads();

        uint32_t base = smb + (uint32_t)((h & 1) * S_BUF);
        float acc[2][4][4];
#pragma unroll
        for (int i = 0; i < 2; i++)
#pragma unroll
            for (int j = 0; j < 4; j++)
#pragma unroll
                for (int e = 0; e < 4; e++) acc[i][j][e] = 0.f;

#pragma unroll
        for (int kc = 0; kc < 4; kc++) {
            uint32_t af[2][4], bf[4][2];
#pragma unroll
            for (int mt = 0; mt < 2; mt++) {
                uint32_t r = base + S_Q + (uint32_t)((wm * 32 + mt * 16) * 144) + kc * 32 + a_off;
                LDSM_X4(af[mt][0], af[mt][1], af[mt][2], af[mt][3], r);
            }
#pragma unroll
            for (int pp = 0; pp < 2; pp++) {
                uint32_t r = base + S_K + (uint32_t)((wn * 32 + pp * 16) * 144) + kc * 32 + b_off;
                LDSM_X4(bf[pp*2][0], bf[pp*2][1], bf[pp*2+1][0], bf[pp*2+1][1], r);
            }
#pragma unroll
            for (int mt = 0; mt < 2; mt++)
#pragma unroll
                for (int nt = 0; nt < 4; nt++)
                    mma_f16(acc[mt][nt], af[mt], bf[nt]);
        }

        size_t splane = ((size_t)b * 16 + h) * 524288;
#pragma unroll
        for (int mt = 0; mt < 2; mt++)
#pragma unroll
            for (int nt = 0; nt < 4; nt++) {
                float s0 = __fdividef(1.f, 1.f + __expf(-0.125f * acc[mt][nt][0]));
                float s1 = __fdividef(1.f, 1.f + __expf(-0.125f * acc[mt][nt][1]));
                float s2 = __fdividef(1.f, 1.f + __expf(-0.125f * acc[mt][nt][2]));
                float s3 = __fdividef(1.f, 1.f + __expf(-0.125f * acc[mt][nt][3]));
                am[mt][nt][0] += s0; am[mt][nt][1] += s1;
                am[mt][nt][2] += s2; am[mt][nt][3] += s3;
                int row = q0 + wm * 32 + mt * 16 + lr;
                int col = k0 + wn * 32 + nt * 8 + lc;
                *reinterpret_cast<uint32_t*>(reinterpret_cast<char*>(g_sf) + (splane + (size_t)row * 1024 + col) * 2) =
                    pack_h2(s0, s1);
                *reinterpret_cast<uint32_t*>(reinterpret_cast<char*>(g_sf) + (splane + (size_t)(row + 8) * 1024 + col) * 2) =
                    pack_h2(s2, s3);
            }
        __syncthreads();
    }

#pragma unroll
    for (int mt = 0; mt < 2; mt++)
#pragma unroll
        for (int nt = 0; nt < 4; nt++) {
            int row = q0 + wm * 32 + mt * 16 + lr;
            int col = k0 + wn * 32 + nt * 8 + lc;
            *reinterpret_cast<float2*>(amean + ((size_t)(b * 512) + row) * 1024 + col) =
                make_float2(am[mt][nt][0] * 0.0625f, am[mt][nt][1] * 0.0625f);
            *reinterpret_cast<float2*>(amean + ((size_t)(b * 512) + row + 8) * 1024 + col) =
                make_float2(am[mt][nt][2] * 0.0625f, am[mt][nt][3] * 0.0625f);
        }
}

// ---------------- AV: out = S @ V, fp16, K-chunk 64, 3-stage ----------------
// stage: S [128 q][64 fp16 + 8 pad = 144B] = 18432, V [64 k][144B] = 9216
#define A_S 0
#define A_V 18432
#define A_STAGE 27648

__global__ __launch_bounds__(256, 2) void av_tc(float* __restrict__ out)
{
    extern __shared__ __align__(16) uint8_t smg[];
    int bh = blockIdx.y, b = bh >> 4, h = bh & 15;
    int q0 = blockIdx.x * 128;
    int t = threadIdx.x, lane = t & 31, warp = t >> 5;
    int wm = warp >> 1, wn = warp & 1;                   // 4x2, warp tile 32x32
    uint32_t smb = smem_to_u32(smg);

    int sr = t >> 3, ss8 = t & 7;
    const __half* sg = g_sf + ((size_t)bh * 512 + q0 + sr) * 1024 + ss8 * 8;
    uint32_t s_dst = sr * 144 + ss8 * 16;
    int vr = t >> 3;
    const __half* vg = g_vf + (size_t)(b * 1024 + vr) * 1024 + h * 64 + ss8 * 8;
    uint32_t v_dst = A_V + vr * 144 + ss8 * 16;

    auto issue = [&](int ch) {
        uint32_t base = smb + (uint32_t)((ch % 3) * A_STAGE);
#pragma unroll
        for (int i = 0; i < 4; i++)
            CP16(base + A_S + s_dst + i * 32 * 144, sg + (size_t)i * 32 * 1024 + ch * 64);
#pragma unroll
        for (int i = 0; i < 2; i++)
            CP16(base + v_dst + i * 32 * 144, vg + ((size_t)ch * 64 + i * 32) * 1024);
    };

    float acc[2][4][4];
#pragma unroll
    for (int i = 0; i < 2; i++)
#pragma unroll
        for (int j = 0; j < 4; j++)
#pragma unroll
            for (int e = 0; e < 4; e++) acc[i][j][e] = 0.f;

    issue(0); CP_COMMIT();
    issue(1); CP_COMMIT();

    uint32_t a_off = (lane & 15) * 144 + (lane >> 4) * 16;
    uint32_t b_off = ((lane & 7) + ((lane >> 3) & 1) * 8) * 144 + (lane >> 4) * 16;

    for (int ch = 0; ch < 16; ch++) {
        CP_WAIT(1);
        __syncthreads();
        if (ch + 2 < 16) issue(ch + 2);
        CP_COMMIT();

        uint32_t base = smb + (uint32_t)((ch % 3) * A_STAGE);
#pragma unroll
        for (int kc = 0; kc < 4; kc++) {
            uint32_t af[2][4], bf[4][2];
#pragma unroll
            for (int mt = 0; mt < 2; mt++) {
                uint32_t r = base + A_S + (uint32_t)((wm * 32 + mt * 16) * 144) + kc * 32 + a_off;
                LDSM_X4(af[mt][0], af[mt][1], af[mt][2], af[mt][3], r);
            }
#pragma unroll
            for (int pp = 0; pp < 2; pp++) {
                uint32_t r = base + A_V + (uint32_t)(kc * 16 * 144) +
                             (uint32_t)((wn * 32 + pp * 16) * 2) + b_off;
                LDSM_X4_T(bf[pp*2][0], bf[pp*2][1], bf[pp*2+1][0], bf[pp*2+1][1], r);
            }
#pragma unroll
            for (int mt = 0; mt < 2; mt++)
#pragma unroll
                for (int nt = 0; nt < 4; nt++)
                    mma_f16(acc[mt][nt], af[mt], bf[nt]);
        }
    }

    int lr = lane >> 2, lc = (lane & 3) * 2;
#pragma unroll
    for (int nt = 0; nt < 4; nt++) {
        int col = h * 64 + wn * 32 + nt * 8 + lc;
#pragma unroll
        for (int mt = 0; mt < 2; mt++) {
            int row = b * 512 + q0 + wm * 32 + mt * 16 + lr;
            *reinterpret_cast<float2*>(out + (size_t)row * 1024 + col) =
                make_float2(acc[mt][nt][0], acc[mt][nt][1]);
            *reinterpret_cast<float2*>(out + (size_t)(row + 8) * 1024 + col) =
                make_float2(acc[mt][nt][2], acc[mt][nt][3]);
        }
    }
}

// ---------------- launch ----------------
extern "C" void kernel_launch(void* const* d_in, const int* in_sizes, int n_in,
                              void* d_out, int out_size)
{
    (void)in_sizes; (void)n_in; (void)out_size;
    const float* text = (const float*)d_in[0];
    const float* av   = (const float*)d_in[1];
    const float* tn_w = (const float*)d_in[2];
    const float* tn_b = (const float*)d_in[3];
    const float* an_w = (const float*)d_in[4];
    const float* an_b = (const float*)d_in[5];
    const float* Wq   = (const float*)d_in[6];
    const float* bq   = (const float*)d_in[7];
    const float* Wk   = (const float*)d_in[8];
    const float* bk   = (const float*)d_in[9];
    const float* Wv   = (const float*)d_in[10];
    const float* bv   = (const float*)d_in[11];

    float* out   = (float*)d_out;
    float* amean = out + (size_t)BS * NW * 1024;

    static int attr_done = 0;
    if (!attr_done) {
        cudaFuncSetAttribute(gemm_tc,       cudaFuncAttributeMaxDynamicSharedMemorySize, 4 * G_STAGE);
        cudaFuncSetAttribute(score_mean_tc, cudaFuncAttributeMaxDynamicSharedMemorySize, 2 * S_BUF);
        cudaFuncSetAttribute(av_tc,         cudaFuncAttributeMaxDynamicSharedMemorySize, 3 * A_STAGE);
        attr_done = 1;
    }

    ln_f16<<<BS * NW, 256>>>(text, tn_w, tn_b, 0);
    ln_f16<<<BS * NV, 256>>>(av, an_w, an_b, 1);
    wsplit<<<dim3(32, 32, 3), dim3(32, 8)>>>(Wq, Wk, Wv);

    gemm_tc<<<dim3(32, 8), 256, 4 * G_STAGE>>>(0, 0, bq);
    gemm_tc<<<dim3(64, 8), 256, 4 * G_STAGE>>>(1, 1, bk);
    gemm_tc<<<dim3(64, 8), 256, 4 * G_STAGE>>>(1, 2, bv);

    score_mean_tc<<<dim3(8, 4, 8), 512, 2 * S_BUF>>>(amean);
    av_tc<<<dim3(4, 128), 256, 3 * A_STAGE>>>(out);
}

// round 12
// speedup vs baseline: 3.2155x; 1.0752x over previous
#include <cuda_runtime.h>
#include <cuda_fp16.h>
#include <cstdint>

#define BS 8
#define NW 512
#define NV 1024

// ---------------- fp16 scratch (allocation-free) ----------------
__device__ __half g_taf[BS*NW*1024];                       // LN(text)
__device__ __half g_aaf[BS*NV*1024];                       // LN(av)
__device__ __half g_wtf[3][1024*1024];                     // W^T [k][n]
__device__ __half g_qf[BS*NW*1024];
__device__ __half g_kf[BS*NV*1024];
__device__ __half g_vf[BS*NV*1024];
__device__ __half g_sf[(size_t)BS*16*NW*NV];               // sigmoid scores, 128 MB

// ---------------- helpers ----------------
__device__ __forceinline__ uint32_t smem_to_u32(const void* p) {
    uint32_t a;
    asm("{ .reg .u64 t; cvta.to.shared.u64 t, %1; cvt.u32.u64 %0, t; }" : "=r"(a) : "l"(p));
    return a;
}
__device__ __forceinline__ uint32_t pack_h2(float x0, float x1) {
    __half2 p = __floats2half2_rn(x0, x1);
    return *reinterpret_cast<uint32_t*>(&p);
}

#define LDSM_X4(r0, r1, r2, r3, addr) \
    asm volatile("ldmatrix.sync.aligned.m8n8.x4.shared.b16 {%0,%1,%2,%3}, [%4];" \
        : "=r"(r0), "=r"(r1), "=r"(r2), "=r"(r3) : "r"(addr))
#define LDSM_X4_T(r0, r1, r2, r3, addr) \
    asm volatile("ldmatrix.sync.aligned.m8n8.x4.trans.shared.b16 {%0,%1,%2,%3}, [%4];" \
        : "=r"(r0), "=r"(r1), "=r"(r2), "=r"(r3) : "r"(addr))

__device__ __forceinline__ void mma_f16(float* c, const uint32_t* a, const uint32_t* b) {
    asm volatile(
        "mma.sync.aligned.m16n8k16.row.col.f32.f16.f16.f32 "
        "{%0,%1,%2,%3}, {%4,%5,%6,%7}, {%8,%9}, {%0,%1,%2,%3};"
        : "+f"(c[0]), "+f"(c[1]), "+f"(c[2]), "+f"(c[3])
        : "r"(a[0]), "r"(a[1]), "r"(a[2]), "r"(a[3]), "r"(b[0]), "r"(b[1]));
}

#define CP16(dst, src) \
    asm volatile("cp.async.cg.shared.global [%0], [%1], 16;" :: "r"((uint32_t)(dst)), "l"(src) : "memory")
#define CP_COMMIT() asm volatile("cp.async.commit_group;" ::: "memory")
#define CP_WAIT(n)  asm volatile("cp.async.wait_group %0;" :: "n"(n) : "memory")

// ---------------- LayerNorm (both tensors, one launch) -> fp16 ----------------
__global__ __launch_bounds__(256) void ln_f16(const float* __restrict__ text,
                                              const float* __restrict__ av,
                                              const float* __restrict__ tw,
                                              const float* __restrict__ tb,
                                              const float* __restrict__ aw,
                                              const float* __restrict__ ab)
{
    int row = blockIdx.x, t = threadIdx.x;
    const float* x;
    const float* w;
    const float* b;
    __half* y;
    int lrow;
    if (row < BS * NW) {
        x = text; w = tw; b = tb; y = g_taf; lrow = row;
    } else {
        x = av;   w = aw; b = ab; y = g_aaf; lrow = row - BS * NW;
    }
    float4 xv = reinterpret_cast<const float4*>(x)[(size_t)lrow * 256 + t];
    float s  = xv.x + xv.y + xv.z + xv.w;
    float ss = xv.x*xv.x + xv.y*xv.y + xv.z*xv.z + xv.w*xv.w;
#pragma unroll
    for (int o = 16; o > 0; o >>= 1) {
        s  += __shfl_xor_sync(0xffffffffu, s,  o);
        ss += __shfl_xor_sync(0xffffffffu, ss, o);
    }
    __shared__ float rs[8], rss[8];
    if ((t & 31) == 0) { rs[t >> 5] = s; rss[t >> 5] = ss; }
    __syncthreads();
    float tot = 0.f, tot2 = 0.f;
#pragma unroll
    for (int i = 0; i < 8; i++) { tot += rs[i]; tot2 += rss[i]; }
    float mean = tot * (1.f / 1024.f);
    float var  = tot2 * (1.f / 1024.f) - mean * mean;
    float rstd = rsqrtf(var + 1e-5f);
    float4 wv = reinterpret_cast<const float4*>(w)[t];
    float4 bv = reinterpret_cast<const float4*>(b)[t];
    float o0 = (xv.x - mean) * rstd * wv.x + bv.x;
    float o1 = (xv.y - mean) * rstd * wv.y + bv.y;
    float o2 = (xv.z - mean) * rstd * wv.z + bv.z;
    float o3 = (xv.w - mean) * rstd * wv.w + bv.w;
    *reinterpret_cast<uint2*>(reinterpret_cast<char*>(y) + (size_t)lrow * 2048 + t * 8) =
        make_uint2(pack_h2(o0, o1), pack_h2(o2, o3));
}

// ---------------- W[n][k] -> W^T[k][n] fp16 ----------------
__global__ void wsplit(const float* __restrict__ Wq,
                       const float* __restrict__ Wk,
                       const float* __restrict__ Wv)
{
    int wsel = blockIdx.z;
    const float* W = (wsel == 0) ? Wq : (wsel == 1) ? Wk : Wv;
    __half* tf = g_wtf[wsel];
    __shared__ float tile[32][33];
    int k = blockIdx.x * 32 + threadIdx.x;
    int n0 = blockIdx.y * 32;
#pragma unroll
    for (int i = threadIdx.y; i < 32; i += 8)
        tile[i][threadIdx.x] = W[(size_t)(n0 + i) * 1024 + k];
    __syncthreads();
#pragma unroll
    for (int i = threadIdx.y; i < 32; i += 8) {
        float v = tile[threadIdx.x][i];
        size_t idx = (size_t)(blockIdx.x * 32 + i) * 1024 + n0 + threadIdx.x;
        tf[idx] = __float2half_rn(v);
    }
}

// ---------------- merged projection GEMM: Q+K+V in one launch ----------------
// 128x128 tile, K=32, 4-stage, 2 CTAs/SM.
// grid.x = 160 m-tiles: [0,32) Q, [32,96) K, [96,160) V; grid.y = 8 n-tiles.
// stage: A [128 rows][32 fp16 + 8 pad = 80B] = 10240
//        B [32 k][128 fp16 + 8 pad = 272B]   = 8704
#define G_A 0
#define G_B 10240
#define G_STAGE 18944

__global__ __launch_bounds__(256, 2) void gemm_tc(const float* __restrict__ bq,
                                                  const float* __restrict__ bk,
                                                  const float* __restrict__ bv)
{
    extern __shared__ __align__(16) uint8_t smg[];
    int tile = blockIdx.x;
    int dst, mtile;
    const float* bias;
    const __half* Af;
    if (tile < 32)      { dst = 0; mtile = tile;      bias = bq; Af = g_taf; }
    else if (tile < 96) { dst = 1; mtile = tile - 32; bias = bk; Af = g_aaf; }
    else                { dst = 2; mtile = tile - 96; bias = bv; Af = g_aaf; }
    const __half* Bf = g_wtf[dst];
    __half* Cf = (dst == 0) ? g_qf : (dst == 1) ? g_kf : g_vf;

    int t = threadIdx.x, lane = t & 31, warp = t >> 5;   // 8 warps, 2x4
    int wm = warp >> 2, wn = warp & 3;                    // warp tile 64 x 32
    int bm = mtile * 128, bn = blockIdx.y * 128;
    uint32_t smb = smem_to_u32(smg);

    int arow = t >> 2, aseg = t & 3;
    int brow = t >> 4, bseg = t & 15;
    const __half* ag0 = Af + (size_t)(bm + arow) * 1024 + aseg * 8;
    const __half* ag1 = Af + (size_t)(bm + arow + 64) * 1024 + aseg * 8;
    const __half* bg0 = Bf + (size_t)brow * 1024 + bn + bseg * 8;
    uint32_t a_dst0 = arow * 80 + aseg * 16;
    uint32_t a_dst1 = (arow + 64) * 80 + aseg * 16;
    uint32_t b_dst0 = brow * 272 + bseg * 16;

    auto issue = [&](int ch) {
        uint32_t base = smb + (uint32_t)((ch & 3) * G_STAGE);
        CP16(base + G_A + a_dst0, ag0 + ch * 32);
        CP16(base + G_A + a_dst1, ag1 + ch * 32);
        CP16(base + G_B + b_dst0, bg0 + (size_t)ch * 32 * 1024);
        CP16(base + G_B + b_dst0 + 16 * 272, bg0 + ((size_t)ch * 32 + 16) * 1024);
    };

    float acc[4][4][4];
#pragma unroll
    for (int i = 0; i < 4; i++)
#pragma unroll
        for (int j = 0; j < 4; j++)
#pragma unroll
            for (int e = 0; e < 4; e++) acc[i][j][e] = 0.f;

    issue(0); CP_COMMIT();
    issue(1); CP_COMMIT();
    issue(2); CP_COMMIT();

    uint32_t a_off = (lane & 15) * 80 + (lane >> 4) * 16;
    uint32_t b_off = ((lane & 7) + ((lane >> 3) & 1) * 8) * 272 + (lane >> 4) * 16;

    for (int ch = 0; ch < 32; ch++) {
        CP_WAIT(2);
        __syncthreads();
        if (ch + 3 < 32) issue(ch + 3);
        CP_COMMIT();

        uint32_t base = smb + (uint32_t)((ch & 3) * G_STAGE);
#pragma unroll
        for (int kc = 0; kc < 2; kc++) {
            uint32_t af[4][4], bf[4][2];
#pragma unroll
            for (int mt = 0; mt < 4; mt++) {
                uint32_t r = base + G_A + (uint32_t)((wm * 64 + mt * 16) * 80) + kc * 32 + a_off;
                LDSM_X4(af[mt][0], af[mt][1], af[mt][2], af[mt][3], r);
            }
#pragma unroll
            for (int pp = 0; pp < 2; pp++) {
                uint32_t r = base + G_B + (uint32_t)(kc * 16 * 272) +
                             (uint32_t)((wn * 32 + pp * 16) * 2) + b_off;
                LDSM_X4_T(bf[pp*2][0], bf[pp*2][1], bf[pp*2+1][0], bf[pp*2+1][1], r);
            }
#pragma unroll
            for (int mt = 0; mt < 4; mt++)
#pragma unroll
                for (int nt = 0; nt < 4; nt++)
                    mma_f16(acc[mt][nt], af[mt], bf[nt]);
        }
    }

    int lr = lane >> 2, lc = (lane & 3) * 2;
#pragma unroll
    for (int nt = 0; nt < 4; nt++) {
        int col = bn + wn * 32 + nt * 8 + lc;
        float b0 = __ldg(bias + col), b1 = __ldg(bias + col + 1);
#pragma unroll
        for (int mt = 0; mt < 4; mt++) {
            int row = bm + wm * 64 + mt * 16 + lr;
            *reinterpret_cast<uint32_t*>(reinterpret_cast<char*>(Cf) + ((size_t)row * 1024 + col) * 2) =
                pack_h2(acc[mt][nt][0] + b0, acc[mt][nt][1] + b1);
            *reinterpret_cast<uint32_t*>(reinterpret_cast<char*>(Cf) + ((size_t)(row + 8) * 1024 + col) * 2) =
                pack_h2(acc[mt][nt][2] + b0, acc[mt][nt][3] + b1);
        }
    }
}

// ---------------- score+mean: fp16, per (b, q-tile, k-tile), loop 16 heads ----------------
#define S_Q 0
#define S_K 18432
#define S_BUF 36864

__global__ __launch_bounds__(512, 1) void score_mean_tc(float* __restrict__ amean)
{
    extern __shared__ __align__(16) uint8_t smg[];
    int b = blockIdx.z;
    int q0 = blockIdx.y * 128, k0 = blockIdx.x * 128;
    int t = threadIdx.x, lane = t & 31, warp = t >> 5;
    int wm = warp >> 2, wn = warp & 3;
    uint32_t smb = smem_to_u32(smg);

    int plane = t >> 8, v = (t & 255) >> 1, hseg = t & 1;
    const __half* srcp = plane ? (g_kf + (size_t)(b * 1024 + k0 + v) * 1024)
                               : (g_qf + (size_t)(b * 512  + q0 + v) * 1024);
    uint32_t doff = (plane ? S_K : S_Q) + v * 144 + hseg * 64;

    auto issue = [&](int h) {
        uint32_t base = smb + (uint32_t)((h & 1) * S_BUF);
        const __half* s = srcp + h * 64 + hseg * 32;
#pragma unroll
        for (int seg = 0; seg < 4; seg++)
            CP16(base + doff + seg * 16, s + seg * 8);
    };

    uint32_t a_off = (lane & 15) * 144 + (lane >> 4) * 16;
    uint32_t b_off = ((lane & 7) + ((lane >> 4) & 1) * 8) * 144 + ((lane >> 3) & 1) * 16;

    float am[2][4][4];
#pragma unroll
    for (int i = 0; i < 2; i++)
#pragma unroll
        for (int j = 0; j < 4; j++)
#pragma unroll
            for (int e = 0; e < 4; e++) am[i][j][e] = 0.f;

    int lr = lane >> 2, lc = (lane & 3) * 2;

    issue(0); CP_COMMIT();

    for (int h = 0; h < 16; h++) {
        if (h < 15) { issue(h + 1); CP_COMMIT(); CP_WAIT(1); }
        else        { CP_WAIT(0); }
        __syncthreads();

        uint32_t base = smb + (uint32_t)((h & 1) * S_BUF);
        float acc[2][4][4];
#pragma unroll
        for (int i = 0; i < 2; i++)
#pragma unroll
            for (int j = 0; j < 4; j++)
#pragma unroll
                for (int e = 0; e < 4; e++) acc[i][j][e] = 0.f;

#pragma unroll
        for (int kc = 0; kc < 4; kc++) {
            uint32_t af[2][4], bf[4][2];
#pragma unroll
            for (int mt = 0; mt < 2; mt++) {
                uint32_t r = base + S_Q + (uint32_t)((wm * 32 + mt * 16) * 144) + kc * 32 + a_off;
                LDSM_X4(af[mt][0], af[mt][1], af[mt][2], af[mt][3], r);
            }
#pragma unroll
            for (int pp = 0; pp < 2; pp++) {
                uint32_t r = base + S_K + (uint32_t)((wn * 32 + pp * 16) * 144) + kc * 32 + b_off;
                LDSM_X4(bf[pp*2][0], bf[pp*2][1], bf[pp*2+1][0], bf[pp*2+1][1], r);
            }
#pragma unroll
            for (int mt = 0; mt < 2; mt++)
#pragma unroll
                for (int nt = 0; nt < 4; nt++)
                    mma_f16(acc[mt][nt], af[mt], bf[nt]);
        }

        size_t splane = ((size_t)b * 16 + h) * 524288;
#pragma unroll
        for (int mt = 0; mt < 2; mt++)
#pragma unroll
            for (int nt = 0; nt < 4; nt++) {
                float s0 = __fdividef(1.f, 1.f + __expf(-0.125f * acc[mt][nt][0]));
                float s1 = __fdividef(1.f, 1.f + __expf(-0.125f * acc[mt][nt][1]));
                float s2 = __fdividef(1.f, 1.f + __expf(-0.125f * acc[mt][nt][2]));
                float s3 = __fdividef(1.f, 1.f + __expf(-0.125f * acc[mt][nt][3]));
                am[mt][nt][0] += s0; am[mt][nt][1] += s1;
                am[mt][nt][2] += s2; am[mt][nt][3] += s3;
                int row = q0 + wm * 32 + mt * 16 + lr;
                int col = k0 + wn * 32 + nt * 8 + lc;
                *reinterpret_cast<uint32_t*>(reinterpret_cast<char*>(g_sf) + (splane + (size_t)row * 1024 + col) * 2) =
                    pack_h2(s0, s1);
                *reinterpret_cast<uint32_t*>(reinterpret_cast<char*>(g_sf) + (splane + (size_t)(row + 8) * 1024 + col) * 2) =
                    pack_h2(s2, s3);
            }
        __syncthreads();
    }

#pragma unroll
    for (int mt = 0; mt < 2; mt++)
#pragma unroll
        for (int nt = 0; nt < 4; nt++) {
            int row = q0 + wm * 32 + mt * 16 + lr;
            int col = k0 + wn * 32 + nt * 8 + lc;
            *reinterpret_cast<float2*>(amean + ((size_t)(b * 512) + row) * 1024 + col) =
                make_float2(am[mt][nt][0] * 0.0625f, am[mt][nt][1] * 0.0625f);
            *reinterpret_cast<float2*>(amean + ((size_t)(b * 512) + row + 8) * 1024 + col) =
                make_float2(am[mt][nt][2] * 0.0625f, am[mt][nt][3] * 0.0625f);
        }
}

// ---------------- AV: out = S @ V, fp16, K-chunk 64, 3-stage ----------------
#define A_S 0
#define A_V 18432
#define A_STAGE 27648

__global__ __launch_bounds__(256, 2) void av_tc(float* __restrict__ out)
{
    extern __shared__ __align__(16) uint8_t smg[];
    int bh = blockIdx.y, b = bh >> 4, h = bh & 15;
    int q0 = blockIdx.x * 128;
    int t = threadIdx.x, lane = t & 31, warp = t >> 5;
    int wm = warp >> 1, wn = warp & 1;                   // 4x2, warp tile 32x32
    uint32_t smb = smem_to_u32(smg);

    int sr = t >> 3, ss8 = t & 7;
    const __half* sg = g_sf + ((size_t)bh * 512 + q0 + sr) * 1024 + ss8 * 8;
    uint32_t s_dst = sr * 144 + ss8 * 16;
    int vr = t >> 3;
    const __half* vg = g_vf + (size_t)(b * 1024 + vr) * 1024 + h * 64 + ss8 * 8;
    uint32_t v_dst = A_V + vr * 144 + ss8 * 16;

    auto issue = [&](int ch) {
        uint32_t base = smb + (uint32_t)((ch % 3) * A_STAGE);
#pragma unroll
        for (int i = 0; i < 4; i++)
            CP16(base + A_S + s_dst + i * 32 * 144, sg + (size_t)i * 32 * 1024 + ch * 64);
#pragma unroll
        for (int i = 0; i < 2; i++)
            CP16(base + v_dst + i * 32 * 144, vg + ((size_t)ch * 64 + i * 32) * 1024);
    };

    float acc[2][4][4];
#pragma unroll
    for (int i = 0; i < 2; i++)
#pragma unroll
        for (int j = 0; j < 4; j++)
#pragma unroll
            for (int e = 0; e < 4; e++) acc[i][j][e] = 0.f;

    issue(0); CP_COMMIT();
    issue(1); CP_COMMIT();

    uint32_t a_off = (lane & 15) * 144 + (lane >> 4) * 16;
    uint32_t b_off = ((lane & 7) + ((lane >> 3) & 1) * 8) * 144 + (lane >> 4) * 16;

    for (int ch = 0; ch < 16; ch++) {
        CP_WAIT(1);
        __syncthreads();
        if (ch + 2 < 16) issue(ch + 2);
        CP_COMMIT();

        uint32_t base = smb + (uint32_t)((ch % 3) * A_STAGE);
#pragma unroll
        for (int kc = 0; kc < 4; kc++) {
            uint32_t af[2][4], bf[4][2];
#pragma unroll
            for (int mt = 0; mt < 2; mt++) {
                uint32_t r = base + A_S + (uint32_t)((wm * 32 + mt * 16) * 144) + kc * 32 + a_off;
                LDSM_X4(af[mt][0], af[mt][1], af[mt][2], af[mt][3], r);
            }
#pragma unroll
            for (int pp = 0; pp < 2; pp++) {
                uint32_t r = base + A_V + (uint32_t)(kc * 16 * 144) +
                             (uint32_t)((wn * 32 + pp * 16) * 2) + b_off;
                LDSM_X4_T(bf[pp*2][0], bf[pp*2][1], bf[pp*2+1][0], bf[pp*2+1][1], r);
            }
#pragma unroll
            for (int mt = 0; mt < 2; mt++)
#pragma unroll
                for (int nt = 0; nt < 4; nt++)
                    mma_f16(acc[mt][nt], af[mt], bf[nt]);
        }
    }

    int lr = lane >> 2, lc = (lane & 3) * 2;
#pragma unroll
    for (int nt = 0; nt < 4; nt++) {
        int col = h * 64 + wn * 32 + nt * 8 + lc;
#pragma unroll
        for (int mt = 0; mt < 2; mt++) {
            int row = b * 512 + q0 + wm * 32 + mt * 16 + lr;
            *reinterpret_cast<float2*>(out + (size_t)row * 1024 + col) =
                make_float2(acc[mt][nt][0], acc[mt][nt][1]);
            *reinterpret_cast<float2*>(out + (size_t)(row + 8) * 1024 + col) =
                make_float2(acc[mt][nt][2], acc[mt][nt][3]);
        }
    }
}

// ---------------- launch ----------------
extern "C" void kernel_launch(void* const* d_in, const int* in_sizes, int n_in,
                              void* d_out, int out_size)
{
    (void)in_sizes; (void)n_in; (void)out_size;
    const float* text = (const float*)d_in[0];
    const float* av   = (const float*)d_in[1];
    const float* tn_w = (const float*)d_in[2];
    const float* tn_b = (const float*)d_in[3];
    const float* an_w = (const float*)d_in[4];
    const float* an_b = (const float*)d_in[5];
    const float* Wq   = (const float*)d_in[6];
    const float* bq   = (const float*)d_in[7];
    const float* Wk   = (const float*)d_in[8];
    const float* bk   = (const float*)d_in[9];
    const float* Wv   = (const float*)d_in[10];
    const float* bv   = (const float*)d_in[11];

    float* out   = (float*)d_out;
    float* amean = out + (size_t)BS * NW * 1024;

    static int attr_done = 0;
    if (!attr_done) {
        cudaFuncSetAttribute(gemm_tc,       cudaFuncAttributeMaxDynamicSharedMemorySize, 4 * G_STAGE);
        cudaFuncSetAttribute(score_mean_tc, cudaFuncAttributeMaxDynamicSharedMemorySize, 2 * S_BUF);
        cudaFuncSetAttribute(av_tc,         cudaFuncAttributeMaxDynamicSharedMemorySize, 3 * A_STAGE);
        attr_done = 1;
    }

    ln_f16<<<BS * NW + BS * NV, 256>>>(text, av, tn_w, tn_b, an_w, an_b);
    wsplit<<<dim3(32, 32, 3), dim3(32, 8)>>>(Wq, Wk, Wv);

    gemm_tc<<<dim3(160, 8), 256, 4 * G_STAGE>>>(bq, bk, bv);

    score_mean_tc<<<dim3(8, 4, 8), 512, 2 * S_BUF>>>(amean);
    av_tc<<<dim3(4, 128), 256, 3 * A_STAGE>>>(out);
}

// round 13
// speedup vs baseline: 3.2650x; 1.0154x over previous
#include <cuda_runtime.h>
#include <cuda_fp16.h>
#include <cstdint>

#define BS 8
#define NW 512
#define NV 1024

// ---------------- fp16 scratch (allocation-free) ----------------
__device__ __half g_taf[BS*NW*1024];                       // LN(text)
__device__ __half g_aaf[BS*NV*1024];                       // LN(av)
__device__ __half g_wtf[3][1024*1024];                     // W^T [k][n]
__device__ __half g_qf[BS*NW*1024];
__device__ __half g_kf[BS*NV*1024];
__device__ __half g_vf[BS*NV*1024];
__device__ __half g_sf[(size_t)BS*16*NW*NV];               // sigmoid scores, 128 MB

// ---------------- helpers ----------------
__device__ __forceinline__ uint32_t smem_to_u32(const void* p) {
    uint32_t a;
    asm("{ .reg .u64 t; cvta.to.shared.u64 t, %1; cvt.u32.u64 %0, t; }" : "=r"(a) : "l"(p));
    return a;
}
__device__ __forceinline__ uint32_t pack_h2(float x0, float x1) {
    __half2 p = __floats2half2_rn(x0, x1);
    return *reinterpret_cast<uint32_t*>(&p);
}

#define LDSM_X4(r0, r1, r2, r3, addr) \
    asm volatile("ldmatrix.sync.aligned.m8n8.x4.shared.b16 {%0,%1,%2,%3}, [%4];" \
        : "=r"(r0), "=r"(r1), "=r"(r2), "=r"(r3) : "r"(addr))
#define LDSM_X4_T(r0, r1, r2, r3, addr) \
    asm volatile("ldmatrix.sync.aligned.m8n8.x4.trans.shared.b16 {%0,%1,%2,%3}, [%4];" \
        : "=r"(r0), "=r"(r1), "=r"(r2), "=r"(r3) : "r"(addr))

__device__ __forceinline__ void mma_f16(float* c, const uint32_t* a, const uint32_t* b) {
    asm volatile(
        "mma.sync.aligned.m16n8k16.row.col.f32.f16.f16.f32 "
        "{%0,%1,%2,%3}, {%4,%5,%6,%7}, {%8,%9}, {%0,%1,%2,%3};"
        : "+f"(c[0]), "+f"(c[1]), "+f"(c[2]), "+f"(c[3])
        : "r"(a[0]), "r"(a[1]), "r"(a[2]), "r"(a[3]), "r"(b[0]), "r"(b[1]));
}

#define CP16(dst, src) \
    asm volatile("cp.async.cg.shared.global [%0], [%1], 16;" :: "r"((uint32_t)(dst)), "l"(src) : "memory")
#define CP_COMMIT() asm volatile("cp.async.commit_group;" ::: "memory")
#define CP_WAIT(n)  asm volatile("cp.async.wait_group %0;" :: "n"(n) : "memory")

// ---------------- LayerNorm (both tensors, one launch) -> fp16 ----------------
__global__ __launch_bounds__(256) void ln_f16(const float* __restrict__ text,
                                              const float* __restrict__ av,
                                              const float* __restrict__ tw,
                                              const float* __restrict__ tb,
                                              const float* __restrict__ aw,
                                              const float* __restrict__ ab)
{
    int row = blockIdx.x, t = threadIdx.x;
    const float* x;
    const float* w;
    const float* b;
    __half* y;
    int lrow;
    if (row < BS * NW) {
        x = text; w = tw; b = tb; y = g_taf; lrow = row;
    } else {
        x = av;   w = aw; b = ab; y = g_aaf; lrow = row - BS * NW;
    }
    float4 xv = reinterpret_cast<const float4*>(x)[(size_t)lrow * 256 + t];
    float s  = xv.x + xv.y + xv.z + xv.w;
    float ss = xv.x*xv.x + xv.y*xv.y + xv.z*xv.z + xv.w*xv.w;
#pragma unroll
    for (int o = 16; o > 0; o >>= 1) {
        s  += __shfl_xor_sync(0xffffffffu, s,  o);
        ss += __shfl_xor_sync(0xffffffffu, ss, o);
    }
    __shared__ float rs[8], rss[8];
    if ((t & 31) == 0) { rs[t >> 5] = s; rss[t >> 5] = ss; }
    __syncthreads();
    float tot = 0.f, tot2 = 0.f;
#pragma unroll
    for (int i = 0; i < 8; i++) { tot += rs[i]; tot2 += rss[i]; }
    float mean = tot * (1.f / 1024.f);
    float var  = tot2 * (1.f / 1024.f) - mean * mean;
    float rstd = rsqrtf(var + 1e-5f);
    float4 wv = reinterpret_cast<const float4*>(w)[t];
    float4 bv = reinterpret_cast<const float4*>(b)[t];
    float o0 = (xv.x - mean) * rstd * wv.x + bv.x;
    float o1 = (xv.y - mean) * rstd * wv.y + bv.y;
    float o2 = (xv.z - mean) * rstd * wv.z + bv.z;
    float o3 = (xv.w - mean) * rstd * wv.w + bv.w;
    *reinterpret_cast<uint2*>(reinterpret_cast<char*>(y) + (size_t)lrow * 2048 + t * 8) =
        make_uint2(pack_h2(o0, o1), pack_h2(o2, o3));
}

// ---------------- W[n][k] -> W^T[k][n] fp16 ----------------
__global__ void wsplit(const float* __restrict__ Wq,
                       const float* __restrict__ Wk,
                       const float* __restrict__ Wv)
{
    int wsel = blockIdx.z;
    const float* W = (wsel == 0) ? Wq : (wsel == 1) ? Wk : Wv;
    __half* tf = g_wtf[wsel];
    __shared__ float tile[32][33];
    int k = blockIdx.x * 32 + threadIdx.x;
    int n0 = blockIdx.y * 32;
#pragma unroll
    for (int i = threadIdx.y; i < 32; i += 8)
        tile[i][threadIdx.x] = W[(size_t)(n0 + i) * 1024 + k];
    __syncthreads();
#pragma unroll
    for (int i = threadIdx.y; i < 32; i += 8) {
        float v = tile[threadIdx.x][i];
        size_t idx = (size_t)(blockIdx.x * 32 + i) * 1024 + n0 + threadIdx.x;
        tf[idx] = __float2half_rn(v);
    }
}

// ---------------- merged projection GEMM: Q+K+V in one launch ----------------
// 128x128 tile, K=32, 4-stage, 2 CTAs/SM. Epilogue staged via smem for coalesced STG.
#define G_A 0
#define G_B 10240
#define G_STAGE 18944

__global__ __launch_bounds__(256, 2) void gemm_tc(const float* __restrict__ bq,
                                                  const float* __restrict__ bk,
                                                  const float* __restrict__ bv)
{
    extern __shared__ __align__(16) uint8_t smg[];
    int tile = blockIdx.x;
    int dst, mtile;
    const float* bias;
    const __half* Af;
    if (tile < 32)      { dst = 0; mtile = tile;      bias = bq; Af = g_taf; }
    else if (tile < 96) { dst = 1; mtile = tile - 32; bias = bk; Af = g_aaf; }
    else                { dst = 2; mtile = tile - 96; bias = bv; Af = g_aaf; }
    const __half* Bf = g_wtf[dst];
    __half* Cf = (dst == 0) ? g_qf : (dst == 1) ? g_kf : g_vf;

    int t = threadIdx.x, lane = t & 31, warp = t >> 5;   // 8 warps, 2x4
    int wm = warp >> 2, wn = warp & 3;                    // warp tile 64 x 32
    int bm = mtile * 128, bn = blockIdx.y * 128;
    uint32_t smb = smem_to_u32(smg);

    int arow = t >> 2, aseg = t & 3;
    int brow = t >> 4, bseg = t & 15;
    const __half* ag0 = Af + (size_t)(bm + arow) * 1024 + aseg * 8;
    const __half* ag1 = Af + (size_t)(bm + arow + 64) * 1024 + aseg * 8;
    const __half* bg0 = Bf + (size_t)brow * 1024 + bn + bseg * 8;
    uint32_t a_dst0 = arow * 80 + aseg * 16;
    uint32_t a_dst1 = (arow + 64) * 80 + aseg * 16;
    uint32_t b_dst0 = brow * 272 + bseg * 16;

    auto issue = [&](int ch) {
        uint32_t base = smb + (uint32_t)((ch & 3) * G_STAGE);
        CP16(base + G_A + a_dst0, ag0 + ch * 32);
        CP16(base + G_A + a_dst1, ag1 + ch * 32);
        CP16(base + G_B + b_dst0, bg0 + (size_t)ch * 32 * 1024);
        CP16(base + G_B + b_dst0 + 16 * 272, bg0 + ((size_t)ch * 32 + 16) * 1024);
    };

    float acc[4][4][4];
#pragma unroll
    for (int i = 0; i < 4; i++)
#pragma unroll
        for (int j = 0; j < 4; j++)
#pragma unroll
            for (int e = 0; e < 4; e++) acc[i][j][e] = 0.f;

    issue(0); CP_COMMIT();
    issue(1); CP_COMMIT();
    issue(2); CP_COMMIT();

    uint32_t a_off = (lane & 15) * 80 + (lane >> 4) * 16;
    uint32_t b_off = ((lane & 7) + ((lane >> 3) & 1) * 8) * 272 + (lane >> 4) * 16;

    for (int ch = 0; ch < 32; ch++) {
        CP_WAIT(2);
        __syncthreads();
        if (ch + 3 < 32) issue(ch + 3);
        CP_COMMIT();

        uint32_t base = smb + (uint32_t)((ch & 3) * G_STAGE);
#pragma unroll
        for (int kc = 0; kc < 2; kc++) {
            uint32_t af[4][4], bf[4][2];
#pragma unroll
            for (int mt = 0; mt < 4; mt++) {
                uint32_t r = base + G_A + (uint32_t)((wm * 64 + mt * 16) * 80) + kc * 32 + a_off;
                LDSM_X4(af[mt][0], af[mt][1], af[mt][2], af[mt][3], r);
            }
#pragma unroll
            for (int pp = 0; pp < 2; pp++) {
                uint32_t r = base + G_B + (uint32_t)(kc * 16 * 272) +
                             (uint32_t)((wn * 32 + pp * 16) * 2) + b_off;
                LDSM_X4_T(bf[pp*2][0], bf[pp*2][1], bf[pp*2+1][0], bf[pp*2+1][1], r);
            }
#pragma unroll
            for (int mt = 0; mt < 4; mt++)
#pragma unroll
                for (int nt = 0; nt < 4; nt++)
                    mma_f16(acc[mt][nt], af[mt], bf[nt]);
        }
    }

    // ---- staged epilogue: fragments -> smem stage -> coalesced 16B STG ----
    CP_WAIT(0);
    __syncthreads();                     // pipeline buffers dead; reuse as stage
    int lr = lane >> 2, lc = (lane & 3) * 2;
#pragma unroll
    for (int nt = 0; nt < 4; nt++) {
        int col = bn + wn * 32 + nt * 8 + lc;
        float b0 = __ldg(bias + col), b1 = __ldg(bias + col + 1);
        int lcol = wn * 32 + nt * 8 + lc;
#pragma unroll
        for (int mt = 0; mt < 4; mt++) {
            int lrow = wm * 64 + mt * 16 + lr;
            *reinterpret_cast<uint32_t*>(smg + lrow * 272 + lcol * 2) =
                pack_h2(acc[mt][nt][0] + b0, acc[mt][nt][1] + b1);
            *reinterpret_cast<uint32_t*>(smg + (lrow + 8) * 272 + lcol * 2) =
                pack_h2(acc[mt][nt][2] + b0, acc[mt][nt][3] + b1);
        }
    }
    __syncthreads();
    char* cdst = reinterpret_cast<char*>(Cf) + ((size_t)bm * 1024 + bn) * 2;
#pragma unroll
    for (int i = 0; i < 8; i++) {
        int idx = t + i * 256;           // 2048 float4 total
        int row = idx >> 4, f4 = idx & 15;
        uint4 v = *reinterpret_cast<uint4*>(smg + row * 272 + f4 * 16);
        *reinterpret_cast<uint4*>(cdst + (size_t)row * 2048 + f4 * 16) = v;
    }
}

// ---------------- score+mean: fp16, per (b, q-tile, k-tile), loop 16 heads ----------------
// smem: double-buffered Q/K (2 x 36864) + S stage (128 x 272 = 34816) = 108544
#define S_Q 0
#define S_K 18432
#define S_BUF 36864
#define S_STG 73728
#define S_SMEM 108544

__global__ __launch_bounds__(512, 1) void score_mean_tc(float* __restrict__ amean)
{
    extern __shared__ __align__(16) uint8_t smg[];
    int b = blockIdx.z;
    int q0 = blockIdx.y * 128, k0 = blockIdx.x * 128;
    int t = threadIdx.x, lane = t & 31, warp = t >> 5;
    int wm = warp >> 2, wn = warp & 3;
    uint32_t smb = smem_to_u32(smg);

    int plane = t >> 8, v = (t & 255) >> 1, hseg = t & 1;
    const __half* srcp = plane ? (g_kf + (size_t)(b * 1024 + k0 + v) * 1024)
                               : (g_qf + (size_t)(b * 512  + q0 + v) * 1024);
    uint32_t doff = (plane ? S_K : S_Q) + v * 144 + hseg * 64;

    auto issue = [&](int h) {
        uint32_t base = smb + (uint32_t)((h & 1) * S_BUF);
        const __half* s = srcp + h * 64 + hseg * 32;
#pragma unroll
        for (int seg = 0; seg < 4; seg++)
            CP16(base + doff + seg * 16, s + seg * 8);
    };

    uint32_t a_off = (lane & 15) * 144 + (lane >> 4) * 16;
    uint32_t b_off = ((lane & 7) + ((lane >> 4) & 1) * 8) * 144 + ((lane >> 3) & 1) * 16;

    float am[2][4][4];
#pragma unroll
    for (int i = 0; i < 2; i++)
#pragma unroll
        for (int j = 0; j < 4; j++)
#pragma unroll
            for (int e = 0; e < 4; e++) am[i][j][e] = 0.f;

    int lr = lane >> 2, lc = (lane & 3) * 2;
    char* sbase = reinterpret_cast<char*>(g_sf) +
                  ((size_t)b * 16 * 524288 + (size_t)q0 * 1024 + k0) * 2;

    issue(0); CP_COMMIT();

    for (int h = 0; h < 16; h++) {
        if (h < 15) { issue(h + 1); CP_COMMIT(); CP_WAIT(1); }
        else        { CP_WAIT(0); }
        __syncthreads();

        uint32_t base = smb + (uint32_t)((h & 1) * S_BUF);
        float acc[2][4][4];
#pragma unroll
        for (int i = 0; i < 2; i++)
#pragma unroll
            for (int j = 0; j < 4; j++)
#pragma unroll
                for (int e = 0; e < 4; e++) acc[i][j][e] = 0.f;

#pragma unroll
        for (int kc = 0; kc < 4; kc++) {
            uint32_t af[2][4], bf[4][2];
#pragma unroll
            for (int mt = 0; mt < 2; mt++) {
                uint32_t r = base + S_Q + (uint32_t)((wm * 32 + mt * 16) * 144) + kc * 32 + a_off;
                LDSM_X4(af[mt][0], af[mt][1], af[mt][2], af[mt][3], r);
            }
#pragma unroll
            for (int pp = 0; pp < 2; pp++) {
                uint32_t r = base + S_K + (uint32_t)((wn * 32 + pp * 16) * 144) + kc * 32 + b_off;
                LDSM_X4(bf[pp*2][0], bf[pp*2][1], bf[pp*2+1][0], bf[pp*2+1][1], r);
            }
#pragma unroll
            for (int mt = 0; mt < 2; mt++)
#pragma unroll
                for (int nt = 0; nt < 4; nt++)
                    mma_f16(acc[mt][nt], af[mt], bf[nt]);
        }

        // sigmoid + mean accumulate + STS to stage
#pragma unroll
        for (int mt = 0; mt < 2; mt++)
#pragma unroll
            for (int nt = 0; nt < 4; nt++) {
                float s0 = __fdividef(1.f, 1.f + __expf(-0.125f * acc[mt][nt][0]));
                float s1 = __fdividef(1.f, 1.f + __expf(-0.125f * acc[mt][nt][1]));
                float s2 = __fdividef(1.f, 1.f + __expf(-0.125f * acc[mt][nt][2]));
                float s3 = __fdividef(1.f, 1.f + __expf(-0.125f * acc[mt][nt][3]));
                am[mt][nt][0] += s0; am[mt][nt][1] += s1;
                am[mt][nt][2] += s2; am[mt][nt][3] += s3;
                int lrow = wm * 32 + mt * 16 + lr;
                int lcol = wn * 32 + nt * 8 + lc;
                *reinterpret_cast<uint32_t*>(smg + S_STG + lrow * 272 + lcol * 2) = pack_h2(s0, s1);
                *reinterpret_cast<uint32_t*>(smg + S_STG + (lrow + 8) * 272 + lcol * 2) = pack_h2(s2, s3);
            }
        __syncthreads();

        // coalesced 16B store of the 128x128 fp16 S tile
        char* hdst = sbase + (size_t)h * 1048576;       // 524288 fp16 * 2 bytes
#pragma unroll
        for (int i = 0; i < 4; i++) {
            int idx = t + i * 512;                      // 2048 float4 total
            int row = idx >> 4, f4 = idx & 15;
            uint4 vv = *reinterpret_cast<uint4*>(smg + S_STG + row * 272 + f4 * 16);
            *reinterpret_cast<uint4*>(hdst + (size_t)row * 2048 + f4 * 16) = vv;
        }
        __syncthreads();
    }

#pragma unroll
    for (int mt = 0; mt < 2; mt++)
#pragma unroll
        for (int nt = 0; nt < 4; nt++) {
            int row = q0 + wm * 32 + mt * 16 + lr;
            int col = k0 + wn * 32 + nt * 8 + lc;
            *reinterpret_cast<float2*>(amean + ((size_t)(b * 512) + row) * 1024 + col) =
                make_float2(am[mt][nt][0] * 0.0625f, am[mt][nt][1] * 0.0625f);
            *reinterpret_cast<float2*>(amean + ((size_t)(b * 512) + row + 8) * 1024 + col) =
                make_float2(am[mt][nt][2] * 0.0625f, am[mt][nt][3] * 0.0625f);
        }
}

// ---------------- AV: out = S @ V, fp16, K-chunk 64, 3-stage ----------------
#define A_S 0
#define A_V 18432
#define A_STAGE 27648

__global__ __launch_bounds__(256, 2) void av_tc(float* __restrict__ out)
{
    extern __shared__ __align__(16) uint8_t smg[];
    int bh = blockIdx.y, b = bh >> 4, h = bh & 15;
    int q0 = blockIdx.x * 128;
    int t = threadIdx.x, lane = t & 31, warp = t >> 5;
    int wm = warp >> 1, wn = warp & 1;                   // 4x2, warp tile 32x32
    uint32_t smb = smem_to_u32(smg);

    int sr = t >> 3, ss8 = t & 7;
    const __half* sg = g_sf + ((size_t)bh * 512 + q0 + sr) * 1024 + ss8 * 8;
    uint32_t s_dst = sr * 144 + ss8 * 16;
    int vr = t >> 3;
    const __half* vg = g_vf + (size_t)(b * 1024 + vr) * 1024 + h * 64 + ss8 * 8;
    uint32_t v_dst = A_V + vr * 144 + ss8 * 16;

    auto issue = [&](int ch) {
        uint32_t base = smb + (uint32_t)((ch % 3) * A_STAGE);
#pragma unroll
        for (int i = 0; i < 4; i++)
            CP16(base + A_S + s_dst + i * 32 * 144, sg + (size_t)i * 32 * 1024 + ch * 64);
#pragma unroll
        for (int i = 0; i < 2; i++)
            CP16(base + v_dst + i * 32 * 144, vg + ((size_t)ch * 64 + i * 32) * 1024);
    };

    float acc[2][4][4];
#pragma unroll
    for (int i = 0; i < 2; i++)
#pragma unroll
        for (int j = 0; j < 4; j++)
#pragma unroll
            for (int e = 0; e < 4; e++) acc[i][j][e] = 0.f;

    issue(0); CP_COMMIT();
    issue(1); CP_COMMIT();

    uint32_t a_off = (lane & 15) * 144 + (lane >> 4) * 16;
    uint32_t b_off = ((lane & 7) + ((lane >> 3) & 1) * 8) * 144 + (lane >> 4) * 16;

    for (int ch = 0; ch < 16; ch++) {
        CP_WAIT(1);
        __syncthreads();
        if (ch + 2 < 16) issue(ch + 2);
        CP_COMMIT();

        uint32_t base = smb + (uint32_t)((ch % 3) * A_STAGE);
#pragma unroll
        for (int kc = 0; kc < 4; kc++) {
            uint32_t af[2][4], bf[4][2];
#pragma unroll
            for (int mt = 0; mt < 2; mt++) {
                uint32_t r = base + A_S + (uint32_t)((wm * 32 + mt * 16) * 144) + kc * 32 + a_off;
                LDSM_X4(af[mt][0], af[mt][1], af[mt][2], af[mt][3], r);
            }
#pragma unroll
            for (int pp = 0; pp < 2; pp++) {
                uint32_t r = base + A_V + (uint32_t)(kc * 16 * 144) +
                             (uint32_t)((wn * 32 + pp * 16) * 2) + b_off;
                LDSM_X4_T(bf[pp*2][0], bf[pp*2][1], bf[pp*2+1][0], bf[pp*2+1][1], r);
            }
#pragma unroll
            for (int mt = 0; mt < 2; mt++)
#pragma unroll
                for (int nt = 0; nt < 4; nt++)
                    mma_f16(acc[mt][nt], af[mt], bf[nt]);
        }
    }

    int lr = lane >> 2, lc = (lane & 3) * 2;
#pragma unroll
    for (int nt = 0; nt < 4; nt++) {
        int col = h * 64 + wn * 32 + nt * 8 + lc;
#pragma unroll
        for (int mt = 0; mt < 2; mt++) {
            int row = b * 512 + q0 + wm * 32 + mt * 16 + lr;
            *reinterpret_cast<float2*>(out + (size_t)row * 1024 + col) =
                make_float2(acc[mt][nt][0], acc[mt][nt][1]);
            *reinterpret_cast<float2*>(out + (size_t)(row + 8) * 1024 + col) =
                make_float2(acc[mt][nt][2], acc[mt][nt][3]);
        }
    }
}

// ---------------- launch ----------------
extern "C" void kernel_launch(void* const* d_in, const int* in_sizes, int n_in,
                              void* d_out, int out_size)
{
    (void)in_sizes; (void)n_in; (void)out_size;
    const float* text = (const float*)d_in[0];
    const float* av   = (const float*)d_in[1];
    const float* tn_w = (const float*)d_in[2];
    const float* tn_b = (const float*)d_in[3];
    const float* an_w = (const float*)d_in[4];
    const float* an_b = (const float*)d_in[5];
    const float* Wq   = (const float*)d_in[6];
    const float* bq   = (const float*)d_in[7];
    const float* Wk   = (const float*)d_in[8];
    const float* bk   = (const float*)d_in[9];
    const float* Wv   = (const float*)d_in[10];
    const float* bv   = (const float*)d_in[11];

    float* out   = (float*)d_out;
    float* amean = out + (size_t)BS * NW * 1024;

    static int attr_done = 0;
    if (!attr_done) {
        cudaFuncSetAttribute(gemm_tc,       cudaFuncAttributeMaxDynamicSharedMemorySize, 4 * G_STAGE);
        cudaFuncSetAttribute(score_mean_tc, cudaFuncAttributeMaxDynamicSharedMemorySize, S_SMEM);
        cudaFuncSetAttribute(av_tc,         cudaFuncAttributeMaxDynamicSharedMemorySize, 3 * A_STAGE);
        attr_done = 1;
    }

    ln_f16<<<BS * NW + BS * NV, 256>>>(text, av, tn_w, tn_b, an_w, an_b);
    wsplit<<<dim3(32, 32, 3), dim3(32, 8)>>>(Wq, Wk, Wv);

    gemm_tc<<<dim3(160, 8), 256, 4 * G_STAGE>>>(bq, bk, bv);

    score_mean_tc<<<dim3(8, 4, 8), 512, S_SMEM>>>(amean);
    av_tc<<<dim3(4, 128), 256, 3 * A_STAGE>>>(out);
}

// round 14
// speedup vs baseline: 3.3793x; 1.0350x over previous
#include <cuda_runtime.h>
#include <cuda_fp16.h>
#include <cstdint>

#define BS 8
#define NW 512
#define NV 1024

// ---------------- fp16 scratch (allocation-free) ----------------
__device__ __half g_taf[BS*NW*1024];                       // LN(text)
__device__ __half g_aaf[BS*NV*1024];                       // LN(av)
__device__ __half g_wtf[3][1024*1024];                     // W^T [k][n]
__device__ __half g_qf[BS*NW*1024];
__device__ __half g_kf[BS*NV*1024];
__device__ __half g_vf[BS*NV*1024];
__device__ __half g_sf[(size_t)BS*16*NW*NV];               // sigmoid scores, 128 MB

// ---------------- helpers ----------------
__device__ __forceinline__ uint32_t smem_to_u32(const void* p) {
    uint32_t a;
    asm("{ .reg .u64 t; cvta.to.shared.u64 t, %1; cvt.u32.u64 %0, t; }" : "=r"(a) : "l"(p));
    return a;
}
__device__ __forceinline__ uint32_t pack_h2(float x0, float x1) {
    __half2 p = __floats2half2_rn(x0, x1);
    return *reinterpret_cast<uint32_t*>(&p);
}
__device__ __forceinline__ float sigmoid8(float x) {   // sigmoid(x/8) via tanh.approx
    float t;
    asm("tanh.approx.f32 %0, %1;" : "=f"(t) : "f"(x * 0.0625f));
    return fmaf(t, 0.5f, 0.5f);
}

#define LDSM_X4(r0, r1, r2, r3, addr) \
    asm volatile("ldmatrix.sync.aligned.m8n8.x4.shared.b16 {%0,%1,%2,%3}, [%4];" \
        : "=r"(r0), "=r"(r1), "=r"(r2), "=r"(r3) : "r"(addr))
#define LDSM_X4_T(r0, r1, r2, r3, addr) \
    asm volatile("ldmatrix.sync.aligned.m8n8.x4.trans.shared.b16 {%0,%1,%2,%3}, [%4];" \
        : "=r"(r0), "=r"(r1), "=r"(r2), "=r"(r3) : "r"(addr))

__device__ __forceinline__ void mma_f16(float* c, const uint32_t* a, const uint32_t* b) {
    asm volatile(
        "mma.sync.aligned.m16n8k16.row.col.f32.f16.f16.f32 "
        "{%0,%1,%2,%3}, {%4,%5,%6,%7}, {%8,%9}, {%0,%1,%2,%3};"
        : "+f"(c[0]), "+f"(c[1]), "+f"(c[2]), "+f"(c[3])
        : "r"(a[0]), "r"(a[1]), "r"(a[2]), "r"(a[3]), "r"(b[0]), "r"(b[1]));
}

#define CP16(dst, src) \
    asm volatile("cp.async.cg.shared.global [%0], [%1], 16;" :: "r"((uint32_t)(dst)), "l"(src) : "memory")
#define CP_COMMIT() asm volatile("cp.async.commit_group;" ::: "memory")
#define CP_WAIT(n)  asm volatile("cp.async.wait_group %0;" :: "n"(n) : "memory")

// ---------------- LayerNorm (both tensors, one launch) -> fp16 ----------------
__global__ __launch_bounds__(256) void ln_f16(const float* __restrict__ text,
                                              const float* __restrict__ av,
                                              const float* __restrict__ tw,
                                              const float* __restrict__ tb,
                                              const float* __restrict__ aw,
                                              const float* __restrict__ ab)
{
    int row = blockIdx.x, t = threadIdx.x;
    const float* x;
    const float* w;
    const float* b;
    __half* y;
    int lrow;
    if (row < BS * NW) {
        x = text; w = tw; b = tb; y = g_taf; lrow = row;
    } else {
        x = av;   w = aw; b = ab; y = g_aaf; lrow = row - BS * NW;
    }
    float4 xv = reinterpret_cast<const float4*>(x)[(size_t)lrow * 256 + t];
    float s  = xv.x + xv.y + xv.z + xv.w;
    float ss = xv.x*xv.x + xv.y*xv.y + xv.z*xv.z + xv.w*xv.w;
#pragma unroll
    for (int o = 16; o > 0; o >>= 1) {
        s  += __shfl_xor_sync(0xffffffffu, s,  o);
        ss += __shfl_xor_sync(0xffffffffu, ss, o);
    }
    __shared__ float rs[8], rss[8];
    if ((t & 31) == 0) { rs[t >> 5] = s; rss[t >> 5] = ss; }
    __syncthreads();
    float tot = 0.f, tot2 = 0.f;
#pragma unroll
    for (int i = 0; i < 8; i++) { tot += rs[i]; tot2 += rss[i]; }
    float mean = tot * (1.f / 1024.f);
    float var  = tot2 * (1.f / 1024.f) - mean * mean;
    float rstd = rsqrtf(var + 1e-5f);
    float4 wv = reinterpret_cast<const float4*>(w)[t];
    float4 bv = reinterpret_cast<const float4*>(b)[t];
    float o0 = (xv.x - mean) * rstd * wv.x + bv.x;
    float o1 = (xv.y - mean) * rstd * wv.y + bv.y;
    float o2 = (xv.z - mean) * rstd * wv.z + bv.z;
    float o3 = (xv.w - mean) * rstd * wv.w + bv.w;
    *reinterpret_cast<uint2*>(reinterpret_cast<char*>(y) + (size_t)lrow * 2048 + t * 8) =
        make_uint2(pack_h2(o0, o1), pack_h2(o2, o3));
}

// ---------------- W[n][k] -> W^T[k][n] fp16 ----------------
__global__ void wsplit(const float* __restrict__ Wq,
                       const float* __restrict__ Wk,
                       const float* __restrict__ Wv)
{
    int wsel = blockIdx.z;
    const float* W = (wsel == 0) ? Wq : (wsel == 1) ? Wk : Wv;
    __half* tf = g_wtf[wsel];
    __shared__ float tile[32][33];
    int k = blockIdx.x * 32 + threadIdx.x;
    int n0 = blockIdx.y * 32;
#pragma unroll
    for (int i = threadIdx.y; i < 32; i += 8)
        tile[i][threadIdx.x] = W[(size_t)(n0 + i) * 1024 + k];
    __syncthreads();
#pragma unroll
    for (int i = threadIdx.y; i < 32; i += 8) {
        float v = tile[threadIdx.x][i];
        size_t idx = (size_t)(blockIdx.x * 32 + i) * 1024 + n0 + threadIdx.x;
        tf[idx] = __float2half_rn(v);
    }
}

// ---------------- merged projection GEMM: Q+K+V in one launch ----------------
// 128x128 tile, K=32, 4-stage, 2 CTAs/SM. Epilogue staged via smem for coalesced STG.
#define G_A 0
#define G_B 10240
#define G_STAGE 18944

__global__ __launch_bounds__(256, 2) void gemm_tc(const float* __restrict__ bq,
                                                  const float* __restrict__ bk,
                                                  const float* __restrict__ bv)
{
    extern __shared__ __align__(16) uint8_t smg[];
    int tile = blockIdx.x;
    int dst, mtile;
    const float* bias;
    const __half* Af;
    if (tile < 32)      { dst = 0; mtile = tile;      bias = bq; Af = g_taf; }
    else if (tile < 96) { dst = 1; mtile = tile - 32; bias = bk; Af = g_aaf; }
    else                { dst = 2; mtile = tile - 96; bias = bv; Af = g_aaf; }
    const __half* Bf = g_wtf[dst];
    __half* Cf = (dst == 0) ? g_qf : (dst == 1) ? g_kf : g_vf;

    int t = threadIdx.x, lane = t & 31, warp = t >> 5;   // 8 warps, 2x4
    int wm = warp >> 2, wn = warp & 3;                    // warp tile 64 x 32
    int bm = mtile * 128, bn = blockIdx.y * 128;
    uint32_t smb = smem_to_u32(smg);

    int arow = t >> 2, aseg = t & 3;
    int brow = t >> 4, bseg = t & 15;
    const __half* ag0 = Af + (size_t)(bm + arow) * 1024 + aseg * 8;
    const __half* ag1 = Af + (size_t)(bm + arow + 64) * 1024 + aseg * 8;
    const __half* bg0 = Bf + (size_t)brow * 1024 + bn + bseg * 8;
    uint32_t a_dst0 = arow * 80 + aseg * 16;
    uint32_t a_dst1 = (arow + 64) * 80 + aseg * 16;
    uint32_t b_dst0 = brow * 272 + bseg * 16;

    auto issue = [&](int ch) {
        uint32_t base = smb + (uint32_t)((ch & 3) * G_STAGE);
        CP16(base + G_A + a_dst0, ag0 + ch * 32);
        CP16(base + G_A + a_dst1, ag1 + ch * 32);
        CP16(base + G_B + b_dst0, bg0 + (size_t)ch * 32 * 1024);
        CP16(base + G_B + b_dst0 + 16 * 272, bg0 + ((size_t)ch * 32 + 16) * 1024);
    };

    float acc[4][4][4];
#pragma unroll
    for (int i = 0; i < 4; i++)
#pragma unroll
        for (int j = 0; j < 4; j++)
#pragma unroll
            for (int e = 0; e < 4; e++) acc[i][j][e] = 0.f;

    issue(0); CP_COMMIT();
    issue(1); CP_COMMIT();
    issue(2); CP_COMMIT();

    uint32_t a_off = (lane & 15) * 80 + (lane >> 4) * 16;
    uint32_t b_off = ((lane & 7) + ((lane >> 3) & 1) * 8) * 272 + (lane >> 4) * 16;

    for (int ch = 0; ch < 32; ch++) {
        CP_WAIT(2);
        __syncthreads();
        if (ch + 3 < 32) issue(ch + 3);
        CP_COMMIT();

        uint32_t base = smb + (uint32_t)((ch & 3) * G_STAGE);
#pragma unroll
        for (int kc = 0; kc < 2; kc++) {
            uint32_t af[4][4], bf[4][2];
#pragma unroll
            for (int mt = 0; mt < 4; mt++) {
                uint32_t r = base + G_A + (uint32_t)((wm * 64 + mt * 16) * 80) + kc * 32 + a_off;
                LDSM_X4(af[mt][0], af[mt][1], af[mt][2], af[mt][3], r);
            }
#pragma unroll
            for (int pp = 0; pp < 2; pp++) {
                uint32_t r = base + G_B + (uint32_t)(kc * 16 * 272) +
                             (uint32_t)((wn * 32 + pp * 16) * 2) + b_off;
                LDSM_X4_T(bf[pp*2][0], bf[pp*2][1], bf[pp*2+1][0], bf[pp*2+1][1], r);
            }
#pragma unroll
            for (int mt = 0; mt < 4; mt++)
#pragma unroll
                for (int nt = 0; nt < 4; nt++)
                    mma_f16(acc[mt][nt], af[mt], bf[nt]);
        }
    }

    // ---- staged epilogue: fragments -> smem stage -> coalesced 16B STG ----
    CP_WAIT(0);
    __syncthreads();
    int lr = lane >> 2, lc = (lane & 3) * 2;
#pragma unroll
    for (int nt = 0; nt < 4; nt++) {
        int col = bn + wn * 32 + nt * 8 + lc;
        float b0 = __ldg(bias + col), b1 = __ldg(bias + col + 1);
        int lcol = wn * 32 + nt * 8 + lc;
#pragma unroll
        for (int mt = 0; mt < 4; mt++) {
            int lrow = wm * 64 + mt * 16 + lr;
            *reinterpret_cast<uint32_t*>(smg + lrow * 272 + lcol * 2) =
                pack_h2(acc[mt][nt][0] + b0, acc[mt][nt][1] + b1);
            *reinterpret_cast<uint32_t*>(smg + (lrow + 8) * 272 + lcol * 2) =
                pack_h2(acc[mt][nt][2] + b0, acc[mt][nt][3] + b1);
        }
    }
    __syncthreads();
    char* cdst = reinterpret_cast<char*>(Cf) + ((size_t)bm * 1024 + bn) * 2;
#pragma unroll
    for (int i = 0; i < 8; i++) {
        int idx = t + i * 256;
        int row = idx >> 4, f4 = idx & 15;
        uint4 v = *reinterpret_cast<uint4*>(smg + row * 272 + f4 * 16);
        *reinterpret_cast<uint4*>(cdst + (size_t)row * 2048 + f4 * 16) = v;
    }
}

// ---------------- score+mean: fp16, tanh-sigmoid, direct stores ----------------
#define S_Q 0
#define S_K 18432
#define S_BUF 36864

__global__ __launch_bounds__(512, 1) void score_mean_tc(float* __restrict__ amean)
{
    extern __shared__ __align__(16) uint8_t smg[];
    int b = blockIdx.z;
    int q0 = blockIdx.y * 128, k0 = blockIdx.x * 128;
    int t = threadIdx.x, lane = t & 31, warp = t >> 5;
    int wm = warp >> 2, wn = warp & 3;
    uint32_t smb = smem_to_u32(smg);

    int plane = t >> 8, v = (t & 255) >> 1, hseg = t & 1;
    const __half* srcp = plane ? (g_kf + (size_t)(b * 1024 + k0 + v) * 1024)
                               : (g_qf + (size_t)(b * 512  + q0 + v) * 1024);
    uint32_t doff = (plane ? S_K : S_Q) + v * 144 + hseg * 64;

    auto issue = [&](int h) {
        uint32_t base = smb + (uint32_t)((h & 1) * S_BUF);
        const __half* s = srcp + h * 64 + hseg * 32;
#pragma unroll
        for (int seg = 0; seg < 4; seg++)
            CP16(base + doff + seg * 16, s + seg * 8);
    };

    uint32_t a_off = (lane & 15) * 144 + (lane >> 4) * 16;
    uint32_t b_off = ((lane & 7) + ((lane >> 4) & 1) * 8) * 144 + ((lane >> 3) & 1) * 16;

    float am[2][4][4];
#pragma unroll
    for (int i = 0; i < 2; i++)
#pragma unroll
        for (int j = 0; j < 4; j++)
#pragma unroll
            for (int e = 0; e < 4; e++) am[i][j][e] = 0.f;

    int lr = lane >> 2, lc = (lane & 3) * 2;

    issue(0); CP_COMMIT();

    for (int h = 0; h < 16; h++) {
        if (h < 15) { issue(h + 1); CP_COMMIT(); CP_WAIT(1); }
        else        { CP_WAIT(0); }
        __syncthreads();

        uint32_t base = smb + (uint32_t)((h & 1) * S_BUF);
        float acc[2][4][4];
#pragma unroll
        for (int i = 0; i < 2; i++)
#pragma unroll
            for (int j = 0; j < 4; j++)
#pragma unroll
                for (int e = 0; e < 4; e++) acc[i][j][e] = 0.f;

#pragma unroll
        for (int kc = 0; kc < 4; kc++) {
            uint32_t af[2][4], bf[4][2];
#pragma unroll
            for (int mt = 0; mt < 2; mt++) {
                uint32_t r = base + S_Q + (uint32_t)((wm * 32 + mt * 16) * 144) + kc * 32 + a_off;
                LDSM_X4(af[mt][0], af[mt][1], af[mt][2], af[mt][3], r);
            }
#pragma unroll
            for (int pp = 0; pp < 2; pp++) {
                uint32_t r = base + S_K + (uint32_t)((wn * 32 + pp * 16) * 144) + kc * 32 + b_off;
                LDSM_X4(bf[pp*2][0], bf[pp*2][1], bf[pp*2+1][0], bf[pp*2+1][1], r);
            }
#pragma unroll
            for (int mt = 0; mt < 2; mt++)
#pragma unroll
                for (int nt = 0; nt < 4; nt++)
                    mma_f16(acc[mt][nt], af[mt], bf[nt]);
        }

        size_t splane = ((size_t)b * 16 + h) * 524288;
#pragma unroll
        for (int mt = 0; mt < 2; mt++)
#pragma unroll
            for (int nt = 0; nt < 4; nt++) {
                float s0 = sigmoid8(acc[mt][nt][0]);
                float s1 = sigmoid8(acc[mt][nt][1]);
                float s2 = sigmoid8(acc[mt][nt][2]);
                float s3 = sigmoid8(acc[mt][nt][3]);
                am[mt][nt][0] += s0; am[mt][nt][1] += s1;
                am[mt][nt][2] += s2; am[mt][nt][3] += s3;
                int row = q0 + wm * 32 + mt * 16 + lr;
                int col = k0 + wn * 32 + nt * 8 + lc;
                *reinterpret_cast<uint32_t*>(reinterpret_cast<char*>(g_sf) + (splane + (size_t)row * 1024 + col) * 2) =
                    pack_h2(s0, s1);
                *reinterpret_cast<uint32_t*>(reinterpret_cast<char*>(g_sf) + (splane + (size_t)(row + 8) * 1024 + col) * 2) =
                    pack_h2(s2, s3);
            }
        __syncthreads();
    }

#pragma unroll
    for (int mt = 0; mt < 2; mt++)
#pragma unroll
        for (int nt = 0; nt < 4; nt++) {
            int row = q0 + wm * 32 + mt * 16 + lr;
            int col = k0 + wn * 32 + nt * 8 + lc;
            *reinterpret_cast<float2*>(amean + ((size_t)(b * 512) + row) * 1024 + col) =
                make_float2(am[mt][nt][0] * 0.0625f, am[mt][nt][1] * 0.0625f);
            *reinterpret_cast<float2*>(amean + ((size_t)(b * 512) + row + 8) * 1024 + col) =
                make_float2(am[mt][nt][2] * 0.0625f, am[mt][nt][3] * 0.0625f);
        }
}

// ---------------- AV: out = S @ V, fp16, K-chunk 64, 3-stage ----------------
#define A_S 0
#define A_V 18432
#define A_STAGE 27648

__global__ __launch_bounds__(256, 2) void av_tc(float* __restrict__ out)
{
    extern __shared__ __align__(16) uint8_t smg[];
    int bh = blockIdx.y, b = bh >> 4, h = bh & 15;
    int q0 = blockIdx.x * 128;
    int t = threadIdx.x, lane = t & 31, warp = t >> 5;
    int wm = warp >> 1, wn = warp & 1;
    uint32_t smb = smem_to_u32(smg);

    int sr = t >> 3, ss8 = t & 7;
    const __half* sg = g_sf + ((size_t)bh * 512 + q0 + sr) * 1024 + ss8 * 8;
    uint32_t s_dst = sr * 144 + ss8 * 16;
    int vr = t >> 3;
    const __half* vg = g_vf + (size_t)(b * 1024 + vr) * 1024 + h * 64 + ss8 * 8;
    uint32_t v_dst = A_V + vr * 144 + ss8 * 16;

    auto issue = [&](int ch) {
        uint32_t base = smb + (uint32_t)((ch % 3) * A_STAGE);
#pragma unroll
        for (int i = 0; i < 4; i++)
            CP16(base + A_S + s_dst + i * 32 * 144, sg + (size_t)i * 32 * 1024 + ch * 64);
#pragma unroll
        for (int i = 0; i < 2; i++)
            CP16(base + v_dst + i * 32 * 144, vg + ((size_t)ch * 64 + i * 32) * 1024);
    };

    float acc[2][4][4];
#pragma unroll
    for (int i = 0; i < 2; i++)
#pragma unroll
        for (int j = 0; j < 4; j++)
#pragma unroll
            for (int e = 0; e < 4; e++) acc[i][j][e] = 0.f;

    issue(0); CP_COMMIT();
    issue(1); CP_COMMIT();

    uint32_t a_off = (lane & 15) * 144 + (lane >> 4) * 16;
    uint32_t b_off = ((lane & 7) + ((lane >> 3) & 1) * 8) * 144 + (lane >> 4) * 16;

    for (int ch = 0; ch < 16; ch++) {
        CP_WAIT(1);
        __syncthreads();
        if (ch + 2 < 16) issue(ch + 2);
        CP_COMMIT();

        uint32_t base = smb + (uint32_t)((ch % 3) * A_STAGE);
#pragma unroll
        for (int kc = 0; kc < 4; kc++) {
            uint32_t af[2][4], bf[4][2];
#pragma unroll
            for (int mt = 0; mt < 2; mt++) {
                uint32_t r = base + A_S + (uint32_t)((wm * 32 + mt * 16) * 144) + kc * 32 + a_off;
                LDSM_X4(af[mt][0], af[mt][1], af[mt][2], af[mt][3], r);
            }
#pragma unroll
            for (int pp = 0; pp < 2; pp++) {
                uint32_t r = base + A_V + (uint32_t)(kc * 16 * 144) +
                             (uint32_t)((wn * 32 + pp * 16) * 2) + b_off;
                LDSM_X4_T(bf[pp*2][0], bf[pp*2][1], bf[pp*2+1][0], bf[pp*2+1][1], r);
            }
#pragma unroll
            for (int mt = 0; mt < 2; mt++)
#pragma unroll
                for (int nt = 0; nt < 4; nt++)
                    mma_f16(acc[mt][nt], af[mt], bf[nt]);
        }
    }

    int lr = lane >> 2, lc = (lane & 3) * 2;
#pragma unroll
    for (int nt = 0; nt < 4; nt++) {
        int col = h * 64 + wn * 32 + nt * 8 + lc;
#pragma unroll
        for (int mt = 0; mt < 2; mt++) {
            int row = b * 512 + q0 + wm * 32 + mt * 16 + lr;
            *reinterpret_cast<float2*>(out + (size_t)row * 1024 + col) =
                make_float2(acc[mt][nt][0], acc[mt][nt][1]);
            *reinterpret_cast<float2*>(out + (size_t)(row + 8) * 1024 + col) =
                make_float2(acc[mt][nt][2], acc[mt][nt][3]);
        }
    }
}

// ---------------- launch ----------------
extern "C" void kernel_launch(void* const* d_in, const int* in_sizes, int n_in,
                              void* d_out, int out_size)
{
    (void)in_sizes; (void)n_in; (void)out_size;
    const float* text = (const float*)d_in[0];
    const float* av   = (const float*)d_in[1];
    const float* tn_w = (const float*)d_in[2];
    const float* tn_b = (const float*)d_in[3];
    const float* an_w = (const float*)d_in[4];
    const float* an_b = (const float*)d_in[5];
    const float* Wq   = (const float*)d_in[6];
    const float* bq   = (const float*)d_in[7];
    const float* Wk   = (const float*)d_in[8];
    const float* bk   = (const float*)d_in[9];
    const float* Wv   = (const float*)d_in[10];
    const float* bv   = (const float*)d_in[11];

    float* out   = (float*)d_out;
    float* amean = out + (size_t)BS * NW * 1024;

    static int attr_done = 0;
    if (!attr_done) {
        cudaFuncSetAttribute(gemm_tc,       cudaFuncAttributeMaxDynamicSharedMemorySize, 4 * G_STAGE);
        cudaFuncSetAttribute(score_mean_tc, cudaFuncAttributeMaxDynamicSharedMemorySize, 2 * S_BUF);
        cudaFuncSetAttribute(av_tc,         cudaFuncAttributeMaxDynamicSharedMemorySize, 3 * A_STAGE);
        attr_done = 1;
    }

    ln_f16<<<BS * NW + BS * NV, 256>>>(text, av, tn_w, tn_b, an_w, an_b);
    wsplit<<<dim3(32, 32, 3), dim3(32, 8)>>>(Wq, Wk, Wv);

    gemm_tc<<<dim3(160, 8), 256, 4 * G_STAGE>>>(bq, bk, bv);

    score_mean_tc<<<dim3(8, 4, 8), 512, 2 * S_BUF>>>(amean);
    av_tc<<<dim3(4, 128), 256, 3 * A_STAGE>>>(out);
}

// round 15
// speedup vs baseline: 3.5819x; 1.0599x over previous
#include <cuda_runtime.h>
#include <cuda_fp16.h>
#include <cstdint>

#define BS 8
#define NW 512
#define NV 1024

// ---------------- fp16 scratch (allocation-free) ----------------
__device__ __half g_taf[BS*NW*1024];                       // LN(text)
__device__ __half g_aaf[BS*NV*1024];                       // LN(av)
__device__ __half g_wtf[3][1024*1024];                     // W^T [k][n]
__device__ __half g_qf[BS*NW*1024];
__device__ __half g_kf[BS*NV*1024];
__device__ __half g_vf[BS*NV*1024];
__device__ __half g_sf[(size_t)BS*16*NW*NV];               // sigmoid scores, 128 MB

// ---------------- helpers ----------------
__device__ __forceinline__ uint32_t smem_to_u32(const void* p) {
    uint32_t a;
    asm("{ .reg .u64 t; cvta.to.shared.u64 t, %1; cvt.u32.u64 %0, t; }" : "=r"(a) : "l"(p));
    return a;
}
__device__ __forceinline__ uint32_t pack_h2(float x0, float x1) {
    __half2 p = __floats2half2_rn(x0, x1);
    return *reinterpret_cast<uint32_t*>(&p);
}
__device__ __forceinline__ float sigmoid8(float x) {   // sigmoid(x/8) via tanh.approx
    float t;
    asm("tanh.approx.f32 %0, %1;" : "=f"(t) : "f"(x * 0.0625f));
    return fmaf(t, 0.5f, 0.5f);
}

#define LDSM_X4(r0, r1, r2, r3, addr) \
    asm volatile("ldmatrix.sync.aligned.m8n8.x4.shared.b16 {%0,%1,%2,%3}, [%4];" \
        : "=r"(r0), "=r"(r1), "=r"(r2), "=r"(r3) : "r"(addr))
#define LDSM_X4_T(r0, r1, r2, r3, addr) \
    asm volatile("ldmatrix.sync.aligned.m8n8.x4.trans.shared.b16 {%0,%1,%2,%3}, [%4];" \
        : "=r"(r0), "=r"(r1), "=r"(r2), "=r"(r3) : "r"(addr))

__device__ __forceinline__ void mma_f16(float* c, const uint32_t* a, const uint32_t* b) {
    asm volatile(
        "mma.sync.aligned.m16n8k16.row.col.f32.f16.f16.f32 "
        "{%0,%1,%2,%3}, {%4,%5,%6,%7}, {%8,%9}, {%0,%1,%2,%3};"
        : "+f"(c[0]), "+f"(c[1]), "+f"(c[2]), "+f"(c[3])
        : "r"(a[0]), "r"(a[1]), "r"(a[2]), "r"(a[3]), "r"(b[0]), "r"(b[1]));
}

#define CP16(dst, src) \
    asm volatile("cp.async.cg.shared.global [%0], [%1], 16;" :: "r"((uint32_t)(dst)), "l"(src) : "memory")
#define CP_COMMIT() asm volatile("cp.async.commit_group;" ::: "memory")
#define CP_WAIT(n)  asm volatile("cp.async.wait_group %0;" :: "n"(n) : "memory")

// ---------------- LayerNorm (both tensors, one launch) -> fp16 ----------------
__global__ __launch_bounds__(256) void ln_f16(const float* __restrict__ text,
                                              const float* __restrict__ av,
                                              const float* __restrict__ tw,
                                              const float* __restrict__ tb,
                                              const float* __restrict__ aw,
                                              const float* __restrict__ ab)
{
    int row = blockIdx.x, t = threadIdx.x;
    const float* x;
    const float* w;
    const float* b;
    __half* y;
    int lrow;
    if (row < BS * NW) {
        x = text; w = tw; b = tb; y = g_taf; lrow = row;
    } else {
        x = av;   w = aw; b = ab; y = g_aaf; lrow = row - BS * NW;
    }
    float4 xv = reinterpret_cast<const float4*>(x)[(size_t)lrow * 256 + t];
    float s  = xv.x + xv.y + xv.z + xv.w;
    float ss = xv.x*xv.x + xv.y*xv.y + xv.z*xv.z + xv.w*xv.w;
#pragma unroll
    for (int o = 16; o > 0; o >>= 1) {
        s  += __shfl_xor_sync(0xffffffffu, s,  o);
        ss += __shfl_xor_sync(0xffffffffu, ss, o);
    }
    __shared__ float rs[8], rss[8];
    if ((t & 31) == 0) { rs[t >> 5] = s; rss[t >> 5] = ss; }
    __syncthreads();
    float tot = 0.f, tot2 = 0.f;
#pragma unroll
    for (int i = 0; i < 8; i++) { tot += rs[i]; tot2 += rss[i]; }
    float mean = tot * (1.f / 1024.f);
    float var  = tot2 * (1.f / 1024.f) - mean * mean;
    float rstd = rsqrtf(var + 1e-5f);
    float4 wv = reinterpret_cast<const float4*>(w)[t];
    float4 bv = reinterpret_cast<const float4*>(b)[t];
    float o0 = (xv.x - mean) * rstd * wv.x + bv.x;
    float o1 = (xv.y - mean) * rstd * wv.y + bv.y;
    float o2 = (xv.z - mean) * rstd * wv.z + bv.z;
    float o3 = (xv.w - mean) * rstd * wv.w + bv.w;
    *reinterpret_cast<uint2*>(reinterpret_cast<char*>(y) + (size_t)lrow * 2048 + t * 8) =
        make_uint2(pack_h2(o0, o1), pack_h2(o2, o3));
}

// ---------------- W[n][k] -> W^T[k][n] fp16 ----------------
__global__ void wsplit(const float* __restrict__ Wq,
                       const float* __restrict__ Wk,
                       const float* __restrict__ Wv)
{
    int wsel = blockIdx.z;
    const float* W = (wsel == 0) ? Wq : (wsel == 1) ? Wk : Wv;
    __half* tf = g_wtf[wsel];
    __shared__ float tile[32][33];
    int k = blockIdx.x * 32 + threadIdx.x;
    int n0 = blockIdx.y * 32;
#pragma unroll
    for (int i = threadIdx.y; i < 32; i += 8)
        tile[i][threadIdx.x] = W[(size_t)(n0 + i) * 1024 + k];
    __syncthreads();
#pragma unroll
    for (int i = threadIdx.y; i < 32; i += 8) {
        float v = tile[threadIdx.x][i];
        size_t idx = (size_t)(blockIdx.x * 32 + i) * 1024 + n0 + threadIdx.x;
        tf[idx] = __float2half_rn(v);
    }
}

// ---------------- merged projection GEMM: Q+K+V in one launch ----------------
// 128x128 tile, K=32, 4-stage, 2 CTAs/SM. Epilogue staged via smem for coalesced STG.
#define G_A 0
#define G_B 10240
#define G_STAGE 18944

__global__ __launch_bounds__(256, 2) void gemm_tc(const float* __restrict__ bq,
                                                  const float* __restrict__ bk,
                                                  const float* __restrict__ bv)
{
    extern __shared__ __align__(16) uint8_t smg[];
    int tile = blockIdx.x;
    int dst, mtile;
    const float* bias;
    const __half* Af;
    if (tile < 32)      { dst = 0; mtile = tile;      bias = bq; Af = g_taf; }
    else if (tile < 96) { dst = 1; mtile = tile - 32; bias = bk; Af = g_aaf; }
    else                { dst = 2; mtile = tile - 96; bias = bv; Af = g_aaf; }
    const __half* Bf = g_wtf[dst];
    __half* Cf = (dst == 0) ? g_qf : (dst == 1) ? g_kf : g_vf;

    int t = threadIdx.x, lane = t & 31, warp = t >> 5;   // 8 warps, 2x4
    int wm = warp >> 2, wn = warp & 3;                    // warp tile 64 x 32
    int bm = mtile * 128, bn = blockIdx.y * 128;
    uint32_t smb = smem_to_u32(smg);

    int arow = t >> 2, aseg = t & 3;
    int brow = t >> 4, bseg = t & 15;
    const __half* ag0 = Af + (size_t)(bm + arow) * 1024 + aseg * 8;
    const __half* ag1 = Af + (size_t)(bm + arow + 64) * 1024 + aseg * 8;
    const __half* bg0 = Bf + (size_t)brow * 1024 + bn + bseg * 8;
    uint32_t a_dst0 = arow * 80 + aseg * 16;
    uint32_t a_dst1 = (arow + 64) * 80 + aseg * 16;
    uint32_t b_dst0 = brow * 272 + bseg * 16;

    auto issue = [&](int ch) {
        uint32_t base = smb + (uint32_t)((ch & 3) * G_STAGE);
        CP16(base + G_A + a_dst0, ag0 + ch * 32);
        CP16(base + G_A + a_dst1, ag1 + ch * 32);
        CP16(base + G_B + b_dst0, bg0 + (size_t)ch * 32 * 1024);
        CP16(base + G_B + b_dst0 + 16 * 272, bg0 + ((size_t)ch * 32 + 16) * 1024);
    };

    float acc[4][4][4];
#pragma unroll
    for (int i = 0; i < 4; i++)
#pragma unroll
        for (int j = 0; j < 4; j++)
#pragma unroll
            for (int e = 0; e < 4; e++) acc[i][j][e] = 0.f;

    issue(0); CP_COMMIT();
    issue(1); CP_COMMIT();
    issue(2); CP_COMMIT();

    uint32_t a_off = (lane & 15) * 80 + (lane >> 4) * 16;
    uint32_t b_off = ((lane & 7) + ((lane >> 3) & 1) * 8) * 272 + (lane >> 4) * 16;

    for (int ch = 0; ch < 32; ch++) {
        CP_WAIT(2);
        __syncthreads();
        if (ch + 3 < 32) issue(ch + 3);
        CP_COMMIT();

        uint32_t base = smb + (uint32_t)((ch & 3) * G_STAGE);
#pragma unroll
        for (int kc = 0; kc < 2; kc++) {
            uint32_t af[4][4], bf[4][2];
#pragma unroll
            for (int mt = 0; mt < 4; mt++) {
                uint32_t r = base + G_A + (uint32_t)((wm * 64 + mt * 16) * 80) + kc * 32 + a_off;
                LDSM_X4(af[mt][0], af[mt][1], af[mt][2], af[mt][3], r);
            }
#pragma unroll
            for (int pp = 0; pp < 2; pp++) {
                uint32_t r = base + G_B + (uint32_t)(kc * 16 * 272) +
                             (uint32_t)((wn * 32 + pp * 16) * 2) + b_off;
                LDSM_X4_T(bf[pp*2][0], bf[pp*2][1], bf[pp*2+1][0], bf[pp*2+1][1], r);
            }
#pragma unroll
            for (int mt = 0; mt < 4; mt++)
#pragma unroll
                for (int nt = 0; nt < 4; nt++)
                    mma_f16(acc[mt][nt], af[mt], bf[nt]);
        }
    }

    // ---- staged epilogue: fragments -> smem stage -> coalesced 16B STG ----
    CP_WAIT(0);
    __syncthreads();
    int lr = lane >> 2, lc = (lane & 3) * 2;
#pragma unroll
    for (int nt = 0; nt < 4; nt++) {
        int col = bn + wn * 32 + nt * 8 + lc;
        float b0 = __ldg(bias + col), b1 = __ldg(bias + col + 1);
        int lcol = wn * 32 + nt * 8 + lc;
#pragma unroll
        for (int mt = 0; mt < 4; mt++) {
            int lrow = wm * 64 + mt * 16 + lr;
            *reinterpret_cast<uint32_t*>(smg + lrow * 272 + lcol * 2) =
                pack_h2(acc[mt][nt][0] + b0, acc[mt][nt][1] + b1);
            *reinterpret_cast<uint32_t*>(smg + (lrow + 8) * 272 + lcol * 2) =
                pack_h2(acc[mt][nt][2] + b0, acc[mt][nt][3] + b1);
        }
    }
    __syncthreads();
    char* cdst = reinterpret_cast<char*>(Cf) + ((size_t)bm * 1024 + bn) * 2;
#pragma unroll
    for (int i = 0; i < 8; i++) {
        int idx = t + i * 256;
        int row = idx >> 4, f4 = idx & 15;
        uint4 v = *reinterpret_cast<uint4*>(smg + row * 272 + f4 * 16);
        *reinterpret_cast<uint4*>(cdst + (size_t)row * 2048 + f4 * 16) = v;
    }
}

// ---------------- score+mean: 128q x 64k CTA tile, 256 thr, 2 CTAs/SM ----------------
// buffer: Q [128 rows][144B] = 18432, K [64 rows][144B] = 9216 -> 27648; double buffered
#define S_Q 0
#define S_K 18432
#define S_BUF 27648

__global__ __launch_bounds__(256, 2) void score_mean_tc(float* __restrict__ amean)
{
    extern __shared__ __align__(16) uint8_t smg[];
    int b = blockIdx.z;
    int q0 = blockIdx.y * 128, k0 = blockIdx.x * 64;
    int t = threadIdx.x, lane = t & 31, warp = t >> 5;   // 8 warps
    int wm = warp >> 1, wn = warp & 1;                    // 4x2, warp tile 32x32
    uint32_t smb = smem_to_u32(smg);

    // staging: Q 1024 segs (4/thread), K 512 segs (2/thread)
    const __half* qp[4];
    uint32_t qd[4];
#pragma unroll
    for (int i = 0; i < 4; i++) {
        int idx = t + i * 256, row = idx >> 3, seg = idx & 7;
        qp[i] = g_qf + (size_t)(b * 512 + q0 + row) * 1024 + seg * 8;
        qd[i] = S_Q + row * 144 + seg * 16;
    }
    const __half* kp[2];
    uint32_t kd[2];
#pragma unroll
    for (int i = 0; i < 2; i++) {
        int idx = t + i * 256, row = idx >> 3, seg = idx & 7;
        kp[i] = g_kf + (size_t)(b * 1024 + k0 + row) * 1024 + seg * 8;
        kd[i] = S_K + row * 144 + seg * 16;
    }

    auto issue = [&](int h) {
        uint32_t base = smb + (uint32_t)((h & 1) * S_BUF);
#pragma unroll
        for (int i = 0; i < 4; i++) CP16(base + qd[i], qp[i] + h * 64);
#pragma unroll
        for (int i = 0; i < 2; i++) CP16(base + kd[i], kp[i] + h * 64);
    };

    uint32_t a_off = (lane & 15) * 144 + (lane >> 4) * 16;
    uint32_t b_off = ((lane & 7) + ((lane >> 4) & 1) * 8) * 144 + ((lane >> 3) & 1) * 16;

    float am[2][4][4];
#pragma unroll
    for (int i = 0; i < 2; i++)
#pragma unroll
        for (int j = 0; j < 4; j++)
#pragma unroll
            for (int e = 0; e < 4; e++) am[i][j][e] = 0.f;

    int lr = lane >> 2, lc = (lane & 3) * 2;

    issue(0); CP_COMMIT();

    for (int h = 0; h < 16; h++) {
        if (h < 15) { issue(h + 1); CP_COMMIT(); CP_WAIT(1); }
        else        { CP_WAIT(0); }
        __syncthreads();

        uint32_t base = smb + (uint32_t)((h & 1) * S_BUF);
        float acc[2][4][4];
#pragma unroll
        for (int i = 0; i < 2; i++)
#pragma unroll
            for (int j = 0; j < 4; j++)
#pragma unroll
                for (int e = 0; e < 4; e++) acc[i][j][e] = 0.f;

#pragma unroll
        for (int kc = 0; kc < 4; kc++) {
            uint32_t af[2][4], bf[4][2];
#pragma unroll
            for (int mt = 0; mt < 2; mt++) {
                uint32_t r = base + S_Q + (uint32_t)((wm * 32 + mt * 16) * 144) + kc * 32 + a_off;
                LDSM_X4(af[mt][0], af[mt][1], af[mt][2], af[mt][3], r);
            }
#pragma unroll
            for (int pp = 0; pp < 2; pp++) {
                uint32_t r = base + S_K + (uint32_t)((wn * 32 + pp * 16) * 144) + kc * 32 + b_off;
                LDSM_X4(bf[pp*2][0], bf[pp*2][1], bf[pp*2+1][0], bf[pp*2+1][1], r);
            }
#pragma unroll
            for (int mt = 0; mt < 2; mt++)
#pragma unroll
                for (int nt = 0; nt < 4; nt++)
                    mma_f16(acc[mt][nt], af[mt], bf[nt]);
        }

        size_t splane = ((size_t)b * 16 + h) * 524288;
#pragma unroll
        for (int mt = 0; mt < 2; mt++)
#pragma unroll
            for (int nt = 0; nt < 4; nt++) {
                float s0 = sigmoid8(acc[mt][nt][0]);
                float s1 = sigmoid8(acc[mt][nt][1]);
                float s2 = sigmoid8(acc[mt][nt][2]);
                float s3 = sigmoid8(acc[mt][nt][3]);
                am[mt][nt][0] += s0; am[mt][nt][1] += s1;
                am[mt][nt][2] += s2; am[mt][nt][3] += s3;
                int row = q0 + wm * 32 + mt * 16 + lr;
                int col = k0 + wn * 32 + nt * 8 + lc;
                *reinterpret_cast<uint32_t*>(reinterpret_cast<char*>(g_sf) + (splane + (size_t)row * 1024 + col) * 2) =
                    pack_h2(s0, s1);
                *reinterpret_cast<uint32_t*>(reinterpret_cast<char*>(g_sf) + (splane + (size_t)(row + 8) * 1024 + col) * 2) =
                    pack_h2(s2, s3);
            }
        __syncthreads();
    }

#pragma unroll
    for (int mt = 0; mt < 2; mt++)
#pragma unroll
        for (int nt = 0; nt < 4; nt++) {
            int row = q0 + wm * 32 + mt * 16 + lr;
            int col = k0 + wn * 32 + nt * 8 + lc;
            *reinterpret_cast<float2*>(amean + ((size_t)(b * 512) + row) * 1024 + col) =
                make_float2(am[mt][nt][0] * 0.0625f, am[mt][nt][1] * 0.0625f);
            *reinterpret_cast<float2*>(amean + ((size_t)(b * 512) + row + 8) * 1024 + col) =
                make_float2(am[mt][nt][2] * 0.0625f, am[mt][nt][3] * 0.0625f);
        }
}

// ---------------- AV: out = S @ V, fp16, K-chunk 64, 3-stage ----------------
#define A_S 0
#define A_V 18432
#define A_STAGE 27648

__global__ __launch_bounds__(256, 2) void av_tc(float* __restrict__ out)
{
    extern __shared__ __align__(16) uint8_t smg[];
    int bh = blockIdx.y, b = bh >> 4, h = bh & 15;
    int q0 = blockIdx.x * 128;
    int t = threadIdx.x, lane = t & 31, warp = t >> 5;
    int wm = warp >> 1, wn = warp & 1;
    uint32_t smb = smem_to_u32(smg);

    int sr = t >> 3, ss8 = t & 7;
    const __half* sg = g_sf + ((size_t)bh * 512 + q0 + sr) * 1024 + ss8 * 8;
    uint32_t s_dst = sr * 144 + ss8 * 16;
    int vr = t >> 3;
    const __half* vg = g_vf + (size_t)(b * 1024 + vr) * 1024 + h * 64 + ss8 * 8;
    uint32_t v_dst = A_V + vr * 144 + ss8 * 16;

    auto issue = [&](int ch) {
        uint32_t base = smb + (uint32_t)((ch % 3) * A_STAGE);
#pragma unroll
        for (int i = 0; i < 4; i++)
            CP16(base + A_S + s_dst + i * 32 * 144, sg + (size_t)i * 32 * 1024 + ch * 64);
#pragma unroll
        for (int i = 0; i < 2; i++)
            CP16(base + v_dst + i * 32 * 144, vg + ((size_t)ch * 64 + i * 32) * 1024);
    };

    float acc[2][4][4];
#pragma unroll
    for (int i = 0; i < 2; i++)
#pragma unroll
        for (int j = 0; j < 4; j++)
#pragma unroll
            for (int e = 0; e < 4; e++) acc[i][j][e] = 0.f;

    issue(0); CP_COMMIT();
    issue(1); CP_COMMIT();

    uint32_t a_off = (lane & 15) * 144 + (lane >> 4) * 16;
    uint32_t b_off = ((lane & 7) + ((lane >> 3) & 1) * 8) * 144 + (lane >> 4) * 16;

    for (int ch = 0; ch < 16; ch++) {
        CP_WAIT(1);
        __syncthreads();
        if (ch + 2 < 16) issue(ch + 2);
        CP_COMMIT();

        uint32_t base = smb + (uint32_t)((ch % 3) * A_STAGE);
#pragma unroll
        for (int kc = 0; kc < 4; kc++) {
            uint32_t af[2][4], bf[4][2];
#pragma unroll
            for (int mt = 0; mt < 2; mt++) {
                uint32_t r = base + A_S + (uint32_t)((wm * 32 + mt * 16) * 144) + kc * 32 + a_off;
                LDSM_X4(af[mt][0], af[mt][1], af[mt][2], af[mt][3], r);
            }
#pragma unroll
            for (int pp = 0; pp < 2; pp++) {
                uint32_t r = base + A_V + (uint32_t)(kc * 16 * 144) +
                             (uint32_t)((wn * 32 + pp * 16) * 2) + b_off;
                LDSM_X4_T(bf[pp*2][0], bf[pp*2][1], bf[pp*2+1][0], bf[pp*2+1][1], r);
            }
#pragma unroll
            for (int mt = 0; mt < 2; mt++)
#pragma unroll
                for (int nt = 0; nt < 4; nt++)
                    mma_f16(acc[mt][nt], af[mt], bf[nt]);
        }
    }

    int lr = lane >> 2, lc = (lane & 3) * 2;
#pragma unroll
    for (int nt = 0; nt < 4; nt++) {
        int col = h * 64 + wn * 32 + nt * 8 + lc;
#pragma unroll
        for (int mt = 0; mt < 2; mt++) {
            int row = b * 512 + q0 + wm * 32 + mt * 16 + lr;
            *reinterpret_cast<float2*>(out + (size_t)row * 1024 + col) =
                make_float2(acc[mt][nt][0], acc[mt][nt][1]);
            *reinterpret_cast<float2*>(out + (size_t)(row + 8) * 1024 + col) =
                make_float2(acc[mt][nt][2], acc[mt][nt][3]);
        }
    }
}

// ---------------- launch ----------------
extern "C" void kernel_launch(void* const* d_in, const int* in_sizes, int n_in,
                              void* d_out, int out_size)
{
    (void)in_sizes; (void)n_in; (void)out_size;
    const float* text = (const float*)d_in[0];
    const float* av   = (const float*)d_in[1];
    const float* tn_w = (const float*)d_in[2];
    const float* tn_b = (const float*)d_in[3];
    const float* an_w = (const float*)d_in[4];
    const float* an_b = (const float*)d_in[5];
    const float* Wq   = (const float*)d_in[6];
    const float* bq   = (const float*)d_in[7];
    const float* Wk   = (const float*)d_in[8];
    const float* bk   = (const float*)d_in[9];
    const float* Wv   = (const float*)d_in[10];
    const float* bv   = (const float*)d_in[11];

    float* out   = (float*)d_out;
    float* amean = out + (size_t)BS * NW * 1024;

    static int attr_done = 0;
    if (!attr_done) {
        cudaFuncSetAttribute(gemm_tc,       cudaFuncAttributeMaxDynamicSharedMemorySize, 4 * G_STAGE);
        cudaFuncSetAttribute(score_mean_tc, cudaFuncAttributeMaxDynamicSharedMemorySize, 2 * S_BUF);
        cudaFuncSetAttribute(av_tc,         cudaFuncAttributeMaxDynamicSharedMemorySize, 3 * A_STAGE);
        attr_done = 1;
    }

    ln_f16<<<BS * NW + BS * NV, 256>>>(text, av, tn_w, tn_b, an_w, an_b);
    wsplit<<<dim3(32, 32, 3), dim3(32, 8)>>>(Wq, Wk, Wv);

    gemm_tc<<<dim3(160, 8), 256, 4 * G_STAGE>>>(bq, bk, bv);

    score_mean_tc<<<dim3(16, 4, 8), 256, 2 * S_BUF>>>(amean);
    av_tc<<<dim3(4, 128), 256, 3 * A_STAGE>>>(out);
}